// round 8
// baseline (speedup 1.0000x reference)
#include <cuda_runtime.h>
#include <math.h>
#include <stdint.h>

#define BATCH 2
#define SEQ   1024
#define HID   1024
#define DI    2048
#define NST   16
#define KCONV 4
#define NLAYER 4
#define ROWS  (BATCH*SEQ)      // 2048
#define LN_EPS 1e-5f

// ---------------- scratch (device globals; no allocation) ----------------
__device__ float g_x  [ROWS*HID];
__device__ float g_xn [ROWS*HID];
__device__ float g_res[ROWS*DI];
__device__ float g_xi [ROWS*DI];
__device__ float g_xi2[ROWS*DI];
__device__ float g_pr [ROWS*64];        // padded proj (stride 64)
__device__ float g_y  [ROWS*DI];
__device__ float g_t1 [ROWS*HID];
__device__ float g_wp [NLAYER*64*DI];   // zero-padded+rounded x_proj weights
__device__ float g_wr [27262976];       // tf32-rounded weights: in_proj|out_proj|op1|op2

#define WR_IN  0
#define WR_OUT 16777216
#define WR_OP1 25165824
#define WR_OP2 26214400

// ---------------- helpers ----------------
__device__ __forceinline__ float siluf(float v) { return v / (1.f + expf(-v)); }
__device__ __forceinline__ float sigmoidf_(float v) { return 1.f / (1.f + expf(-v)); }
__device__ __forceinline__ float geluf(float v) { return 0.5f * v * (1.f + erff(v * 0.70710678118654752f)); }
__device__ __forceinline__ uint32_t to_tf32u(float x) {
    uint32_t u;
    asm("cvt.rna.tf32.f32 %0, %1;" : "=r"(u) : "f"(x));
    return u;
}
__device__ __forceinline__ uint32_t smem_u32(const void* p) {
    uint32_t a;
    asm("{ .reg .u64 t; cvta.to.shared.u64 t, %1; cvt.u32.u64 %0, t; }" : "=r"(a) : "l"(p));
    return a;
}
__device__ __forceinline__ void cp16(uint32_t d, const void* g) {
    asm volatile("cp.async.cg.shared.global [%0], [%1], 16;" :: "r"(d), "l"(g));
}

// ---------------- weight pre-round ----------------
__global__ void round_tf32(const float* __restrict__ in, float* __restrict__ out, int n)
{
    int i = blockIdx.x * blockDim.x + threadIdx.x;
    if (i < n) out[i] = __uint_as_float(to_tf32u(in[i]));
}

// ---------------- LayerNorm (optional sigmoid-gate epilogue) ----------------
template<bool GATE>
__global__ void ln_kernel(const float* __restrict__ in,
                          const float* __restrict__ g,
                          const float* __restrict__ b,
                          const float* __restrict__ gate,
                          float* __restrict__ out, int cols)
{
    __shared__ float buf[2048];
    __shared__ float red[8];
    __shared__ float s_mu, s_rstd;
    const int row = blockIdx.x;
    const int tid = threadIdx.x;
    const float* pin = in + (size_t)row * cols;

    float s = 0.f;
    for (int c = tid; c < cols; c += 256) { float v = pin[c]; buf[c] = v; s += v; }
    #pragma unroll
    for (int o = 16; o; o >>= 1) s += __shfl_xor_sync(0xffffffffu, s, o);
    if ((tid & 31) == 0) red[tid >> 5] = s;
    __syncthreads();
    if (tid == 0) {
        float t = 0.f;
        #pragma unroll
        for (int i = 0; i < 8; i++) t += red[i];
        s_mu = t / (float)cols;
    }
    __syncthreads();
    const float mu = s_mu;
    float v2 = 0.f;
    for (int c = tid; c < cols; c += 256) { float xc = buf[c] - mu; v2 += xc * xc; }
    #pragma unroll
    for (int o = 16; o; o >>= 1) v2 += __shfl_xor_sync(0xffffffffu, v2, o);
    __syncthreads();
    if ((tid & 31) == 0) red[tid >> 5] = v2;
    __syncthreads();
    if (tid == 0) {
        float t = 0.f;
        #pragma unroll
        for (int i = 0; i < 8; i++) t += red[i];
        s_rstd = 1.f / sqrtf(t / (float)cols + LN_EPS);
    }
    __syncthreads();
    const float rstd = s_rstd;
    for (int c = tid; c < cols; c += 256) {
        float val = (buf[c] - mu) * rstd * g[c] + b[c];
        if (GATE) val *= sigmoidf_(gate[(size_t)row * cols + c]);
        out[(size_t)row * cols + c] = val;
    }
}

// ---------------- tf32 mma.sync GEMM, multi-stage cp.async, 1 sync/k-tile --------
// C = A(MxK) * B(NxK)^T, 128 x TBN tile, BK=32. B must be pre-rounded to tf32.
// EPI: 0 plain ; 1 +resid ; 2 gelu(acc+bias) ; 3 acc+bias+resid ; 5 silu(acc)
#define SKEWF 36

template<int EPI, int TBN, int NSTG>
__global__ __launch_bounds__(256, 2)
void gemm_mma(const float* __restrict__ A, const float* __restrict__ Bw,
              const float* __restrict__ bias, float* __restrict__ resid,
              float* __restrict__ C, int M, int N, int K)
{
    constexpr int NT   = TBN / 32;
    constexpr int WNC  = TBN / 4;
    constexpr int ASTG = 128 * SKEWF;
    constexpr int BSTG = TBN * SKEWF;
    constexpr int STG  = ASTG + BSTG;
    extern __shared__ float sm[];

    const int tid  = threadIdx.x;
    const int lane = tid & 31;
    const int w    = tid >> 5;
    const int wm   = w & 1;
    const int wn   = w >> 1;
    const int m0 = blockIdx.y * 128;
    const int n0 = blockIdx.x * TBN;
    const int lq = lane >> 2;
    const int lr = lane & 3;

    float acc[4][NT][4];
    #pragma unroll
    for (int i = 0; i < 4; i++)
        #pragma unroll
        for (int j = 0; j < NT; j++)
            #pragma unroll
            for (int r = 0; r < 4; r++) acc[i][j][r] = 0.f;

    const int NC = K >> 5;

    auto load_stage = [&](int s, int k0) {
        float* dA = sm + s * STG;
        float* dB = dA + ASTG;
        #pragma unroll
        for (int i = 0; i < 4; i++) {
            int slot = tid + i * 256;
            int row = slot >> 3, c4 = (slot & 7) * 4;
            cp16(smem_u32(dA + row * SKEWF + c4), A + (size_t)(m0 + row) * K + k0 + c4);
        }
        #pragma unroll
        for (int i = 0; i < TBN * 8 / 256; i++) {
            int slot = tid + i * 256;
            int row = slot >> 3, c4 = (slot & 7) * 4;
            cp16(smem_u32(dB + row * SKEWF + c4), Bw + (size_t)(n0 + row) * K + k0 + c4);
        }
        asm volatile("cp.async.commit_group;" ::: "memory");
    };

    // prologue: fill NSTG-1 stages
    #pragma unroll
    for (int c = 0; c < NSTG - 1; c++) load_stage(c, c * 32);

    int s = 0;          // stage index = c % NSTG, tracked incrementally
    int sl = NSTG - 1;  // load target index = (c + NSTG - 1) % NSTG
    for (int c = 0; c < NC; c++) {
        if (c <= NC - NSTG + 1) {
            asm volatile("cp.async.wait_group %0;" :: "n"(NSTG - 2) : "memory");
        } else {
            asm volatile("cp.async.wait_group 0;" ::: "memory");
        }
        __syncthreads();

        if (c + NSTG - 1 < NC) load_stage(sl, (c + NSTG - 1) * 32);

        const float* sA = sm + s * STG;
        const float* sB = sA + ASTG;
        #pragma unroll
        for (int kk = 0; kk < 32; kk += 8) {
            uint32_t afr[4][4], bfr[NT][2];
            #pragma unroll
            for (int mt = 0; mt < 4; mt++) {
                int r = wm * 64 + mt * 16 + lq;
                afr[mt][0] = to_tf32u(sA[(r    ) * SKEWF + kk     + lr]);
                afr[mt][1] = to_tf32u(sA[(r + 8) * SKEWF + kk     + lr]);
                afr[mt][2] = to_tf32u(sA[(r    ) * SKEWF + kk + 4 + lr]);
                afr[mt][3] = to_tf32u(sA[(r + 8) * SKEWF + kk + 4 + lr]);
            }
            #pragma unroll
            for (int nt = 0; nt < NT; nt++) {
                int rn = wn * WNC + nt * 8 + lq;
                bfr[nt][0] = __float_as_uint(sB[rn * SKEWF + kk     + lr]);
                bfr[nt][1] = __float_as_uint(sB[rn * SKEWF + kk + 4 + lr]);
            }
            #pragma unroll
            for (int mt = 0; mt < 4; mt++)
                #pragma unroll
                for (int nt = 0; nt < NT; nt++) {
                    asm volatile(
                        "mma.sync.aligned.m16n8k8.row.col.f32.tf32.tf32.f32 "
                        "{%0,%1,%2,%3}, {%4,%5,%6,%7}, {%8,%9}, {%0,%1,%2,%3};"
                        : "+f"(acc[mt][nt][0]), "+f"(acc[mt][nt][1]),
                          "+f"(acc[mt][nt][2]), "+f"(acc[mt][nt][3])
                        : "r"(afr[mt][0]), "r"(afr[mt][1]), "r"(afr[mt][2]), "r"(afr[mt][3]),
                          "r"(bfr[nt][0]), "r"(bfr[nt][1]));
                }
        }
        if (++s == NSTG) s = 0;
        if (++sl == NSTG) sl = 0;
    }

    #pragma unroll
    for (int mt = 0; mt < 4; mt++) {
        #pragma unroll
        for (int nt = 0; nt < NT; nt++) {
            int r0 = m0 + wm * 64 + mt * 16 + lq;
            int cc = n0 + wn * WNC + nt * 8 + lr * 2;
            #pragma unroll
            for (int half = 0; half < 2; half++) {
                int m = r0 + half * 8;
                float v0 = acc[mt][nt][half * 2 + 0];
                float v1 = acc[mt][nt][half * 2 + 1];
                if (EPI == 0) {
                    *reinterpret_cast<float2*>(&C[(size_t)m * N + cc]) = make_float2(v0, v1);
                } else if (EPI == 1) {
                    float2 rr = *reinterpret_cast<const float2*>(&resid[(size_t)m * N + cc]);
                    *reinterpret_cast<float2*>(&C[(size_t)m * N + cc]) = make_float2(v0 + rr.x, v1 + rr.y);
                } else if (EPI == 2) {
                    *reinterpret_cast<float2*>(&C[(size_t)m * N + cc]) =
                        make_float2(geluf(v0 + bias[cc]), geluf(v1 + bias[cc + 1]));
                } else if (EPI == 3) {
                    float2 rr = *reinterpret_cast<const float2*>(&resid[(size_t)m * N + cc]);
                    *reinterpret_cast<float2*>(&C[(size_t)m * N + cc]) =
                        make_float2(v0 + bias[cc] + rr.x, v1 + bias[cc + 1] + rr.y);
                } else if (EPI == 5) {
                    *reinterpret_cast<float2*>(&C[(size_t)m * N + cc]) =
                        make_float2(siluf(v0), siluf(v1));
                }
            }
        }
    }
}

// ---------------- fused double causal dwconv (K=4) + silu ----------------
#define CCHUNK 16
__global__ void conv2_kernel(const float* __restrict__ in,
                             const float* __restrict__ w1, const float* __restrict__ b1,
                             const float* __restrict__ w2, const float* __restrict__ b2,
                             float* __restrict__ out)
{
    int idx = blockIdx.x * blockDim.x + threadIdx.x;
    if (idx >= BATCH * DI * (SEQ / CCHUNK)) return;
    int d  = idx % DI;
    int r  = idx / DI;
    int c0 = r % (SEQ / CCHUNK);
    int b  = r / (SEQ / CCHUNK);
    int t0 = c0 * CCHUNK;

    const float wa0 = w1[d*4+0], wa1 = w1[d*4+1], wa2 = w1[d*4+2], wa3 = w1[d*4+3];
    const float wb0 = w2[d*4+0], wb1 = w2[d*4+1], wb2 = w2[d*4+2], wb3 = w2[d*4+3];
    const float bb1 = b1[d], bb2 = b2[d];
    const float* pin  = in  + (size_t)b * SEQ * DI + d;
    float*       pout = out + (size_t)b * SEQ * DI + d;

    float h[3];
    #pragma unroll
    for (int j = 0; j < 3; j++) {
        int t = t0 - 3 + j;
        if (t >= 0) {
            float a = bb1;
            float wv[4] = {wa0, wa1, wa2, wa3};
            #pragma unroll
            for (int k = 0; k < 4; k++) {
                int tt = t - 3 + k;
                if (tt >= 0) a = fmaf(pin[(size_t)tt * DI], wv[k], a);
            }
            h[j] = siluf(a);
        } else h[j] = 0.f;
    }
    float xm3 = (t0 - 3 >= 0) ? pin[(size_t)(t0 - 3) * DI] : 0.f;
    float xm2 = (t0 - 2 >= 0) ? pin[(size_t)(t0 - 2) * DI] : 0.f;
    float xm1 = (t0 - 1 >= 0) ? pin[(size_t)(t0 - 1) * DI] : 0.f;

    #pragma unroll
    for (int t = t0; t < t0 + CCHUNK; t++) {
        float xt = pin[(size_t)t * DI];
        float v1 = bb1;
        v1 = fmaf(wa0, xm3, v1); v1 = fmaf(wa1, xm2, v1);
        v1 = fmaf(wa2, xm1, v1); v1 = fmaf(wa3, xt,  v1);
        float s = siluf(v1);
        float v2 = bb2;
        v2 = fmaf(wb0, h[0], v2); v2 = fmaf(wb1, h[1], v2);
        v2 = fmaf(wb2, h[2], v2); v2 = fmaf(wb3, s,    v2);
        pout[(size_t)t * DI] = siluf(v2);
        xm3 = xm2; xm2 = xm1; xm1 = xt;
        h[0] = h[1]; h[1] = h[2]; h[2] = s;
    }
}

// ---------------- x_proj weight zero-pad + round: W[l][33][2048] -> Wp[l][64][2048] ----
__global__ void wpad_kernel(const float* __restrict__ W, float* __restrict__ Wp)
{
    int idx = blockIdx.x * blockDim.x + threadIdx.x;
    if (idx >= NLAYER * 64 * DI) return;
    int k = idx % DI;
    int p = (idx / DI) % 64;
    int l = idx / (DI * 64);
    Wp[idx] = (p < 33) ? __uint_as_float(to_tf32u(W[((size_t)l * 33 + p) * DI + k])) : 0.f;
}

// ---------------- selective scan: smem-staged, double-buffered chunks ----------------
#define SCH 64
#define NCHK (SEQ / SCH)
#define SCAN_SMEM ((2*SCH*32 + 2*SCH*64 + SCH*32) * 4)

__global__ __launch_bounds__(256)
void scan_kernel(const float* __restrict__ x, const float* __restrict__ pr,
                 const float* __restrict__ dtw, const float* __restrict__ dtb,
                 const float* __restrict__ Dv, float* __restrict__ y)
{
    extern __shared__ float sm[];
    float* SX = sm;                     // [2][SCH][32]
    float* SP = sm + 2 * SCH * 32;      // [2][SCH][64]
    float* SY = SP + 2 * SCH * 64;      // [SCH][32]

    const int tid = threadIdx.x;
    const int dd  = tid >> 3;
    const int sub = tid & 7;
    const int nblk = DI / 32;
    const int b  = blockIdx.x / nblk;
    const int d0 = (blockIdx.x % nblk) * 32;
    const int d  = d0 + dd;

    const float wdt = dtw[d], bdt = dtb[d], Dd = Dv[d];
    const float A0 = -(float)(sub * 2 + 1);
    const float A1 = -(float)(sub * 2 + 2);
    float h0 = 0.f, h1 = 0.f;

    const float* xg = x + (size_t)b * SEQ * DI + d0;
    const float* pg = pr + (size_t)b * SEQ * 64;
    float*       yg = y + (size_t)b * SEQ * DI + d0;

    auto load_chunk = [&](int buf, int c) {
        int t0 = c * SCH;
        float* dx = SX + buf * SCH * 32;
        float* dp = SP + buf * SCH * 64;
        #pragma unroll
        for (int i = 0; i < 2; i++) {
            int sl = tid + i * 256;
            int t = sl >> 3, ch = sl & 7;
            cp16(smem_u32(dx + t * 32 + ch * 4), xg + (size_t)(t0 + t) * DI + ch * 4);
        }
        #pragma unroll
        for (int i = 0; i < 4; i++) {
            int sl = tid + i * 256;
            int t = sl >> 4, ch = sl & 15;
            cp16(smem_u32(dp + t * 64 + ch * 4), pg + (size_t)(t0 + t) * 64 + ch * 4);
        }
        asm volatile("cp.async.commit_group;" ::: "memory");
    };

    load_chunk(0, 0);
    load_chunk(1, 1);

    for (int c = 0; c < NCHK; c++) {
        const int buf = c & 1;
        if (c + 1 < NCHK) asm volatile("cp.async.wait_group 1;" ::: "memory");
        else              asm volatile("cp.async.wait_group 0;" ::: "memory");
        __syncthreads();

        const float* cx = SX + buf * SCH * 32;
        const float* cp = SP + buf * SCH * 64;
        #pragma unroll 4
        for (int s = 0; s < SCH; s++) {
            float dtraw = cp[s * 64];
            float xv    = cx[s * 32 + dd];
            float B0 = cp[s * 64 + 1 + 2 * sub], B1 = cp[s * 64 + 2 + 2 * sub];
            float C0 = cp[s * 64 + 17 + 2 * sub], C1 = cp[s * 64 + 18 + 2 * sub];
            float z  = fmaf(dtraw, wdt, bdt);
            float dt = (z > 20.f) ? z : log1pf(expf(z));
            float dtx = dt * xv;
            float t0v = fmaf(h0, A0, dtx * B0); h0 = fmaf(dt, t0v, h0);
            float t1v = fmaf(h1, A1, dtx * B1); h1 = fmaf(dt, t1v, h1);
            float yp = fmaf(h1, C1, h0 * C0);
            yp += __shfl_xor_sync(0xffffffffu, yp, 1);
            yp += __shfl_xor_sync(0xffffffffu, yp, 2);
            yp += __shfl_xor_sync(0xffffffffu, yp, 4);
            if (sub == 0) SY[s * 32 + dd] = fmaf(xv, Dd, yp);
        }
        __syncthreads();

        const int t0 = c * SCH;
        #pragma unroll
        for (int i = 0; i < 8; i++) {
            int sl = tid + i * 256;
            int s = sl >> 5, dd2 = sl & 31;
            yg[(size_t)(t0 + s) * DI + dd2] = SY[s * 32 + dd2];
        }
        if (c + 2 < NCHK) load_chunk(buf, c + 2);
    }
}

// ---------------- host orchestration ----------------
#define SMEM_G(TBN, NSTG) ((NSTG) * (128 + (TBN)) * SKEWF * 4)

extern "C" void kernel_launch(void* const* d_in, const int* in_sizes, int n_in,
                              void* d_out, int out_size)
{
    const float* hidden      = (const float*)d_in[0];
    const float* in_norm_g   = (const float*)d_in[1];
    const float* in_norm_b   = (const float*)d_in[2];
    const float* ln_g        = (const float*)d_in[3];
    const float* ln_b        = (const float*)d_in[4];
    const float* in_proj_w   = (const float*)d_in[5];
    const float* conv_w      = (const float*)d_in[6];
    const float* conv_b      = (const float*)d_in[7];
    const float* x_proj_w    = (const float*)d_in[8];
    const float* dt_proj_w   = (const float*)d_in[9];
    const float* dt_proj_b   = (const float*)d_in[10];
    const float* Dv          = (const float*)d_in[11];
    const float* mamba_ln_g  = (const float*)d_in[12];
    const float* mamba_ln_b  = (const float*)d_in[13];
    const float* out_proj_w  = (const float*)d_in[14];
    const float* op1_w       = (const float*)d_in[15];
    const float* op1_b       = (const float*)d_in[16];
    const float* op2_w       = (const float*)d_in[17];
    const float* op2_b       = (const float*)d_in[18];

    float *x, *xn, *res, *xi, *xi2, *pr, *y, *t1, *wp, *wr;
    cudaGetSymbolAddress((void**)&x,   g_x);
    cudaGetSymbolAddress((void**)&xn,  g_xn);
    cudaGetSymbolAddress((void**)&res, g_res);
    cudaGetSymbolAddress((void**)&xi,  g_xi);
    cudaGetSymbolAddress((void**)&xi2, g_xi2);
    cudaGetSymbolAddress((void**)&pr,  g_pr);
    cudaGetSymbolAddress((void**)&y,   g_y);
    cudaGetSymbolAddress((void**)&t1,  g_t1);
    cudaGetSymbolAddress((void**)&wp,  g_wp);
    cudaGetSymbolAddress((void**)&wr,  g_wr);

    cudaFuncSetAttribute(gemm_mma<5,128,3>, cudaFuncAttributeMaxDynamicSharedMemorySize, SMEM_G(128,3));
    cudaFuncSetAttribute(gemm_mma<0,128,3>, cudaFuncAttributeMaxDynamicSharedMemorySize, SMEM_G(128,3));
    cudaFuncSetAttribute(gemm_mma<0,64,4>,  cudaFuncAttributeMaxDynamicSharedMemorySize, SMEM_G(64,4));
    cudaFuncSetAttribute(gemm_mma<1,64,4>,  cudaFuncAttributeMaxDynamicSharedMemorySize, SMEM_G(64,4));
    cudaFuncSetAttribute(gemm_mma<2,64,4>,  cudaFuncAttributeMaxDynamicSharedMemorySize, SMEM_G(64,4));
    cudaFuncSetAttribute(gemm_mma<3,64,4>,  cudaFuncAttributeMaxDynamicSharedMemorySize, SMEM_G(64,4));
    cudaFuncSetAttribute(scan_kernel, cudaFuncAttributeMaxDynamicSharedMemorySize, SCAN_SMEM);

    // pre-round weights to tf32 (rna) once
    round_tf32<<<(NLAYER*2*DI*HID + 255)/256, 256>>>(in_proj_w,  wr + WR_IN,  NLAYER*2*DI*HID);
    round_tf32<<<(NLAYER*HID*DI  + 255)/256, 256>>>(out_proj_w, wr + WR_OUT, NLAYER*HID*DI);
    round_tf32<<<(HID*HID        + 255)/256, 256>>>(op1_w,      wr + WR_OP1, HID*HID);
    round_tf32<<<(HID*HID        + 255)/256, 256>>>(op2_w,      wr + WR_OP2, HID*HID);
    wpad_kernel<<<(NLAYER * 64 * DI + 255) / 256, 256>>>(x_proj_w, wp);

    // x = LN(hidden)
    ln_kernel<false><<<ROWS, 256>>>(hidden, in_norm_g, in_norm_b, nullptr, x, HID);

    for (int l = 0; l < NLAYER; l++) {
        // xn = LN(x)
        ln_kernel<false><<<ROWS, 256>>>(x, ln_g + (size_t)l * HID, ln_b + (size_t)l * HID,
                                        nullptr, xn, HID);
        // in_proj split: xi = silu(xn @ W_x^T)
        gemm_mma<5,128,3><<<dim3(DI / 128, ROWS / 128), 256, SMEM_G(128,3)>>>(
            xn, wr + WR_IN + (size_t)l * 2 * DI * HID, nullptr, nullptr, xi, ROWS, DI, HID);
        // res = xn @ W_res^T
        gemm_mma<0,128,3><<<dim3(DI / 128, ROWS / 128), 256, SMEM_G(128,3)>>>(
            xn, wr + WR_IN + (size_t)l * 2 * DI * HID + (size_t)DI * HID, nullptr, nullptr,
            res, ROWS, DI, HID);
        // fused conv1+silu+conv2+silu : xi -> xi2
        conv2_kernel<<<(BATCH * DI * (SEQ / CCHUNK)) / 256, 256>>>(
            xi,
            conv_w + (size_t)(l * 2 + 0) * DI * KCONV, conv_b + (size_t)(l * 2 + 0) * DI,
            conv_w + (size_t)(l * 2 + 1) * DI * KCONV, conv_b + (size_t)(l * 2 + 1) * DI,
            xi2);
        // proj = x_inner @ Wp^T  (2048 x 64 x 2048)
        gemm_mma<0,64,4><<<dim3(1, ROWS / 128), 256, SMEM_G(64,4)>>>(
            xi2, wp + (size_t)l * 64 * DI, nullptr, nullptr, pr, ROWS, 64, DI);
        // selective scan -> y (+ x_inner * D)
        scan_kernel<<<BATCH * (DI / 32), 256, SCAN_SMEM>>>(
            xi2, pr, dt_proj_w + (size_t)l * DI, dt_proj_b + (size_t)l * DI,
            Dv + (size_t)l * DI, y);
        // y = LN(y) * sigmoid(res)
        ln_kernel<true><<<ROWS, 256>>>(y, mamba_ln_g + (size_t)l * DI, mamba_ln_b + (size_t)l * DI,
                                       res, y, DI);
        // x = x + y @ out_proj_w^T
        gemm_mma<1,64,4><<<dim3(HID / 64, ROWS / 128), 256, SMEM_G(64,4)>>>(
            y, wr + WR_OUT + (size_t)l * HID * DI, nullptr, x, x, ROWS, HID, DI);
    }

    // t1 = gelu(x @ op1_w^T + op1_b)
    gemm_mma<2,64,4><<<dim3(HID / 64, ROWS / 128), 256, SMEM_G(64,4)>>>(
        x, wr + WR_OP1, op1_b, nullptr, t1, ROWS, HID, HID);
    // out = t1 @ op2_w^T + op2_b + hidden
    gemm_mma<3,64,4><<<dim3(HID / 64, ROWS / 128), 256, SMEM_G(64,4)>>>(
        t1, wr + WR_OP2, op2_b, (float*)hidden, (float*)d_out, ROWS, HID, HID);
}

// round 9
// speedup vs baseline: 1.0826x; 1.0826x over previous
#include <cuda_runtime.h>
#include <math.h>
#include <stdint.h>

#define BATCH 2
#define SEQ   1024
#define HID   1024
#define DI    2048
#define NST   16
#define KCONV 4
#define NLAYER 4
#define ROWS  (BATCH*SEQ)      // 2048
#define LN_EPS 1e-5f
#define KSPL  8                // xproj split-K factor

// ---------------- scratch (device globals; no allocation) ----------------
__device__ float g_x  [ROWS*HID];
__device__ float g_xn [ROWS*HID];
__device__ float g_res[ROWS*DI];
__device__ float g_xi [ROWS*DI];
__device__ float g_xi2[ROWS*DI];
__device__ float g_pr [ROWS*64];          // padded proj (stride 64)
__device__ float g_prp[KSPL*ROWS*64];     // split-K partials
__device__ float g_y  [ROWS*DI];
__device__ float g_t1 [ROWS*HID];
__device__ float g_wp [NLAYER*64*DI];     // zero-padded x_proj weights

// ---------------- helpers ----------------
__device__ __forceinline__ float siluf(float v) { return v / (1.f + expf(-v)); }
__device__ __forceinline__ float sigmoidf_(float v) { return 1.f / (1.f + expf(-v)); }
__device__ __forceinline__ float geluf(float v) { return 0.5f * v * (1.f + erff(v * 0.70710678118654752f)); }
__device__ __forceinline__ uint32_t to_tf32u(float x) {
    uint32_t u;
    asm("cvt.rna.tf32.f32 %0, %1;" : "=r"(u) : "f"(x));
    return u;
}
__device__ __forceinline__ uint32_t smem_u32(const void* p) {
    uint32_t a;
    asm("{ .reg .u64 t; cvta.to.shared.u64 t, %1; cvt.u32.u64 %0, t; }" : "=r"(a) : "l"(p));
    return a;
}
__device__ __forceinline__ void cp16(uint32_t d, const void* g) {
    asm volatile("cp.async.cg.shared.global [%0], [%1], 16;" :: "r"(d), "l"(g));
}

// ---------------- LayerNorm (optional sigmoid-gate epilogue) ----------------
template<bool GATE>
__global__ void ln_kernel(const float* __restrict__ in,
                          const float* __restrict__ g,
                          const float* __restrict__ b,
                          const float* __restrict__ gate,
                          float* __restrict__ out, int cols)
{
    __shared__ float buf[2048];
    __shared__ float red[8];
    __shared__ float s_mu, s_rstd;
    const int row = blockIdx.x;
    const int tid = threadIdx.x;
    const float* pin = in + (size_t)row * cols;

    float s = 0.f;
    for (int c = tid; c < cols; c += 256) { float v = pin[c]; buf[c] = v; s += v; }
    #pragma unroll
    for (int o = 16; o; o >>= 1) s += __shfl_xor_sync(0xffffffffu, s, o);
    if ((tid & 31) == 0) red[tid >> 5] = s;
    __syncthreads();
    if (tid == 0) {
        float t = 0.f;
        #pragma unroll
        for (int i = 0; i < 8; i++) t += red[i];
        s_mu = t / (float)cols;
    }
    __syncthreads();
    const float mu = s_mu;
    float v2 = 0.f;
    for (int c = tid; c < cols; c += 256) { float xc = buf[c] - mu; v2 += xc * xc; }
    #pragma unroll
    for (int o = 16; o; o >>= 1) v2 += __shfl_xor_sync(0xffffffffu, v2, o);
    __syncthreads();
    if ((tid & 31) == 0) red[tid >> 5] = v2;
    __syncthreads();
    if (tid == 0) {
        float t = 0.f;
        #pragma unroll
        for (int i = 0; i < 8; i++) t += red[i];
        s_rstd = 1.f / sqrtf(t / (float)cols + LN_EPS);
    }
    __syncthreads();
    const float rstd = s_rstd;
    for (int c = tid; c < cols; c += 256) {
        float val = (buf[c] - mu) * rstd * g[c] + b[c];
        if (GATE) val *= sigmoidf_(gate[(size_t)row * cols + c]);
        out[(size_t)row * cols + c] = val;
    }
}

// ---------------- tf32 mma.sync GEMM, multi-stage cp.async, 1 sync/k-tile --------
// C = A(MxK) * B(NxK)^T, 128 x TBN tile, BK=32.
// EPI: 0 plain ; 1 +resid ; 2 gelu(acc+bias) ; 3 acc+bias+resid ;
//      4 in_proj split: n<DI -> C[m*DI+n]=silu(acc), else resid[m*DI+n-DI]=acc
#define SKEWF 36

template<int EPI, int TBN, int NSTG>
__global__ __launch_bounds__(256, 2)
void gemm_mma(const float* __restrict__ A, const float* __restrict__ Bw,
              const float* __restrict__ bias, float* __restrict__ resid,
              float* __restrict__ C, int M, int N, int K)
{
    constexpr int NT   = TBN / 32;
    constexpr int WNC  = TBN / 4;
    constexpr int ASTG = 128 * SKEWF;
    constexpr int BSTG = TBN * SKEWF;
    constexpr int STG  = ASTG + BSTG;
    extern __shared__ float sm[];

    const int tid  = threadIdx.x;
    const int lane = tid & 31;
    const int w    = tid >> 5;
    const int wm   = w & 1;
    const int wn   = w >> 1;
    const int m0 = blockIdx.y * 128;
    const int n0 = blockIdx.x * TBN;
    const int lq = lane >> 2;
    const int lr = lane & 3;

    float acc[4][NT][4];
    #pragma unroll
    for (int i = 0; i < 4; i++)
        #pragma unroll
        for (int j = 0; j < NT; j++)
            #pragma unroll
            for (int r = 0; r < 4; r++) acc[i][j][r] = 0.f;

    const int NC = K >> 5;

    auto load_stage = [&](int s, int k0) {
        float* dA = sm + s * STG;
        float* dB = dA + ASTG;
        #pragma unroll
        for (int i = 0; i < 4; i++) {
            int slot = tid + i * 256;
            int row = slot >> 3, c4 = (slot & 7) * 4;
            cp16(smem_u32(dA + row * SKEWF + c4), A + (size_t)(m0 + row) * K + k0 + c4);
        }
        #pragma unroll
        for (int i = 0; i < TBN * 8 / 256; i++) {
            int slot = tid + i * 256;
            int row = slot >> 3, c4 = (slot & 7) * 4;
            cp16(smem_u32(dB + row * SKEWF + c4), Bw + (size_t)(n0 + row) * K + k0 + c4);
        }
        asm volatile("cp.async.commit_group;" ::: "memory");
    };

    #pragma unroll
    for (int c = 0; c < NSTG - 1; c++) load_stage(c, c * 32);

    int s = 0;
    int sl = NSTG - 1;
    for (int c = 0; c < NC; c++) {
        if (c <= NC - NSTG + 1) {
            asm volatile("cp.async.wait_group %0;" :: "n"(NSTG - 2) : "memory");
        } else {
            asm volatile("cp.async.wait_group 0;" ::: "memory");
        }
        __syncthreads();

        if (c + NSTG - 1 < NC) load_stage(sl, (c + NSTG - 1) * 32);

        const float* sA = sm + s * STG;
        const float* sB = sA + ASTG;
        #pragma unroll
        for (int kk = 0; kk < 32; kk += 8) {
            uint32_t afr[4][4], bfr[NT][2];
            #pragma unroll
            for (int mt = 0; mt < 4; mt++) {
                int r = wm * 64 + mt * 16 + lq;
                afr[mt][0] = to_tf32u(sA[(r    ) * SKEWF + kk     + lr]);
                afr[mt][1] = to_tf32u(sA[(r + 8) * SKEWF + kk     + lr]);
                afr[mt][2] = to_tf32u(sA[(r    ) * SKEWF + kk + 4 + lr]);
                afr[mt][3] = to_tf32u(sA[(r + 8) * SKEWF + kk + 4 + lr]);
            }
            #pragma unroll
            for (int nt = 0; nt < NT; nt++) {
                int rn = wn * WNC + nt * 8 + lq;
                bfr[nt][0] = to_tf32u(sB[rn * SKEWF + kk     + lr]);
                bfr[nt][1] = to_tf32u(sB[rn * SKEWF + kk + 4 + lr]);
            }
            #pragma unroll
            for (int mt = 0; mt < 4; mt++)
                #pragma unroll
                for (int nt = 0; nt < NT; nt++) {
                    asm volatile(
                        "mma.sync.aligned.m16n8k8.row.col.f32.tf32.tf32.f32 "
                        "{%0,%1,%2,%3}, {%4,%5,%6,%7}, {%8,%9}, {%0,%1,%2,%3};"
                        : "+f"(acc[mt][nt][0]), "+f"(acc[mt][nt][1]),
                          "+f"(acc[mt][nt][2]), "+f"(acc[mt][nt][3])
                        : "r"(afr[mt][0]), "r"(afr[mt][1]), "r"(afr[mt][2]), "r"(afr[mt][3]),
                          "r"(bfr[nt][0]), "r"(bfr[nt][1]));
                }
        }
        if (++s == NSTG) s = 0;
        if (++sl == NSTG) sl = 0;
    }

    #pragma unroll
    for (int mt = 0; mt < 4; mt++) {
        #pragma unroll
        for (int nt = 0; nt < NT; nt++) {
            int r0 = m0 + wm * 64 + mt * 16 + lq;
            int cc = n0 + wn * WNC + nt * 8 + lr * 2;
            #pragma unroll
            for (int half = 0; half < 2; half++) {
                int m = r0 + half * 8;
                float v0 = acc[mt][nt][half * 2 + 0];
                float v1 = acc[mt][nt][half * 2 + 1];
                if (EPI == 0) {
                    *reinterpret_cast<float2*>(&C[(size_t)m * N + cc]) = make_float2(v0, v1);
                } else if (EPI == 1) {
                    float2 rr = *reinterpret_cast<const float2*>(&resid[(size_t)m * N + cc]);
                    *reinterpret_cast<float2*>(&C[(size_t)m * N + cc]) = make_float2(v0 + rr.x, v1 + rr.y);
                } else if (EPI == 2) {
                    *reinterpret_cast<float2*>(&C[(size_t)m * N + cc]) =
                        make_float2(geluf(v0 + bias[cc]), geluf(v1 + bias[cc + 1]));
                } else if (EPI == 3) {
                    float2 rr = *reinterpret_cast<const float2*>(&resid[(size_t)m * N + cc]);
                    *reinterpret_cast<float2*>(&C[(size_t)m * N + cc]) =
                        make_float2(v0 + bias[cc] + rr.x, v1 + bias[cc + 1] + rr.y);
                } else if (EPI == 4) {   // in_proj split; tile cols never straddle DI
                    if (cc < DI)
                        *reinterpret_cast<float2*>(&C[(size_t)m * DI + cc]) =
                            make_float2(siluf(v0), siluf(v1));
                    else
                        *reinterpret_cast<float2*>(&resid[(size_t)m * DI + cc - DI]) =
                            make_float2(v0, v1);
                }
            }
        }
    }
}

// ---------------- xproj split-K GEMM: partial = A(128xKC) * Wp(64xKC)^T ----------------
// grid (KSPL, M/128); K chunk = K/KSPL; 4-stage pipeline; A/B lda = K (2048).
__global__ __launch_bounds__(256, 2)
void xproj_splitk(const float* __restrict__ A, const float* __restrict__ Bw,
                  float* __restrict__ Cp, int K)
{
    constexpr int TBN  = 64;
    constexpr int NSTG = 4;
    constexpr int NT   = TBN / 32;
    constexpr int WNC  = TBN / 4;
    constexpr int ASTG = 128 * SKEWF;
    constexpr int BSTG = TBN * SKEWF;
    constexpr int STG  = ASTG + BSTG;
    extern __shared__ float sm[];

    const int tid  = threadIdx.x;
    const int lane = tid & 31;
    const int w    = tid >> 5;
    const int wm   = w & 1;
    const int wn   = w >> 1;
    const int m0 = blockIdx.y * 128;
    const int kz = blockIdx.x;                  // split index
    const int kbase = kz * (K / KSPL);
    const int lq = lane >> 2;
    const int lr = lane & 3;
    float* C = Cp + (size_t)kz * ROWS * 64;

    float acc[4][NT][4];
    #pragma unroll
    for (int i = 0; i < 4; i++)
        #pragma unroll
        for (int j = 0; j < NT; j++)
            #pragma unroll
            for (int r = 0; r < 4; r++) acc[i][j][r] = 0.f;

    const int NC = (K / KSPL) >> 5;             // 8

    auto load_stage = [&](int s, int k0) {
        float* dA = sm + s * STG;
        float* dB = dA + ASTG;
        #pragma unroll
        for (int i = 0; i < 4; i++) {
            int slot = tid + i * 256;
            int row = slot >> 3, c4 = (slot & 7) * 4;
            cp16(smem_u32(dA + row * SKEWF + c4), A + (size_t)(m0 + row) * K + kbase + k0 + c4);
        }
        #pragma unroll
        for (int i = 0; i < 2; i++) {
            int slot = tid + i * 256;
            int row = slot >> 3, c4 = (slot & 7) * 4;
            cp16(smem_u32(dB + row * SKEWF + c4), Bw + (size_t)row * K + kbase + k0 + c4);
        }
        asm volatile("cp.async.commit_group;" ::: "memory");
    };

    #pragma unroll
    for (int c = 0; c < NSTG - 1; c++) load_stage(c, c * 32);

    int s = 0, sl = NSTG - 1;
    for (int c = 0; c < NC; c++) {
        if (c <= NC - NSTG + 1) {
            asm volatile("cp.async.wait_group %0;" :: "n"(NSTG - 2) : "memory");
        } else {
            asm volatile("cp.async.wait_group 0;" ::: "memory");
        }
        __syncthreads();
        if (c + NSTG - 1 < NC) load_stage(sl, (c + NSTG - 1) * 32);

        const float* sA = sm + s * STG;
        const float* sB = sA + ASTG;
        #pragma unroll
        for (int kk = 0; kk < 32; kk += 8) {
            uint32_t afr[4][4], bfr[NT][2];
            #pragma unroll
            for (int mt = 0; mt < 4; mt++) {
                int r = wm * 64 + mt * 16 + lq;
                afr[mt][0] = to_tf32u(sA[(r    ) * SKEWF + kk     + lr]);
                afr[mt][1] = to_tf32u(sA[(r + 8) * SKEWF + kk     + lr]);
                afr[mt][2] = to_tf32u(sA[(r    ) * SKEWF + kk + 4 + lr]);
                afr[mt][3] = to_tf32u(sA[(r + 8) * SKEWF + kk + 4 + lr]);
            }
            #pragma unroll
            for (int nt = 0; nt < NT; nt++) {
                int rn = wn * WNC + nt * 8 + lq;
                bfr[nt][0] = to_tf32u(sB[rn * SKEWF + kk     + lr]);
                bfr[nt][1] = to_tf32u(sB[rn * SKEWF + kk + 4 + lr]);
            }
            #pragma unroll
            for (int mt = 0; mt < 4; mt++)
                #pragma unroll
                for (int nt = 0; nt < NT; nt++) {
                    asm volatile(
                        "mma.sync.aligned.m16n8k8.row.col.f32.tf32.tf32.f32 "
                        "{%0,%1,%2,%3}, {%4,%5,%6,%7}, {%8,%9}, {%0,%1,%2,%3};"
                        : "+f"(acc[mt][nt][0]), "+f"(acc[mt][nt][1]),
                          "+f"(acc[mt][nt][2]), "+f"(acc[mt][nt][3])
                        : "r"(afr[mt][0]), "r"(afr[mt][1]), "r"(afr[mt][2]), "r"(afr[mt][3]),
                          "r"(bfr[nt][0]), "r"(bfr[nt][1]));
                }
        }
        if (++s == NSTG) s = 0;
        if (++sl == NSTG) sl = 0;
    }

    #pragma unroll
    for (int mt = 0; mt < 4; mt++)
        #pragma unroll
        for (int nt = 0; nt < NT; nt++) {
            int r0 = m0 + wm * 64 + mt * 16 + lq;
            int cc = wn * WNC + nt * 8 + lr * 2;
            #pragma unroll
            for (int half = 0; half < 2; half++) {
                int m = r0 + half * 8;
                *reinterpret_cast<float2*>(&C[(size_t)m * 64 + cc]) =
                    make_float2(acc[mt][nt][half * 2 + 0], acc[mt][nt][half * 2 + 1]);
            }
        }
}

// ---------------- split-K reduce: pr = sum_z prp[z] ----------------
__global__ void prred_kernel(const float* __restrict__ prp, float* __restrict__ pr)
{
    int i = blockIdx.x * blockDim.x + threadIdx.x;
    if (i >= ROWS * 64) return;
    float s = 0.f;
    #pragma unroll
    for (int z = 0; z < KSPL; z++) s += prp[(size_t)z * ROWS * 64 + i];
    pr[i] = s;
}

// ---------------- fused double causal dwconv (K=4) + silu ----------------
#define CCHUNK 16
__global__ void conv2_kernel(const float* __restrict__ in,
                             const float* __restrict__ w1, const float* __restrict__ b1,
                             const float* __restrict__ w2, const float* __restrict__ b2,
                             float* __restrict__ out)
{
    int idx = blockIdx.x * blockDim.x + threadIdx.x;
    if (idx >= BATCH * DI * (SEQ / CCHUNK)) return;
    int d  = idx % DI;
    int r  = idx / DI;
    int c0 = r % (SEQ / CCHUNK);
    int b  = r / (SEQ / CCHUNK);
    int t0 = c0 * CCHUNK;

    const float wa0 = w1[d*4+0], wa1 = w1[d*4+1], wa2 = w1[d*4+2], wa3 = w1[d*4+3];
    const float wb0 = w2[d*4+0], wb1 = w2[d*4+1], wb2 = w2[d*4+2], wb3 = w2[d*4+3];
    const float bb1 = b1[d], bb2 = b2[d];
    const float* pin  = in  + (size_t)b * SEQ * DI + d;
    float*       pout = out + (size_t)b * SEQ * DI + d;

    float h[3];
    #pragma unroll
    for (int j = 0; j < 3; j++) {
        int t = t0 - 3 + j;
        if (t >= 0) {
            float a = bb1;
            float wv[4] = {wa0, wa1, wa2, wa3};
            #pragma unroll
            for (int k = 0; k < 4; k++) {
                int tt = t - 3 + k;
                if (tt >= 0) a = fmaf(pin[(size_t)tt * DI], wv[k], a);
            }
            h[j] = siluf(a);
        } else h[j] = 0.f;
    }
    float xm3 = (t0 - 3 >= 0) ? pin[(size_t)(t0 - 3) * DI] : 0.f;
    float xm2 = (t0 - 2 >= 0) ? pin[(size_t)(t0 - 2) * DI] : 0.f;
    float xm1 = (t0 - 1 >= 0) ? pin[(size_t)(t0 - 1) * DI] : 0.f;

    #pragma unroll
    for (int t = t0; t < t0 + CCHUNK; t++) {
        float xt = pin[(size_t)t * DI];
        float v1 = bb1;
        v1 = fmaf(wa0, xm3, v1); v1 = fmaf(wa1, xm2, v1);
        v1 = fmaf(wa2, xm1, v1); v1 = fmaf(wa3, xt,  v1);
        float s = siluf(v1);
        float v2 = bb2;
        v2 = fmaf(wb0, h[0], v2); v2 = fmaf(wb1, h[1], v2);
        v2 = fmaf(wb2, h[2], v2); v2 = fmaf(wb3, s,    v2);
        pout[(size_t)t * DI] = siluf(v2);
        xm3 = xm2; xm2 = xm1; xm1 = xt;
        h[0] = h[1]; h[1] = h[2]; h[2] = s;
    }
}

// ---------------- x_proj weight zero-pad: W[l][33][2048] -> Wp[l][64][2048] ----------------
__global__ void wpad_kernel(const float* __restrict__ W, float* __restrict__ Wp)
{
    int idx = blockIdx.x * blockDim.x + threadIdx.x;
    if (idx >= NLAYER * 64 * DI) return;
    int k = idx % DI;
    int p = (idx / DI) % 64;
    int l = idx / (DI * 64);
    Wp[idx] = (p < 33) ? W[((size_t)l * 33 + p) * DI + k] : 0.f;
}

// ---------------- selective scan: smem-staged, double-buffered chunks ----------------
#define SCH 64
#define NCHK (SEQ / SCH)
#define SCAN_SMEM ((2*SCH*32 + 2*SCH*64 + SCH*32) * 4)

__global__ __launch_bounds__(256)
void scan_kernel(const float* __restrict__ x, const float* __restrict__ pr,
                 const float* __restrict__ dtw, const float* __restrict__ dtb,
                 const float* __restrict__ Dv, float* __restrict__ y)
{
    extern __shared__ float sm[];
    float* SX = sm;                     // [2][SCH][32]
    float* SP = sm + 2 * SCH * 32;      // [2][SCH][64]
    float* SY = SP + 2 * SCH * 64;      // [SCH][32]

    const int tid = threadIdx.x;
    const int dd  = tid >> 3;
    const int sub = tid & 7;
    const int nblk = DI / 32;
    const int b  = blockIdx.x / nblk;
    const int d0 = (blockIdx.x % nblk) * 32;
    const int d  = d0 + dd;

    const float wdt = dtw[d], bdt = dtb[d], Dd = Dv[d];
    const float A0 = -(float)(sub * 2 + 1);
    const float A1 = -(float)(sub * 2 + 2);
    float h0 = 0.f, h1 = 0.f;

    const float* xg = x + (size_t)b * SEQ * DI + d0;
    const float* pg = pr + (size_t)b * SEQ * 64;
    float*       yg = y + (size_t)b * SEQ * DI + d0;

    auto load_chunk = [&](int buf, int c) {
        int t0 = c * SCH;
        float* dx = SX + buf * SCH * 32;
        float* dp = SP + buf * SCH * 64;
        #pragma unroll
        for (int i = 0; i < 2; i++) {
            int sl = tid + i * 256;
            int t = sl >> 3, ch = sl & 7;
            cp16(smem_u32(dx + t * 32 + ch * 4), xg + (size_t)(t0 + t) * DI + ch * 4);
        }
        #pragma unroll
        for (int i = 0; i < 4; i++) {
            int sl = tid + i * 256;
            int t = sl >> 4, ch = sl & 15;
            cp16(smem_u32(dp + t * 64 + ch * 4), pg + (size_t)(t0 + t) * 64 + ch * 4);
        }
        asm volatile("cp.async.commit_group;" ::: "memory");
    };

    load_chunk(0, 0);
    load_chunk(1, 1);

    for (int c = 0; c < NCHK; c++) {
        const int buf = c & 1;
        if (c + 1 < NCHK) asm volatile("cp.async.wait_group 1;" ::: "memory");
        else              asm volatile("cp.async.wait_group 0;" ::: "memory");
        __syncthreads();

        const float* cx = SX + buf * SCH * 32;
        const float* cp = SP + buf * SCH * 64;
        #pragma unroll 4
        for (int s = 0; s < SCH; s++) {
            float dtraw = cp[s * 64];
            float xv    = cx[s * 32 + dd];
            float B0 = cp[s * 64 + 1 + 2 * sub], B1 = cp[s * 64 + 2 + 2 * sub];
            float C0 = cp[s * 64 + 17 + 2 * sub], C1 = cp[s * 64 + 18 + 2 * sub];
            float z  = fmaf(dtraw, wdt, bdt);
            float dt = (z > 20.f) ? z : log1pf(expf(z));
            float dtx = dt * xv;
            float t0v = fmaf(h0, A0, dtx * B0); h0 = fmaf(dt, t0v, h0);
            float t1v = fmaf(h1, A1, dtx * B1); h1 = fmaf(dt, t1v, h1);
            float yp = fmaf(h1, C1, h0 * C0);
            yp += __shfl_xor_sync(0xffffffffu, yp, 1);
            yp += __shfl_xor_sync(0xffffffffu, yp, 2);
            yp += __shfl_xor_sync(0xffffffffu, yp, 4);
            if (sub == 0) SY[s * 32 + dd] = fmaf(xv, Dd, yp);
        }
        __syncthreads();

        const int t0 = c * SCH;
        #pragma unroll
        for (int i = 0; i < 8; i++) {
            int sl = tid + i * 256;
            int s = sl >> 5, dd2 = sl & 31;
            yg[(size_t)(t0 + s) * DI + dd2] = SY[s * 32 + dd2];
        }
        if (c + 2 < NCHK) load_chunk(buf, c + 2);
    }
}

// ---------------- host orchestration ----------------
#define SMEM_G(TBN, NSTG) ((NSTG) * (128 + (TBN)) * SKEWF * 4)

extern "C" void kernel_launch(void* const* d_in, const int* in_sizes, int n_in,
                              void* d_out, int out_size)
{
    const float* hidden      = (const float*)d_in[0];
    const float* in_norm_g   = (const float*)d_in[1];
    const float* in_norm_b   = (const float*)d_in[2];
    const float* ln_g        = (const float*)d_in[3];
    const float* ln_b        = (const float*)d_in[4];
    const float* in_proj_w   = (const float*)d_in[5];
    const float* conv_w      = (const float*)d_in[6];
    const float* conv_b      = (const float*)d_in[7];
    const float* x_proj_w    = (const float*)d_in[8];
    const float* dt_proj_w   = (const float*)d_in[9];
    const float* dt_proj_b   = (const float*)d_in[10];
    const float* Dv          = (const float*)d_in[11];
    const float* mamba_ln_g  = (const float*)d_in[12];
    const float* mamba_ln_b  = (const float*)d_in[13];
    const float* out_proj_w  = (const float*)d_in[14];
    const float* op1_w       = (const float*)d_in[15];
    const float* op1_b       = (const float*)d_in[16];
    const float* op2_w       = (const float*)d_in[17];
    const float* op2_b       = (const float*)d_in[18];

    float *x, *xn, *res, *xi, *xi2, *pr, *prp, *y, *t1, *wp;
    cudaGetSymbolAddress((void**)&x,   g_x);
    cudaGetSymbolAddress((void**)&xn,  g_xn);
    cudaGetSymbolAddress((void**)&res, g_res);
    cudaGetSymbolAddress((void**)&xi,  g_xi);
    cudaGetSymbolAddress((void**)&xi2, g_xi2);
    cudaGetSymbolAddress((void**)&pr,  g_pr);
    cudaGetSymbolAddress((void**)&prp, g_prp);
    cudaGetSymbolAddress((void**)&y,   g_y);
    cudaGetSymbolAddress((void**)&t1,  g_t1);
    cudaGetSymbolAddress((void**)&wp,  g_wp);

    cudaFuncSetAttribute(gemm_mma<4,128,3>, cudaFuncAttributeMaxDynamicSharedMemorySize, SMEM_G(128,3));
    cudaFuncSetAttribute(gemm_mma<1,64,4>,  cudaFuncAttributeMaxDynamicSharedMemorySize, SMEM_G(64,4));
    cudaFuncSetAttribute(gemm_mma<2,64,4>,  cudaFuncAttributeMaxDynamicSharedMemorySize, SMEM_G(64,4));
    cudaFuncSetAttribute(gemm_mma<3,64,4>,  cudaFuncAttributeMaxDynamicSharedMemorySize, SMEM_G(64,4));
    cudaFuncSetAttribute(xproj_splitk,      cudaFuncAttributeMaxDynamicSharedMemorySize, SMEM_G(64,4));
    cudaFuncSetAttribute(scan_kernel, cudaFuncAttributeMaxDynamicSharedMemorySize, SCAN_SMEM);

    // zero-pad x_proj weights (all layers)
    wpad_kernel<<<(NLAYER * 64 * DI + 255) / 256, 256>>>(x_proj_w, wp);
    // x = LN(hidden)
    ln_kernel<false><<<ROWS, 256>>>(hidden, in_norm_g, in_norm_b, nullptr, x, HID);

    for (int l = 0; l < NLAYER; l++) {
        // xn = LN(x)
        ln_kernel<false><<<ROWS, 256>>>(x, ln_g + (size_t)l * HID, ln_b + (size_t)l * HID,
                                        nullptr, xn, HID);
        // in_proj (merged): xi = silu(first half), res = second half  (2048x4096x1024)
        gemm_mma<4,128,3><<<dim3(2 * DI / 128, ROWS / 128), 256, SMEM_G(128,3)>>>(
            xn, in_proj_w + (size_t)l * 2 * DI * HID, nullptr, res, xi, ROWS, 2 * DI, HID);
        // fused conv1+silu+conv2+silu : xi -> xi2
        conv2_kernel<<<(BATCH * DI * (SEQ / CCHUNK)) / 256, 256>>>(
            xi,
            conv_w + (size_t)(l * 2 + 0) * DI * KCONV, conv_b + (size_t)(l * 2 + 0) * DI,
            conv_w + (size_t)(l * 2 + 1) * DI * KCONV, conv_b + (size_t)(l * 2 + 1) * DI,
            xi2);
        // proj partials (split-K over 128 CTAs), then reduce
        xproj_splitk<<<dim3(KSPL, ROWS / 128), 256, SMEM_G(64,4)>>>(
            xi2, wp + (size_t)l * 64 * DI, prp, DI);
        prred_kernel<<<(ROWS * 64 + 255) / 256, 256>>>(prp, pr);
        // selective scan -> y (+ x_inner * D)
        scan_kernel<<<BATCH * (DI / 32), 256, SCAN_SMEM>>>(
            xi2, pr, dt_proj_w + (size_t)l * DI, dt_proj_b + (size_t)l * DI,
            Dv + (size_t)l * DI, y);
        // y = LN(y) * sigmoid(res)
        ln_kernel<true><<<ROWS, 256>>>(y, mamba_ln_g + (size_t)l * DI, mamba_ln_b + (size_t)l * DI,
                                       res, y, DI);
        // x = x + y @ out_proj_w^T
        gemm_mma<1,64,4><<<dim3(HID / 64, ROWS / 128), 256, SMEM_G(64,4)>>>(
            y, out_proj_w + (size_t)l * HID * DI, nullptr, x, x, ROWS, HID, DI);
    }

    // t1 = gelu(x @ op1_w^T + op1_b)
    gemm_mma<2,64,4><<<dim3(HID / 64, ROWS / 128), 256, SMEM_G(64,4)>>>(
        x, op1_w, op1_b, nullptr, t1, ROWS, HID, HID);
    // out = t1 @ op2_w^T + op2_b + hidden
    gemm_mma<3,64,4><<<dim3(HID / 64, ROWS / 128), 256, SMEM_G(64,4)>>>(
        t1, op2_w, op2_b, (float*)hidden, (float*)d_out, ROWS, HID, HID);
}

// round 10
// speedup vs baseline: 1.1176x; 1.0323x over previous
#include <cuda_runtime.h>
#include <math.h>
#include <stdint.h>

#define BATCH 2
#define SEQ   1024
#define HID   1024
#define DI    2048
#define NST   16
#define KCONV 4
#define NLAYER 4
#define ROWS  (BATCH*SEQ)      // 2048
#define LN_EPS 1e-5f
#define KSPL  8                // xproj split-K factor

// ---------------- scratch (device globals; no allocation) ----------------
__device__ float g_x  [ROWS*HID];
__device__ float g_xn [ROWS*HID];
__device__ float g_res[ROWS*DI];
__device__ float g_xi [ROWS*DI];
__device__ float g_xi2[ROWS*DI];
__device__ float g_pr [ROWS*64];          // padded proj (stride 64)
__device__ float g_prp[KSPL*ROWS*64];     // split-K partials
__device__ float g_y  [ROWS*DI];
__device__ float g_t1 [ROWS*HID];
__device__ float g_wp [NLAYER*64*DI];     // zero-padded x_proj weights

// ---------------- helpers ----------------
__device__ __forceinline__ float siluf(float v) { return v / (1.f + expf(-v)); }
__device__ __forceinline__ float sigmoidf_(float v) { return 1.f / (1.f + expf(-v)); }
__device__ __forceinline__ float geluf(float v) { return 0.5f * v * (1.f + erff(v * 0.70710678118654752f)); }
__device__ __forceinline__ uint32_t to_tf32u(float x) {
    uint32_t u;
    asm("cvt.rna.tf32.f32 %0, %1;" : "=r"(u) : "f"(x));
    return u;
}
__device__ __forceinline__ uint32_t smem_u32(const void* p) {
    uint32_t a;
    asm("{ .reg .u64 t; cvta.to.shared.u64 t, %1; cvt.u32.u64 %0, t; }" : "=r"(a) : "l"(p));
    return a;
}
__device__ __forceinline__ void cp16(uint32_t d, const void* g) {
    asm volatile("cp.async.cg.shared.global [%0], [%1], 16;" :: "r"(d), "l"(g));
}
#define MMA_TF32(acc, a0,a1,a2,a3, b0,b1)                                     \
    asm volatile(                                                             \
        "mma.sync.aligned.m16n8k8.row.col.f32.tf32.tf32.f32 "                 \
        "{%0,%1,%2,%3}, {%4,%5,%6,%7}, {%8,%9}, {%0,%1,%2,%3};"               \
        : "+f"((acc)[0]), "+f"((acc)[1]), "+f"((acc)[2]), "+f"((acc)[3])      \
        : "r"(a0), "r"(a1), "r"(a2), "r"(a3), "r"(b0), "r"(b1))

// ---------------- LayerNorm (optional sigmoid-gate epilogue, optional tf32 round) ----
template<bool GATE, bool ROUND>
__global__ void ln_kernel(const float* __restrict__ in,
                          const float* __restrict__ g,
                          const float* __restrict__ b,
                          const float* __restrict__ gate,
                          float* __restrict__ out, int cols)
{
    __shared__ float buf[2048];
    __shared__ float red[8];
    __shared__ float s_mu, s_rstd;
    const int row = blockIdx.x;
    const int tid = threadIdx.x;
    const float* pin = in + (size_t)row * cols;

    float s = 0.f;
    for (int c = tid; c < cols; c += 256) { float v = pin[c]; buf[c] = v; s += v; }
    #pragma unroll
    for (int o = 16; o; o >>= 1) s += __shfl_xor_sync(0xffffffffu, s, o);
    if ((tid & 31) == 0) red[tid >> 5] = s;
    __syncthreads();
    if (tid == 0) {
        float t = 0.f;
        #pragma unroll
        for (int i = 0; i < 8; i++) t += red[i];
        s_mu = t / (float)cols;
    }
    __syncthreads();
    const float mu = s_mu;
    float v2 = 0.f;
    for (int c = tid; c < cols; c += 256) { float xc = buf[c] - mu; v2 += xc * xc; }
    #pragma unroll
    for (int o = 16; o; o >>= 1) v2 += __shfl_xor_sync(0xffffffffu, v2, o);
    __syncthreads();
    if ((tid & 31) == 0) red[tid >> 5] = v2;
    __syncthreads();
    if (tid == 0) {
        float t = 0.f;
        #pragma unroll
        for (int i = 0; i < 8; i++) t += red[i];
        s_rstd = 1.f / sqrtf(t / (float)cols + LN_EPS);
    }
    __syncthreads();
    const float rstd = s_rstd;
    for (int c = tid; c < cols; c += 256) {
        float val = (buf[c] - mu) * rstd * g[c] + b[c];
        if (GATE) val *= sigmoidf_(gate[(size_t)row * cols + c]);
        if (ROUND) val = __uint_as_float(to_tf32u(val));
        out[(size_t)row * cols + c] = val;
    }
}

#define SKEWF 36

// ---------------- BIG GEMM: 128x128 tile, 4 warps (64x64 each), A pre-rounded ------
// C = A(MxK) * B(NxK)^T.  EPI 4: in_proj split (n<DI -> silu into C[m*DI+n],
// else raw into resid[m*DI+n-DI]).
template<int EPI, int NSTG>
__global__ __launch_bounds__(128, 2)
void gemm_big(const float* __restrict__ A, const float* __restrict__ Bw,
              float* __restrict__ resid, float* __restrict__ C,
              int M, int N, int K)
{
    constexpr int ASTG = 128 * SKEWF;
    constexpr int STG  = 2 * ASTG;
    extern __shared__ float sm[];

    const int tid  = threadIdx.x;            // 128
    const int lane = tid & 31;
    const int w    = tid >> 5;                // 0..3
    const int wm   = w & 1;                   // 2 in M (64 rows)
    const int wn   = w >> 1;                  // 2 in N (64 cols)
    const int m0 = blockIdx.y * 128;
    const int n0 = blockIdx.x * 128;
    const int lq = lane >> 2;
    const int lr = lane & 3;

    float acc[4][8][4];
    #pragma unroll
    for (int i = 0; i < 4; i++)
        #pragma unroll
        for (int j = 0; j < 8; j++)
            #pragma unroll
            for (int r = 0; r < 4; r++) acc[i][j][r] = 0.f;

    const int NC = K >> 5;

    auto load_stage = [&](int s, int k0) {
        float* dA = sm + s * STG;
        float* dB = dA + ASTG;
        #pragma unroll
        for (int i = 0; i < 8; i++) {
            int slot = tid + i * 128;
            int row = slot >> 3, c4 = (slot & 7) * 4;
            cp16(smem_u32(dA + row * SKEWF + c4), A + (size_t)(m0 + row) * K + k0 + c4);
            cp16(smem_u32(dB + row * SKEWF + c4), Bw + (size_t)(n0 + row) * K + k0 + c4);
        }
        asm volatile("cp.async.commit_group;" ::: "memory");
    };

    #pragma unroll
    for (int c = 0; c < NSTG - 1; c++) load_stage(c, c * 32);

    int s = 0, sl = NSTG - 1;
    for (int c = 0; c < NC; c++) {
        if (c <= NC - NSTG + 1) {
            asm volatile("cp.async.wait_group %0;" :: "n"(NSTG - 2) : "memory");
        } else {
            asm volatile("cp.async.wait_group 0;" ::: "memory");
        }
        __syncthreads();
        if (c + NSTG - 1 < NC) load_stage(sl, (c + NSTG - 1) * 32);

        const float* sA = sm + s * STG;
        const float* sB = sA + ASTG;
        #pragma unroll
        for (int kk = 0; kk < 32; kk += 8) {
            uint32_t afr[4][4], bfr[8][2];
            #pragma unroll
            for (int mt = 0; mt < 4; mt++) {           // A pre-rounded: raw bits
                int r = wm * 64 + mt * 16 + lq;
                afr[mt][0] = __float_as_uint(sA[(r    ) * SKEWF + kk     + lr]);
                afr[mt][1] = __float_as_uint(sA[(r + 8) * SKEWF + kk     + lr]);
                afr[mt][2] = __float_as_uint(sA[(r    ) * SKEWF + kk + 4 + lr]);
                afr[mt][3] = __float_as_uint(sA[(r + 8) * SKEWF + kk + 4 + lr]);
            }
            #pragma unroll
            for (int nt = 0; nt < 8; nt++) {           // weights: cvt.rna
                int rn = wn * 64 + nt * 8 + lq;
                bfr[nt][0] = to_tf32u(sB[rn * SKEWF + kk     + lr]);
                bfr[nt][1] = to_tf32u(sB[rn * SKEWF + kk + 4 + lr]);
            }
            #pragma unroll
            for (int mt = 0; mt < 4; mt++)
                #pragma unroll
                for (int nt = 0; nt < 8; nt++)
                    MMA_TF32(acc[mt][nt], afr[mt][0], afr[mt][1], afr[mt][2], afr[mt][3],
                             bfr[nt][0], bfr[nt][1]);
        }
        if (++s == NSTG) s = 0;
        if (++sl == NSTG) sl = 0;
    }

    #pragma unroll
    for (int mt = 0; mt < 4; mt++)
        #pragma unroll
        for (int nt = 0; nt < 8; nt++) {
            int r0 = m0 + wm * 64 + mt * 16 + lq;
            int cc = n0 + wn * 64 + nt * 8 + lr * 2;
            #pragma unroll
            for (int half = 0; half < 2; half++) {
                int m = r0 + half * 8;
                float v0 = acc[mt][nt][half * 2 + 0];
                float v1 = acc[mt][nt][half * 2 + 1];
                if (EPI == 4) {                        // tiles never straddle DI
                    if (cc < DI)
                        *reinterpret_cast<float2*>(&C[(size_t)m * DI + cc]) =
                            make_float2(siluf(v0), siluf(v1));
                    else
                        *reinterpret_cast<float2*>(&resid[(size_t)m * DI + cc - DI]) =
                            make_float2(v0, v1);
                } else {
                    *reinterpret_cast<float2*>(&C[(size_t)m * N + cc]) = make_float2(v0, v1);
                }
            }
        }
}

// ---------------- tf32 mma.sync GEMM (8 warps, 128xTBN), multi-stage ----------------
// EPI: 0 plain ; 1 +resid ; 2 gelu(acc+bias) ; 3 acc+bias+resid
template<int EPI, int TBN, int NSTG>
__global__ __launch_bounds__(256, 2)
void gemm_mma(const float* __restrict__ A, const float* __restrict__ Bw,
              const float* __restrict__ bias, float* __restrict__ resid,
              float* __restrict__ C, int M, int N, int K)
{
    constexpr int NT   = TBN / 32;
    constexpr int WNC  = TBN / 4;
    constexpr int ASTG = 128 * SKEWF;
    constexpr int BSTG = TBN * SKEWF;
    constexpr int STG  = ASTG + BSTG;
    extern __shared__ float sm[];

    const int tid  = threadIdx.x;
    const int lane = tid & 31;
    const int w    = tid >> 5;
    const int wm   = w & 1;
    const int wn   = w >> 1;
    const int m0 = blockIdx.y * 128;
    const int n0 = blockIdx.x * TBN;
    const int lq = lane >> 2;
    const int lr = lane & 3;

    float acc[4][NT][4];
    #pragma unroll
    for (int i = 0; i < 4; i++)
        #pragma unroll
        for (int j = 0; j < NT; j++)
            #pragma unroll
            for (int r = 0; r < 4; r++) acc[i][j][r] = 0.f;

    const int NC = K >> 5;

    auto load_stage = [&](int s, int k0) {
        float* dA = sm + s * STG;
        float* dB = dA + ASTG;
        #pragma unroll
        for (int i = 0; i < 4; i++) {
            int slot = tid + i * 256;
            int row = slot >> 3, c4 = (slot & 7) * 4;
            cp16(smem_u32(dA + row * SKEWF + c4), A + (size_t)(m0 + row) * K + k0 + c4);
        }
        #pragma unroll
        for (int i = 0; i < TBN * 8 / 256; i++) {
            int slot = tid + i * 256;
            int row = slot >> 3, c4 = (slot & 7) * 4;
            cp16(smem_u32(dB + row * SKEWF + c4), Bw + (size_t)(n0 + row) * K + k0 + c4);
        }
        asm volatile("cp.async.commit_group;" ::: "memory");
    };

    #pragma unroll
    for (int c = 0; c < NSTG - 1; c++) load_stage(c, c * 32);

    int s = 0, sl = NSTG - 1;
    for (int c = 0; c < NC; c++) {
        if (c <= NC - NSTG + 1) {
            asm volatile("cp.async.wait_group %0;" :: "n"(NSTG - 2) : "memory");
        } else {
            asm volatile("cp.async.wait_group 0;" ::: "memory");
        }
        __syncthreads();
        if (c + NSTG - 1 < NC) load_stage(sl, (c + NSTG - 1) * 32);

        const float* sA = sm + s * STG;
        const float* sB = sA + ASTG;
        #pragma unroll
        for (int kk = 0; kk < 32; kk += 8) {
            uint32_t afr[4][4], bfr[NT][2];
            #pragma unroll
            for (int mt = 0; mt < 4; mt++) {
                int r = wm * 64 + mt * 16 + lq;
                afr[mt][0] = to_tf32u(sA[(r    ) * SKEWF + kk     + lr]);
                afr[mt][1] = to_tf32u(sA[(r + 8) * SKEWF + kk     + lr]);
                afr[mt][2] = to_tf32u(sA[(r    ) * SKEWF + kk + 4 + lr]);
                afr[mt][3] = to_tf32u(sA[(r + 8) * SKEWF + kk + 4 + lr]);
            }
            #pragma unroll
            for (int nt = 0; nt < NT; nt++) {
                int rn = wn * WNC + nt * 8 + lq;
                bfr[nt][0] = to_tf32u(sB[rn * SKEWF + kk     + lr]);
                bfr[nt][1] = to_tf32u(sB[rn * SKEWF + kk + 4 + lr]);
            }
            #pragma unroll
            for (int mt = 0; mt < 4; mt++)
                #pragma unroll
                for (int nt = 0; nt < NT; nt++)
                    MMA_TF32(acc[mt][nt], afr[mt][0], afr[mt][1], afr[mt][2], afr[mt][3],
                             bfr[nt][0], bfr[nt][1]);
        }
        if (++s == NSTG) s = 0;
        if (++sl == NSTG) sl = 0;
    }

    #pragma unroll
    for (int mt = 0; mt < 4; mt++) {
        #pragma unroll
        for (int nt = 0; nt < NT; nt++) {
            int r0 = m0 + wm * 64 + mt * 16 + lq;
            int cc = n0 + wn * WNC + nt * 8 + lr * 2;
            #pragma unroll
            for (int half = 0; half < 2; half++) {
                int m = r0 + half * 8;
                float v0 = acc[mt][nt][half * 2 + 0];
                float v1 = acc[mt][nt][half * 2 + 1];
                if (EPI == 0) {
                    *reinterpret_cast<float2*>(&C[(size_t)m * N + cc]) = make_float2(v0, v1);
                } else if (EPI == 1) {
                    float2 rr = *reinterpret_cast<const float2*>(&resid[(size_t)m * N + cc]);
                    *reinterpret_cast<float2*>(&C[(size_t)m * N + cc]) = make_float2(v0 + rr.x, v1 + rr.y);
                } else if (EPI == 2) {
                    *reinterpret_cast<float2*>(&C[(size_t)m * N + cc]) =
                        make_float2(geluf(v0 + bias[cc]), geluf(v1 + bias[cc + 1]));
                } else if (EPI == 3) {
                    float2 rr = *reinterpret_cast<const float2*>(&resid[(size_t)m * N + cc]);
                    *reinterpret_cast<float2*>(&C[(size_t)m * N + cc]) =
                        make_float2(v0 + bias[cc] + rr.x, v1 + bias[cc + 1] + rr.y);
                }
            }
        }
    }
}

// ---------------- xproj split-K GEMM ----------------
__global__ __launch_bounds__(256, 2)
void xproj_splitk(const float* __restrict__ A, const float* __restrict__ Bw,
                  float* __restrict__ Cp, int K)
{
    constexpr int TBN  = 64;
    constexpr int NSTG = 4;
    constexpr int NT   = TBN / 32;
    constexpr int WNC  = TBN / 4;
    constexpr int ASTG = 128 * SKEWF;
    constexpr int BSTG = TBN * SKEWF;
    constexpr int STG  = ASTG + BSTG;
    extern __shared__ float sm[];

    const int tid  = threadIdx.x;
    const int lane = tid & 31;
    const int w    = tid >> 5;
    const int wm   = w & 1;
    const int wn   = w >> 1;
    const int m0 = blockIdx.y * 128;
    const int kz = blockIdx.x;
    const int kbase = kz * (K / KSPL);
    const int lq = lane >> 2;
    const int lr = lane & 3;
    float* C = Cp + (size_t)kz * ROWS * 64;

    float acc[4][NT][4];
    #pragma unroll
    for (int i = 0; i < 4; i++)
        #pragma unroll
        for (int j = 0; j < NT; j++)
            #pragma unroll
            for (int r = 0; r < 4; r++) acc[i][j][r] = 0.f;

    const int NC = (K / KSPL) >> 5;

    auto load_stage = [&](int s, int k0) {
        float* dA = sm + s * STG;
        float* dB = dA + ASTG;
        #pragma unroll
        for (int i = 0; i < 4; i++) {
            int slot = tid + i * 256;
            int row = slot >> 3, c4 = (slot & 7) * 4;
            cp16(smem_u32(dA + row * SKEWF + c4), A + (size_t)(m0 + row) * K + kbase + k0 + c4);
        }
        #pragma unroll
        for (int i = 0; i < 2; i++) {
            int slot = tid + i * 256;
            int row = slot >> 3, c4 = (slot & 7) * 4;
            cp16(smem_u32(dB + row * SKEWF + c4), Bw + (size_t)row * K + kbase + k0 + c4);
        }
        asm volatile("cp.async.commit_group;" ::: "memory");
    };

    #pragma unroll
    for (int c = 0; c < NSTG - 1; c++) load_stage(c, c * 32);

    int s = 0, sl = NSTG - 1;
    for (int c = 0; c < NC; c++) {
        if (c <= NC - NSTG + 1) {
            asm volatile("cp.async.wait_group %0;" :: "n"(NSTG - 2) : "memory");
        } else {
            asm volatile("cp.async.wait_group 0;" ::: "memory");
        }
        __syncthreads();
        if (c + NSTG - 1 < NC) load_stage(sl, (c + NSTG - 1) * 32);

        const float* sA = sm + s * STG;
        const float* sB = sA + ASTG;
        #pragma unroll
        for (int kk = 0; kk < 32; kk += 8) {
            uint32_t afr[4][4], bfr[NT][2];
            #pragma unroll
            for (int mt = 0; mt < 4; mt++) {
                int r = wm * 64 + mt * 16 + lq;
                afr[mt][0] = to_tf32u(sA[(r    ) * SKEWF + kk     + lr]);
                afr[mt][1] = to_tf32u(sA[(r + 8) * SKEWF + kk     + lr]);
                afr[mt][2] = to_tf32u(sA[(r    ) * SKEWF + kk + 4 + lr]);
                afr[mt][3] = to_tf32u(sA[(r + 8) * SKEWF + kk + 4 + lr]);
            }
            #pragma unroll
            for (int nt = 0; nt < NT; nt++) {
                int rn = wn * WNC + nt * 8 + lq;
                bfr[nt][0] = to_tf32u(sB[rn * SKEWF + kk     + lr]);
                bfr[nt][1] = to_tf32u(sB[rn * SKEWF + kk + 4 + lr]);
            }
            #pragma unroll
            for (int mt = 0; mt < 4; mt++)
                #pragma unroll
                for (int nt = 0; nt < NT; nt++)
                    MMA_TF32(acc[mt][nt], afr[mt][0], afr[mt][1], afr[mt][2], afr[mt][3],
                             bfr[nt][0], bfr[nt][1]);
        }
        if (++s == NSTG) s = 0;
        if (++sl == NSTG) sl = 0;
    }

    #pragma unroll
    for (int mt = 0; mt < 4; mt++)
        #pragma unroll
        for (int nt = 0; nt < NT; nt++) {
            int r0 = m0 + wm * 64 + mt * 16 + lq;
            int cc = wn * WNC + nt * 8 + lr * 2;
            #pragma unroll
            for (int half = 0; half < 2; half++) {
                int m = r0 + half * 8;
                *reinterpret_cast<float2*>(&C[(size_t)m * 64 + cc]) =
                    make_float2(acc[mt][nt][half * 2 + 0], acc[mt][nt][half * 2 + 1]);
            }
        }
}

// ---------------- split-K reduce ----------------
__global__ void prred_kernel(const float* __restrict__ prp, float* __restrict__ pr)
{
    int i = blockIdx.x * blockDim.x + threadIdx.x;
    if (i >= ROWS * 64) return;
    float s = 0.f;
    #pragma unroll
    for (int z = 0; z < KSPL; z++) s += prp[(size_t)z * ROWS * 64 + i];
    pr[i] = s;
}

// ---------------- fused double causal dwconv (K=4) + silu ----------------
#define CCHUNK 16
__global__ void conv2_kernel(const float* __restrict__ in,
                             const float* __restrict__ w1, const float* __restrict__ b1,
                             const float* __restrict__ w2, const float* __restrict__ b2,
                             float* __restrict__ out)
{
    int idx = blockIdx.x * blockDim.x + threadIdx.x;
    if (idx >= BATCH * DI * (SEQ / CCHUNK)) return;
    int d  = idx % DI;
    int r  = idx / DI;
    int c0 = r % (SEQ / CCHUNK);
    int b  = r / (SEQ / CCHUNK);
    int t0 = c0 * CCHUNK;

    const float wa0 = w1[d*4+0], wa1 = w1[d*4+1], wa2 = w1[d*4+2], wa3 = w1[d*4+3];
    const float wb0 = w2[d*4+0], wb1 = w2[d*4+1], wb2 = w2[d*4+2], wb3 = w2[d*4+3];
    const float bb1 = b1[d], bb2 = b2[d];
    const float* pin  = in  + (size_t)b * SEQ * DI + d;
    float*       pout = out + (size_t)b * SEQ * DI + d;

    float h[3];
    #pragma unroll
    for (int j = 0; j < 3; j++) {
        int t = t0 - 3 + j;
        if (t >= 0) {
            float a = bb1;
            float wv[4] = {wa0, wa1, wa2, wa3};
            #pragma unroll
            for (int k = 0; k < 4; k++) {
                int tt = t - 3 + k;
                if (tt >= 0) a = fmaf(pin[(size_t)tt * DI], wv[k], a);
            }
            h[j] = siluf(a);
        } else h[j] = 0.f;
    }
    float xm3 = (t0 - 3 >= 0) ? pin[(size_t)(t0 - 3) * DI] : 0.f;
    float xm2 = (t0 - 2 >= 0) ? pin[(size_t)(t0 - 2) * DI] : 0.f;
    float xm1 = (t0 - 1 >= 0) ? pin[(size_t)(t0 - 1) * DI] : 0.f;

    #pragma unroll
    for (int t = t0; t < t0 + CCHUNK; t++) {
        float xt = pin[(size_t)t * DI];
        float v1 = bb1;
        v1 = fmaf(wa0, xm3, v1); v1 = fmaf(wa1, xm2, v1);
        v1 = fmaf(wa2, xm1, v1); v1 = fmaf(wa3, xt,  v1);
        float s = siluf(v1);
        float v2 = bb2;
        v2 = fmaf(wb0, h[0], v2); v2 = fmaf(wb1, h[1], v2);
        v2 = fmaf(wb2, h[2], v2); v2 = fmaf(wb3, s,    v2);
        pout[(size_t)t * DI] = siluf(v2);
        xm3 = xm2; xm2 = xm1; xm1 = xt;
        h[0] = h[1]; h[1] = h[2]; h[2] = s;
    }
}

// ---------------- x_proj weight zero-pad ----------------
__global__ void wpad_kernel(const float* __restrict__ W, float* __restrict__ Wp)
{
    int idx = blockIdx.x * blockDim.x + threadIdx.x;
    if (idx >= NLAYER * 64 * DI) return;
    int k = idx % DI;
    int p = (idx / DI) % 64;
    int l = idx / (DI * 64);
    Wp[idx] = (p < 33) ? W[((size_t)l * 33 + p) * DI + k] : 0.f;
}

// ---------------- selective scan: smem-staged, double-buffered chunks ----------------
#define SCH 64
#define NCHK (SEQ / SCH)
#define SCAN_SMEM ((2*SCH*32 + 2*SCH*64 + SCH*32) * 4)

__global__ __launch_bounds__(256)
void scan_kernel(const float* __restrict__ x, const float* __restrict__ pr,
                 const float* __restrict__ dtw, const float* __restrict__ dtb,
                 const float* __restrict__ Dv, float* __restrict__ y)
{
    extern __shared__ float sm[];
    float* SX = sm;
    float* SP = sm + 2 * SCH * 32;
    float* SY = SP + 2 * SCH * 64;

    const int tid = threadIdx.x;
    const int dd  = tid >> 3;
    const int sub = tid & 7;
    const int nblk = DI / 32;
    const int b  = blockIdx.x / nblk;
    const int d0 = (blockIdx.x % nblk) * 32;
    const int d  = d0 + dd;

    const float wdt = dtw[d], bdt = dtb[d], Dd = Dv[d];
    const float A0 = -(float)(sub * 2 + 1);
    const float A1 = -(float)(sub * 2 + 2);
    float h0 = 0.f, h1 = 0.f;

    const float* xg = x + (size_t)b * SEQ * DI + d0;
    const float* pg = pr + (size_t)b * SEQ * 64;
    float*       yg = y + (size_t)b * SEQ * DI + d0;

    auto load_chunk = [&](int buf, int c) {
        int t0 = c * SCH;
        float* dx = SX + buf * SCH * 32;
        float* dp = SP + buf * SCH * 64;
        #pragma unroll
        for (int i = 0; i < 2; i++) {
            int sl = tid + i * 256;
            int t = sl >> 3, ch = sl & 7;
            cp16(smem_u32(dx + t * 32 + ch * 4), xg + (size_t)(t0 + t) * DI + ch * 4);
        }
        #pragma unroll
        for (int i = 0; i < 4; i++) {
            int sl = tid + i * 256;
            int t = sl >> 4, ch = sl & 15;
            cp16(smem_u32(dp + t * 64 + ch * 4), pg + (size_t)(t0 + t) * 64 + ch * 4);
        }
        asm volatile("cp.async.commit_group;" ::: "memory");
    };

    load_chunk(0, 0);
    load_chunk(1, 1);

    for (int c = 0; c < NCHK; c++) {
        const int buf = c & 1;
        if (c + 1 < NCHK) asm volatile("cp.async.wait_group 1;" ::: "memory");
        else              asm volatile("cp.async.wait_group 0;" ::: "memory");
        __syncthreads();

        const float* cx = SX + buf * SCH * 32;
        const float* cp = SP + buf * SCH * 64;
        #pragma unroll 4
        for (int s = 0; s < SCH; s++) {
            float dtraw = cp[s * 64];
            float xv    = cx[s * 32 + dd];
            float B0 = cp[s * 64 + 1 + 2 * sub], B1 = cp[s * 64 + 2 + 2 * sub];
            float C0 = cp[s * 64 + 17 + 2 * sub], C1 = cp[s * 64 + 18 + 2 * sub];
            float z  = fmaf(dtraw, wdt, bdt);
            float dt = (z > 20.f) ? z : log1pf(expf(z));
            float dtx = dt * xv;
            float t0v = fmaf(h0, A0, dtx * B0); h0 = fmaf(dt, t0v, h0);
            float t1v = fmaf(h1, A1, dtx * B1); h1 = fmaf(dt, t1v, h1);
            float yp = fmaf(h1, C1, h0 * C0);
            yp += __shfl_xor_sync(0xffffffffu, yp, 1);
            yp += __shfl_xor_sync(0xffffffffu, yp, 2);
            yp += __shfl_xor_sync(0xffffffffu, yp, 4);
            if (sub == 0) SY[s * 32 + dd] = fmaf(xv, Dd, yp);
        }
        __syncthreads();

        const int t0 = c * SCH;
        #pragma unroll
        for (int i = 0; i < 8; i++) {
            int sl = tid + i * 256;
            int s = sl >> 5, dd2 = sl & 31;
            yg[(size_t)(t0 + s) * DI + dd2] = SY[s * 32 + dd2];
        }
        if (c + 2 < NCHK) load_chunk(buf, c + 2);
    }
}

// ---------------- host orchestration ----------------
#define SMEM_G(TBN, NSTG) ((NSTG) * (128 + (TBN)) * SKEWF * 4)

extern "C" void kernel_launch(void* const* d_in, const int* in_sizes, int n_in,
                              void* d_out, int out_size)
{
    const float* hidden      = (const float*)d_in[0];
    const float* in_norm_g   = (const float*)d_in[1];
    const float* in_norm_b   = (const float*)d_in[2];
    const float* ln_g        = (const float*)d_in[3];
    const float* ln_b        = (const float*)d_in[4];
    const float* in_proj_w   = (const float*)d_in[5];
    const float* conv_w      = (const float*)d_in[6];
    const float* conv_b      = (const float*)d_in[7];
    const float* x_proj_w    = (const float*)d_in[8];
    const float* dt_proj_w   = (const float*)d_in[9];
    const float* dt_proj_b   = (const float*)d_in[10];
    const float* Dv          = (const float*)d_in[11];
    const float* mamba_ln_g  = (const float*)d_in[12];
    const float* mamba_ln_b  = (const float*)d_in[13];
    const float* out_proj_w  = (const float*)d_in[14];
    const float* op1_w       = (const float*)d_in[15];
    const float* op1_b       = (const float*)d_in[16];
    const float* op2_w       = (const float*)d_in[17];
    const float* op2_b       = (const float*)d_in[18];

    float *x, *xn, *res, *xi, *xi2, *pr, *prp, *y, *t1, *wp;
    cudaGetSymbolAddress((void**)&x,   g_x);
    cudaGetSymbolAddress((void**)&xn,  g_xn);
    cudaGetSymbolAddress((void**)&res, g_res);
    cudaGetSymbolAddress((void**)&xi,  g_xi);
    cudaGetSymbolAddress((void**)&xi2, g_xi2);
    cudaGetSymbolAddress((void**)&pr,  g_pr);
    cudaGetSymbolAddress((void**)&prp, g_prp);
    cudaGetSymbolAddress((void**)&y,   g_y);
    cudaGetSymbolAddress((void**)&t1,  g_t1);
    cudaGetSymbolAddress((void**)&wp,  g_wp);

    cudaFuncSetAttribute(gemm_big<4,3>,     cudaFuncAttributeMaxDynamicSharedMemorySize, SMEM_G(128,3));
    cudaFuncSetAttribute(gemm_mma<1,64,4>,  cudaFuncAttributeMaxDynamicSharedMemorySize, SMEM_G(64,4));
    cudaFuncSetAttribute(gemm_mma<2,64,4>,  cudaFuncAttributeMaxDynamicSharedMemorySize, SMEM_G(64,4));
    cudaFuncSetAttribute(gemm_mma<3,64,4>,  cudaFuncAttributeMaxDynamicSharedMemorySize, SMEM_G(64,4));
    cudaFuncSetAttribute(xproj_splitk,      cudaFuncAttributeMaxDynamicSharedMemorySize, SMEM_G(64,4));
    cudaFuncSetAttribute(scan_kernel, cudaFuncAttributeMaxDynamicSharedMemorySize, SCAN_SMEM);

    // zero-pad x_proj weights (all layers)
    wpad_kernel<<<(NLAYER * 64 * DI + 255) / 256, 256>>>(x_proj_w, wp);
    // x = LN(hidden)  (x is residual: full precision)
    ln_kernel<false,false><<<ROWS, 256>>>(hidden, in_norm_g, in_norm_b, nullptr, x, HID);

    for (int l = 0; l < NLAYER; l++) {
        // xn = LN(x), tf32-rounded (consumed only by in_proj GEMM)
        ln_kernel<false,true><<<ROWS, 256>>>(x, ln_g + (size_t)l * HID, ln_b + (size_t)l * HID,
                                             nullptr, xn, HID);
        // in_proj (merged, big-tile): xi = silu(first half), res = second half
        gemm_big<4,3><<<dim3(2 * DI / 128, ROWS / 128), 128, SMEM_G(128,3)>>>(
            xn, in_proj_w + (size_t)l * 2 * DI * HID, res, xi, ROWS, 2 * DI, HID);
        // fused conv1+silu+conv2+silu : xi -> xi2
        conv2_kernel<<<(BATCH * DI * (SEQ / CCHUNK)) / 256, 256>>>(
            xi,
            conv_w + (size_t)(l * 2 + 0) * DI * KCONV, conv_b + (size_t)(l * 2 + 0) * DI,
            conv_w + (size_t)(l * 2 + 1) * DI * KCONV, conv_b + (size_t)(l * 2 + 1) * DI,
            xi2);
        // proj partials (split-K over 128 CTAs), then reduce
        xproj_splitk<<<dim3(KSPL, ROWS / 128), 256, SMEM_G(64,4)>>>(
            xi2, wp + (size_t)l * 64 * DI, prp, DI);
        prred_kernel<<<(ROWS * 64 + 255) / 256, 256>>>(prp, pr);
        // selective scan -> y (+ x_inner * D)
        scan_kernel<<<BATCH * (DI / 32), 256, SCAN_SMEM>>>(
            xi2, pr, dt_proj_w + (size_t)l * DI, dt_proj_b + (size_t)l * DI,
            Dv + (size_t)l * DI, y);
        // y = LN(y) * sigmoid(res)
        ln_kernel<true,false><<<ROWS, 256>>>(y, mamba_ln_g + (size_t)l * DI,
                                             mamba_ln_b + (size_t)l * DI, res, y, DI);
        // x = x + y @ out_proj_w^T
        gemm_mma<1,64,4><<<dim3(HID / 64, ROWS / 128), 256, SMEM_G(64,4)>>>(
            y, out_proj_w + (size_t)l * HID * DI, nullptr, x, x, ROWS, HID, DI);
    }

    // t1 = gelu(x @ op1_w^T + op1_b)
    gemm_mma<2,64,4><<<dim3(HID / 64, ROWS / 128), 256, SMEM_G(64,4)>>>(
        x, op1_w, op1_b, nullptr, t1, ROWS, HID, HID);
    // out = t1 @ op2_w^T + op2_b + hidden
    gemm_mma<3,64,4><<<dim3(HID / 64, ROWS / 128), 256, SMEM_G(64,4)>>>(
        t1, op2_w, op2_b, (float*)hidden, (float*)d_out, ROWS, HID, HID);
}

// round 11
// speedup vs baseline: 1.4073x; 1.2593x over previous
#include <cuda_runtime.h>
#include <cuda_fp16.h>
#include <math.h>
#include <stdint.h>

#define BATCH 2
#define SEQ   1024
#define HID   1024
#define DI    2048
#define NST   16
#define KCONV 4
#define NLAYER 4
#define ROWS  (BATCH*SEQ)      // 2048
#define LN_EPS 1e-5f
#define KSPL  8                // xproj split-K factor

// ---------------- scratch (device globals; no allocation) ----------------
__device__ float g_x  [ROWS*HID];
__device__ float g_res[ROWS*DI];
__device__ float g_xi [ROWS*DI];
__device__ float g_xi2[ROWS*DI];
__device__ float g_pr [ROWS*64];          // padded proj (stride 64)
__device__ float g_prp[KSPL*ROWS*64];     // split-K partials
__device__ float g_y  [ROWS*DI];
__device__ float g_wp [NLAYER*64*DI];     // zero-padded x_proj weights (fp32, tf32 path)
// half operands
__device__ __half g_xnh [ROWS*HID];
__device__ __half g_yh  [ROWS*DI];
__device__ __half g_xh  [ROWS*HID];
__device__ __half g_t1h [ROWS*HID];
__device__ __half g_wih [NLAYER*2*DI*HID];
__device__ __half g_woh [NLAYER*HID*DI];
__device__ __half g_op1h[HID*HID];
__device__ __half g_op2h[HID*HID];

// ---------------- helpers ----------------
__device__ __forceinline__ float siluf(float v) { return v / (1.f + expf(-v)); }
__device__ __forceinline__ float sigmoidf_(float v) { return 1.f / (1.f + expf(-v)); }
__device__ __forceinline__ float geluf(float v) { return 0.5f * v * (1.f + erff(v * 0.70710678118654752f)); }
__device__ __forceinline__ uint32_t to_tf32u(float x) {
    uint32_t u;
    asm("cvt.rna.tf32.f32 %0, %1;" : "=r"(u) : "f"(x));
    return u;
}
__device__ __forceinline__ uint32_t smem_u32(const void* p) {
    uint32_t a;
    asm("{ .reg .u64 t; cvta.to.shared.u64 t, %1; cvt.u32.u64 %0, t; }" : "=r"(a) : "l"(p));
    return a;
}
__device__ __forceinline__ void cp16(uint32_t d, const void* g) {
    asm volatile("cp.async.cg.shared.global [%0], [%1], 16;" :: "r"(d), "l"(g));
}
#define MMA_TF32(acc, a0,a1,a2,a3, b0,b1)                                     \
    asm volatile(                                                             \
        "mma.sync.aligned.m16n8k8.row.col.f32.tf32.tf32.f32 "                 \
        "{%0,%1,%2,%3}, {%4,%5,%6,%7}, {%8,%9}, {%0,%1,%2,%3};"               \
        : "+f"((acc)[0]), "+f"((acc)[1]), "+f"((acc)[2]), "+f"((acc)[3])      \
        : "r"(a0), "r"(a1), "r"(a2), "r"(a3), "r"(b0), "r"(b1))
#define MMA_F16(acc, a0,a1,a2,a3, b0,b1)                                      \
    asm volatile(                                                             \
        "mma.sync.aligned.m16n8k16.row.col.f32.f16.f16.f32 "                  \
        "{%0,%1,%2,%3}, {%4,%5,%6,%7}, {%8,%9}, {%0,%1,%2,%3};"               \
        : "+f"((acc)[0]), "+f"((acc)[1]), "+f"((acc)[2]), "+f"((acc)[3])      \
        : "r"(a0), "r"(a1), "r"(a2), "r"(a3), "r"(b0), "r"(b1))

// ---------------- fp32 -> fp16 weight convert ----------------
__global__ void f2h_kernel(const float* __restrict__ in, __half* __restrict__ out, int n)
{
    int i = blockIdx.x * blockDim.x + threadIdx.x;
    if (i < n) out[i] = __float2half_rn(in[i]);
}

// ---------------- LayerNorm (gate epilogue optional; fp32 or fp16 output) ----------
template<bool GATE, bool OUTH>
__global__ void ln_kernel(const float* __restrict__ in,
                          const float* __restrict__ g,
                          const float* __restrict__ b,
                          const float* __restrict__ gate,
                          void* __restrict__ outv, int cols)
{
    __shared__ float buf[2048];
    __shared__ float red[8];
    __shared__ float s_mu, s_rstd;
    const int row = blockIdx.x;
    const int tid = threadIdx.x;
    const float* pin = in + (size_t)row * cols;

    float s = 0.f;
    for (int c = tid; c < cols; c += 256) { float v = pin[c]; buf[c] = v; s += v; }
    #pragma unroll
    for (int o = 16; o; o >>= 1) s += __shfl_xor_sync(0xffffffffu, s, o);
    if ((tid & 31) == 0) red[tid >> 5] = s;
    __syncthreads();
    if (tid == 0) {
        float t = 0.f;
        #pragma unroll
        for (int i = 0; i < 8; i++) t += red[i];
        s_mu = t / (float)cols;
    }
    __syncthreads();
    const float mu = s_mu;
    float v2 = 0.f;
    for (int c = tid; c < cols; c += 256) { float xc = buf[c] - mu; v2 += xc * xc; }
    #pragma unroll
    for (int o = 16; o; o >>= 1) v2 += __shfl_xor_sync(0xffffffffu, v2, o);
    __syncthreads();
    if ((tid & 31) == 0) red[tid >> 5] = v2;
    __syncthreads();
    if (tid == 0) {
        float t = 0.f;
        #pragma unroll
        for (int i = 0; i < 8; i++) t += red[i];
        s_rstd = 1.f / sqrtf(t / (float)cols + LN_EPS);
    }
    __syncthreads();
    const float rstd = s_rstd;
    for (int c = tid; c < cols; c += 256) {
        float val = (buf[c] - mu) * rstd * g[c] + b[c];
        if (GATE) val *= sigmoidf_(gate[(size_t)row * cols + c]);
        if (OUTH) ((__half*)outv)[(size_t)row * cols + c] = __float2half_rn(val);
        else      ((float*)outv)[(size_t)row * cols + c] = val;
    }
}

// ---------------- fp16 tensor-core GEMM: C = A(MxK) * B(NxK)^T -------------------
// 128x128 tile, 4 warps (64x64 each), NSTG-stage cp.async, fp32 accumulate.
// EPI: 1 out_proj (C=resid+acc fp32, Ch=half copy) ; 2 gelu(acc+bias) -> Ch half ;
//      3 acc+bias+resid -> C fp32 ; 4 in_proj split (silu->C fp32 | raw->residF)
#define RSTR 40                             // halves per smem row (32 + 8 skew)

template<int EPI, int NSTG>
__global__ __launch_bounds__(128, 2)
void gemm_h(const __half* __restrict__ A, const __half* __restrict__ Bw,
            const float* __restrict__ bias, float* __restrict__ residF,
            float* __restrict__ C, __half* __restrict__ Ch,
            int M, int N, int K)
{
    constexpr int ASTG = 128 * RSTR;        // halves per stage per matrix
    constexpr int STG  = 2 * ASTG;
    extern __shared__ __half smh[];

    const int tid  = threadIdx.x;           // 128
    const int lane = tid & 31;
    const int w    = tid >> 5;
    const int wm   = w & 1;
    const int wn   = w >> 1;
    const int m0 = blockIdx.y * 128;
    const int n0 = blockIdx.x * 128;
    const int lq = lane >> 2;
    const int lr = lane & 3;

    float acc[4][8][4];
    #pragma unroll
    for (int i = 0; i < 4; i++)
        #pragma unroll
        for (int j = 0; j < 8; j++)
            #pragma unroll
            for (int r = 0; r < 4; r++) acc[i][j][r] = 0.f;

    const int NC = K >> 5;                  // 32 k-halves per chunk

    auto load_stage = [&](int s, int k0) {
        __half* dA = smh + s * STG;
        __half* dB = dA + ASTG;
        #pragma unroll
        for (int i = 0; i < 4; i++) {
            int slot = tid + i * 128;       // 0..511
            int row = slot >> 2, c = slot & 3;
            cp16(smem_u32(dA + row * RSTR + c * 8), A  + (size_t)(m0 + row) * K + k0 + c * 8);
            cp16(smem_u32(dB + row * RSTR + c * 8), Bw + (size_t)(n0 + row) * K + k0 + c * 8);
        }
        asm volatile("cp.async.commit_group;" ::: "memory");
    };

    #pragma unroll
    for (int c = 0; c < NSTG - 1; c++) load_stage(c, c * 32);

    int s = 0, sl = NSTG - 1;
    for (int c = 0; c < NC; c++) {
        if (c <= NC - NSTG + 1) {
            asm volatile("cp.async.wait_group %0;" :: "n"(NSTG - 2) : "memory");
        } else {
            asm volatile("cp.async.wait_group 0;" ::: "memory");
        }
        __syncthreads();
        if (c + NSTG - 1 < NC) load_stage(sl, (c + NSTG - 1) * 32);

        const __half* sA = smh + s * STG;
        const __half* sB = sA + ASTG;
        #pragma unroll
        for (int kk = 0; kk < 32; kk += 16) {
            uint32_t af[4][4], bf[8][2];
            #pragma unroll
            for (int mt = 0; mt < 4; mt++) {
                int r = wm * 64 + mt * 16 + lq;
                af[mt][0] = *reinterpret_cast<const uint32_t*>(&sA[(r    ) * RSTR + kk     + lr * 2]);
                af[mt][1] = *reinterpret_cast<const uint32_t*>(&sA[(r + 8) * RSTR + kk     + lr * 2]);
                af[mt][2] = *reinterpret_cast<const uint32_t*>(&sA[(r    ) * RSTR + kk + 8 + lr * 2]);
                af[mt][3] = *reinterpret_cast<const uint32_t*>(&sA[(r + 8) * RSTR + kk + 8 + lr * 2]);
            }
            #pragma unroll
            for (int nt = 0; nt < 8; nt++) {
                int rn = wn * 64 + nt * 8 + lq;
                bf[nt][0] = *reinterpret_cast<const uint32_t*>(&sB[rn * RSTR + kk     + lr * 2]);
                bf[nt][1] = *reinterpret_cast<const uint32_t*>(&sB[rn * RSTR + kk + 8 + lr * 2]);
            }
            #pragma unroll
            for (int mt = 0; mt < 4; mt++)
                #pragma unroll
                for (int nt = 0; nt < 8; nt++)
                    MMA_F16(acc[mt][nt], af[mt][0], af[mt][1], af[mt][2], af[mt][3],
                            bf[nt][0], bf[nt][1]);
        }
        if (++s == NSTG) s = 0;
        if (++sl == NSTG) sl = 0;
    }

    #pragma unroll
    for (int mt = 0; mt < 4; mt++)
        #pragma unroll
        for (int nt = 0; nt < 8; nt++) {
            int r0 = m0 + wm * 64 + mt * 16 + lq;
            int cc = n0 + wn * 64 + nt * 8 + lr * 2;
            #pragma unroll
            for (int half_i = 0; half_i < 2; half_i++) {
                int m = r0 + half_i * 8;
                float v0 = acc[mt][nt][half_i * 2 + 0];
                float v1 = acc[mt][nt][half_i * 2 + 1];
                if (EPI == 1) {                 // out_proj: x += acc; also half copy
                    float2 rr = *reinterpret_cast<const float2*>(&residF[(size_t)m * N + cc]);
                    float o0 = v0 + rr.x, o1 = v1 + rr.y;
                    *reinterpret_cast<float2*>(&C[(size_t)m * N + cc]) = make_float2(o0, o1);
                    *reinterpret_cast<__half2*>(&Ch[(size_t)m * N + cc]) = __floats2half2_rn(o0, o1);
                } else if (EPI == 2) {          // MLP1: gelu -> half only
                    *reinterpret_cast<__half2*>(&Ch[(size_t)m * N + cc]) =
                        __floats2half2_rn(geluf(v0 + bias[cc]), geluf(v1 + bias[cc + 1]));
                } else if (EPI == 3) {          // MLP2: + bias + resid -> fp32
                    float2 rr = *reinterpret_cast<const float2*>(&residF[(size_t)m * N + cc]);
                    *reinterpret_cast<float2*>(&C[(size_t)m * N + cc]) =
                        make_float2(v0 + bias[cc] + rr.x, v1 + bias[cc + 1] + rr.y);
                } else {                        // EPI 4: in_proj split (no straddle)
                    if (cc < DI)
                        *reinterpret_cast<float2*>(&C[(size_t)m * DI + cc]) =
                            make_float2(siluf(v0), siluf(v1));
                    else
                        *reinterpret_cast<float2*>(&residF[(size_t)m * DI + cc - DI]) =
                            make_float2(v0, v1);
                }
            }
        }
}

// ---------------- xproj split-K GEMM (tf32, fp32 inputs) ----------------
#define SKEWF 36
__global__ __launch_bounds__(256, 2)
void xproj_splitk(const float* __restrict__ A, const float* __restrict__ Bw,
                  float* __restrict__ Cp, int K)
{
    constexpr int TBN  = 64;
    constexpr int NSTG = 4;
    constexpr int NT   = TBN / 32;
    constexpr int WNC  = TBN / 4;
    constexpr int ASTG = 128 * SKEWF;
    constexpr int BSTG = TBN * SKEWF;
    constexpr int STG  = ASTG + BSTG;
    extern __shared__ float sm[];

    const int tid  = threadIdx.x;
    const int lane = tid & 31;
    const int w    = tid >> 5;
    const int wm   = w & 1;
    const int wn   = w >> 1;
    const int m0 = blockIdx.y * 128;
    const int kz = blockIdx.x;
    const int kbase = kz * (K / KSPL);
    const int lq = lane >> 2;
    const int lr = lane & 3;
    float* C = Cp + (size_t)kz * ROWS * 64;

    float acc[4][NT][4];
    #pragma unroll
    for (int i = 0; i < 4; i++)
        #pragma unroll
        for (int j = 0; j < NT; j++)
            #pragma unroll
            for (int r = 0; r < 4; r++) acc[i][j][r] = 0.f;

    const int NC = (K / KSPL) >> 5;

    auto load_stage = [&](int s, int k0) {
        float* dA = sm + s * STG;
        float* dB = dA + ASTG;
        #pragma unroll
        for (int i = 0; i < 4; i++) {
            int slot = tid + i * 256;
            int row = slot >> 3, c4 = (slot & 7) * 4;
            cp16(smem_u32(dA + row * SKEWF + c4), A + (size_t)(m0 + row) * K + kbase + k0 + c4);
        }
        #pragma unroll
        for (int i = 0; i < 2; i++) {
            int slot = tid + i * 256;
            int row = slot >> 3, c4 = (slot & 7) * 4;
            cp16(smem_u32(dB + row * SKEWF + c4), Bw + (size_t)row * K + kbase + k0 + c4);
        }
        asm volatile("cp.async.commit_group;" ::: "memory");
    };

    #pragma unroll
    for (int c = 0; c < NSTG - 1; c++) load_stage(c, c * 32);

    int s = 0, sl = NSTG - 1;
    for (int c = 0; c < NC; c++) {
        if (c <= NC - NSTG + 1) {
            asm volatile("cp.async.wait_group %0;" :: "n"(NSTG - 2) : "memory");
        } else {
            asm volatile("cp.async.wait_group 0;" ::: "memory");
        }
        __syncthreads();
        if (c + NSTG - 1 < NC) load_stage(sl, (c + NSTG - 1) * 32);

        const float* sA = sm + s * STG;
        const float* sB = sA + ASTG;
        #pragma unroll
        for (int kk = 0; kk < 32; kk += 8) {
            uint32_t afr[4][4], bfr[NT][2];
            #pragma unroll
            for (int mt = 0; mt < 4; mt++) {
                int r = wm * 64 + mt * 16 + lq;
                afr[mt][0] = to_tf32u(sA[(r    ) * SKEWF + kk     + lr]);
                afr[mt][1] = to_tf32u(sA[(r + 8) * SKEWF + kk     + lr]);
                afr[mt][2] = to_tf32u(sA[(r    ) * SKEWF + kk + 4 + lr]);
                afr[mt][3] = to_tf32u(sA[(r + 8) * SKEWF + kk + 4 + lr]);
            }
            #pragma unroll
            for (int nt = 0; nt < NT; nt++) {
                int rn = wn * WNC + nt * 8 + lq;
                bfr[nt][0] = to_tf32u(sB[rn * SKEWF + kk     + lr]);
                bfr[nt][1] = to_tf32u(sB[rn * SKEWF + kk + 4 + lr]);
            }
            #pragma unroll
            for (int mt = 0; mt < 4; mt++)
                #pragma unroll
                for (int nt = 0; nt < NT; nt++)
                    MMA_TF32(acc[mt][nt], afr[mt][0], afr[mt][1], afr[mt][2], afr[mt][3],
                             bfr[nt][0], bfr[nt][1]);
        }
        if (++s == NSTG) s = 0;
        if (++sl == NSTG) sl = 0;
    }

    #pragma unroll
    for (int mt = 0; mt < 4; mt++)
        #pragma unroll
        for (int nt = 0; nt < NT; nt++) {
            int r0 = m0 + wm * 64 + mt * 16 + lq;
            int cc = wn * WNC + nt * 8 + lr * 2;
            #pragma unroll
            for (int half_i = 0; half_i < 2; half_i++) {
                int m = r0 + half_i * 8;
                *reinterpret_cast<float2*>(&C[(size_t)m * 64 + cc]) =
                    make_float2(acc[mt][nt][half_i * 2 + 0], acc[mt][nt][half_i * 2 + 1]);
            }
        }
}

// ---------------- split-K reduce ----------------
__global__ void prred_kernel(const float* __restrict__ prp, float* __restrict__ pr)
{
    int i = blockIdx.x * blockDim.x + threadIdx.x;
    if (i >= ROWS * 64) return;
    float s = 0.f;
    #pragma unroll
    for (int z = 0; z < KSPL; z++) s += prp[(size_t)z * ROWS * 64 + i];
    pr[i] = s;
}

// ---------------- fused double causal dwconv (K=4) + silu ----------------
#define CCHUNK 16
__global__ void conv2_kernel(const float* __restrict__ in,
                             const float* __restrict__ w1, const float* __restrict__ b1,
                             const float* __restrict__ w2, const float* __restrict__ b2,
                             float* __restrict__ out)
{
    int idx = blockIdx.x * blockDim.x + threadIdx.x;
    if (idx >= BATCH * DI * (SEQ / CCHUNK)) return;
    int d  = idx % DI;
    int r  = idx / DI;
    int c0 = r % (SEQ / CCHUNK);
    int b  = r / (SEQ / CCHUNK);
    int t0 = c0 * CCHUNK;

    const float wa0 = w1[d*4+0], wa1 = w1[d*4+1], wa2 = w1[d*4+2], wa3 = w1[d*4+3];
    const float wb0 = w2[d*4+0], wb1 = w2[d*4+1], wb2 = w2[d*4+2], wb3 = w2[d*4+3];
    const float bb1 = b1[d], bb2 = b2[d];
    const float* pin  = in  + (size_t)b * SEQ * DI + d;
    float*       pout = out + (size_t)b * SEQ * DI + d;

    float h[3];
    #pragma unroll
    for (int j = 0; j < 3; j++) {
        int t = t0 - 3 + j;
        if (t >= 0) {
            float a = bb1;
            float wv[4] = {wa0, wa1, wa2, wa3};
            #pragma unroll
            for (int k = 0; k < 4; k++) {
                int tt = t - 3 + k;
                if (tt >= 0) a = fmaf(pin[(size_t)tt * DI], wv[k], a);
            }
            h[j] = siluf(a);
        } else h[j] = 0.f;
    }
    float xm3 = (t0 - 3 >= 0) ? pin[(size_t)(t0 - 3) * DI] : 0.f;
    float xm2 = (t0 - 2 >= 0) ? pin[(size_t)(t0 - 2) * DI] : 0.f;
    float xm1 = (t0 - 1 >= 0) ? pin[(size_t)(t0 - 1) * DI] : 0.f;

    #pragma unroll
    for (int t = t0; t < t0 + CCHUNK; t++) {
        float xt = pin[(size_t)t * DI];
        float v1 = fmaf(wa0, xm3, bb1);
        v1 = fmaf(wa1, xm2, v1);
        v1 = fmaf(wa2, xm1, v1); v1 = fmaf(wa3, xt,  v1);
        float s = siluf(v1);
        float v2 = fmaf(wb0, h[0], bb2);
        v2 = fmaf(wb1, h[1], v2);
        v2 = fmaf(wb2, h[2], v2); v2 = fmaf(wb3, s,    v2);
        pout[(size_t)t * DI] = siluf(v2);
        xm3 = xm2; xm2 = xm1; xm1 = xt;
        h[0] = h[1]; h[1] = h[2]; h[2] = s;
    }
}

// ---------------- x_proj weight zero-pad ----------------
__global__ void wpad_kernel(const float* __restrict__ W, float* __restrict__ Wp)
{
    int idx = blockIdx.x * blockDim.x + threadIdx.x;
    if (idx >= NLAYER * 64 * DI) return;
    int k = idx % DI;
    int p = (idx / DI) % 64;
    int l = idx / (DI * 64);
    Wp[idx] = (p < 33) ? W[((size_t)l * 33 + p) * DI + k] : 0.f;
}

// ---------------- selective scan: smem-staged, double-buffered chunks ----------------
#define SCH 64
#define NCHK (SEQ / SCH)
#define SCAN_SMEM ((2*SCH*32 + 2*SCH*64 + SCH*32) * 4)

__global__ __launch_bounds__(256)
void scan_kernel(const float* __restrict__ x, const float* __restrict__ pr,
                 const float* __restrict__ dtw, const float* __restrict__ dtb,
                 const float* __restrict__ Dv, float* __restrict__ y)
{
    extern __shared__ float sm[];
    float* SX = sm;
    float* SP = sm + 2 * SCH * 32;
    float* SY = SP + 2 * SCH * 64;

    const int tid = threadIdx.x;
    const int dd  = tid >> 3;
    const int sub = tid & 7;
    const int nblk = DI / 32;
    const int b  = blockIdx.x / nblk;
    const int d0 = (blockIdx.x % nblk) * 32;
    const int d  = d0 + dd;

    const float wdt = dtw[d], bdt = dtb[d], Dd = Dv[d];
    const float A0 = -(float)(sub * 2 + 1);
    const float A1 = -(float)(sub * 2 + 2);
    float h0 = 0.f, h1 = 0.f;

    const float* xg = x + (size_t)b * SEQ * DI + d0;
    const float* pg = pr + (size_t)b * SEQ * 64;
    float*       yg = y + (size_t)b * SEQ * DI + d0;

    auto load_chunk = [&](int buf, int c) {
        int t0 = c * SCH;
        float* dx = SX + buf * SCH * 32;
        float* dp = SP + buf * SCH * 64;
        #pragma unroll
        for (int i = 0; i < 2; i++) {
            int sl = tid + i * 256;
            int t = sl >> 3, ch = sl & 7;
            cp16(smem_u32(dx + t * 32 + ch * 4), xg + (size_t)(t0 + t) * DI + ch * 4);
        }
        #pragma unroll
        for (int i = 0; i < 4; i++) {
            int sl = tid + i * 256;
            int t = sl >> 4, ch = sl & 15;
            cp16(smem_u32(dp + t * 64 + ch * 4), pg + (size_t)(t0 + t) * 64 + ch * 4);
        }
        asm volatile("cp.async.commit_group;" ::: "memory");
    };

    load_chunk(0, 0);
    load_chunk(1, 1);

    for (int c = 0; c < NCHK; c++) {
        const int buf = c & 1;
        if (c + 1 < NCHK) asm volatile("cp.async.wait_group 1;" ::: "memory");
        else              asm volatile("cp.async.wait_group 0;" ::: "memory");
        __syncthreads();

        const float* cx = SX + buf * SCH * 32;
        const float* cp = SP + buf * SCH * 64;
        #pragma unroll 4
        for (int s = 0; s < SCH; s++) {
            float dtraw = cp[s * 64];
            float xv    = cx[s * 32 + dd];
            float B0 = cp[s * 64 + 1 + 2 * sub], B1 = cp[s * 64 + 2 + 2 * sub];
            float C0 = cp[s * 64 + 17 + 2 * sub], C1 = cp[s * 64 + 18 + 2 * sub];
            float z  = fmaf(dtraw, wdt, bdt);
            float dt = (z > 20.f) ? z : log1pf(expf(z));
            float dtx = dt * xv;
            float t0v = fmaf(h0, A0, dtx * B0); h0 = fmaf(dt, t0v, h0);
            float t1v = fmaf(h1, A1, dtx * B1); h1 = fmaf(dt, t1v, h1);
            float yp = fmaf(h1, C1, h0 * C0);
            yp += __shfl_xor_sync(0xffffffffu, yp, 1);
            yp += __shfl_xor_sync(0xffffffffu, yp, 2);
            yp += __shfl_xor_sync(0xffffffffu, yp, 4);
            if (sub == 0) SY[s * 32 + dd] = fmaf(xv, Dd, yp);
        }
        __syncthreads();

        const int t0 = c * SCH;
        #pragma unroll
        for (int i = 0; i < 8; i++) {
            int sl = tid + i * 256;
            int s = sl >> 5, dd2 = sl & 31;
            yg[(size_t)(t0 + s) * DI + dd2] = SY[s * 32 + dd2];
        }
        if (c + 2 < NCHK) load_chunk(buf, c + 2);
    }
}

// ---------------- host orchestration ----------------
#define SMEM_H(NSTG)      ((NSTG) * 2 * 128 * RSTR * 2)
#define SMEM_X            (4 * (128 + 64) * SKEWF * 4)

extern "C" void kernel_launch(void* const* d_in, const int* in_sizes, int n_in,
                              void* d_out, int out_size)
{
    const float* hidden      = (const float*)d_in[0];
    const float* in_norm_g   = (const float*)d_in[1];
    const float* in_norm_b   = (const float*)d_in[2];
    const float* ln_g        = (const float*)d_in[3];
    const float* ln_b        = (const float*)d_in[4];
    const float* in_proj_w   = (const float*)d_in[5];
    const float* conv_w      = (const float*)d_in[6];
    const float* conv_b      = (const float*)d_in[7];
    const float* x_proj_w    = (const float*)d_in[8];
    const float* dt_proj_w   = (const float*)d_in[9];
    const float* dt_proj_b   = (const float*)d_in[10];
    const float* Dv          = (const float*)d_in[11];
    const float* mamba_ln_g  = (const float*)d_in[12];
    const float* mamba_ln_b  = (const float*)d_in[13];
    const float* out_proj_w  = (const float*)d_in[14];
    const float* op1_w       = (const float*)d_in[15];
    const float* op1_b       = (const float*)d_in[16];
    const float* op2_w       = (const float*)d_in[17];
    const float* op2_b       = (const float*)d_in[18];

    float *x, *res, *xi, *xi2, *pr, *prp, *y, *wp;
    __half *xnh, *yh, *xh, *t1h, *wih, *woh, *op1h, *op2h;
    cudaGetSymbolAddress((void**)&x,    g_x);
    cudaGetSymbolAddress((void**)&res,  g_res);
    cudaGetSymbolAddress((void**)&xi,   g_xi);
    cudaGetSymbolAddress((void**)&xi2,  g_xi2);
    cudaGetSymbolAddress((void**)&pr,   g_pr);
    cudaGetSymbolAddress((void**)&prp,  g_prp);
    cudaGetSymbolAddress((void**)&y,    g_y);
    cudaGetSymbolAddress((void**)&wp,   g_wp);
    cudaGetSymbolAddress((void**)&xnh,  g_xnh);
    cudaGetSymbolAddress((void**)&yh,   g_yh);
    cudaGetSymbolAddress((void**)&xh,   g_xh);
    cudaGetSymbolAddress((void**)&t1h,  g_t1h);
    cudaGetSymbolAddress((void**)&wih,  g_wih);
    cudaGetSymbolAddress((void**)&woh,  g_woh);
    cudaGetSymbolAddress((void**)&op1h, g_op1h);
    cudaGetSymbolAddress((void**)&op2h, g_op2h);

    cudaFuncSetAttribute(gemm_h<1,4>, cudaFuncAttributeMaxDynamicSharedMemorySize, SMEM_H(4));
    cudaFuncSetAttribute(gemm_h<2,4>, cudaFuncAttributeMaxDynamicSharedMemorySize, SMEM_H(4));
    cudaFuncSetAttribute(gemm_h<3,4>, cudaFuncAttributeMaxDynamicSharedMemorySize, SMEM_H(4));
    cudaFuncSetAttribute(gemm_h<4,4>, cudaFuncAttributeMaxDynamicSharedMemorySize, SMEM_H(4));
    cudaFuncSetAttribute(xproj_splitk, cudaFuncAttributeMaxDynamicSharedMemorySize, SMEM_X);
    cudaFuncSetAttribute(scan_kernel, cudaFuncAttributeMaxDynamicSharedMemorySize, SCAN_SMEM);

    // weight conversions (per launch; ~25us total)
    f2h_kernel<<<(NLAYER*2*DI*HID + 255)/256, 256>>>(in_proj_w,  wih,  NLAYER*2*DI*HID);
    f2h_kernel<<<(NLAYER*HID*DI  + 255)/256, 256>>>(out_proj_w, woh,  NLAYER*HID*DI);
    f2h_kernel<<<(HID*HID        + 255)/256, 256>>>(op1_w,      op1h, HID*HID);
    f2h_kernel<<<(HID*HID        + 255)/256, 256>>>(op2_w,      op2h, HID*HID);
    wpad_kernel<<<(NLAYER * 64 * DI + 255) / 256, 256>>>(x_proj_w, wp);

    // x = LN(hidden)  (fp32 residual)
    ln_kernel<false,false><<<ROWS, 256>>>(hidden, in_norm_g, in_norm_b, nullptr, x, HID);

    for (int l = 0; l < NLAYER; l++) {
        // xnh = half(LN(x))
        ln_kernel<false,true><<<ROWS, 256>>>(x, ln_g + (size_t)l * HID, ln_b + (size_t)l * HID,
                                             nullptr, xnh, HID);
        // in_proj: xi = silu(first half), res = second half  (2048x4096x1024 fp16)
        gemm_h<4,4><<<dim3(2 * DI / 128, ROWS / 128), 128, SMEM_H(4)>>>(
            xnh, wih + (size_t)l * 2 * DI * HID, nullptr, res, xi, nullptr, ROWS, 2 * DI, HID);
        // fused conv1+silu+conv2+silu : xi -> xi2
        conv2_kernel<<<(BATCH * DI * (SEQ / CCHUNK)) / 256, 256>>>(
            xi,
            conv_w + (size_t)(l * 2 + 0) * DI * KCONV, conv_b + (size_t)(l * 2 + 0) * DI,
            conv_w + (size_t)(l * 2 + 1) * DI * KCONV, conv_b + (size_t)(l * 2 + 1) * DI,
            xi2);
        // proj partials (split-K), then reduce
        xproj_splitk<<<dim3(KSPL, ROWS / 128), 256, SMEM_X>>>(
            xi2, wp + (size_t)l * 64 * DI, prp, DI);
        prred_kernel<<<(ROWS * 64 + 255) / 256, 256>>>(prp, pr);
        // selective scan -> y
        scan_kernel<<<BATCH * (DI / 32), 256, SCAN_SMEM>>>(
            xi2, pr, dt_proj_w + (size_t)l * DI, dt_proj_b + (size_t)l * DI,
            Dv + (size_t)l * DI, y);
        // yh = half(LN(y) * sigmoid(res))
        ln_kernel<true,true><<<ROWS, 256>>>(y, mamba_ln_g + (size_t)l * DI,
                                            mamba_ln_b + (size_t)l * DI, res, yh, DI);
        // x = x + yh @ woh^T  (fp32 out + half copy xh)
        gemm_h<1,4><<<dim3(HID / 128, ROWS / 128), 128, SMEM_H(4)>>>(
            yh, woh + (size_t)l * HID * DI, nullptr, x, x, xh, ROWS, HID, DI);
    }

    // t1h = half(gelu(xh @ op1h^T + op1_b))
    gemm_h<2,4><<<dim3(HID / 128, ROWS / 128), 128, SMEM_H(4)>>>(
        xh, op1h, op1_b, nullptr, nullptr, t1h, ROWS, HID, HID);
    // out = t1h @ op2h^T + op2_b + hidden  (fp32)
    gemm_h<3,4><<<dim3(HID / 128, ROWS / 128), 128, SMEM_H(4)>>>(
        t1h, op2h, op2_b, (float*)hidden, (float*)d_out, nullptr, ROWS, HID, HID);
}

// round 12
// speedup vs baseline: 1.4283x; 1.0149x over previous
#include <cuda_runtime.h>
#include <cuda_fp16.h>
#include <math.h>
#include <stdint.h>

#define BATCH 2
#define SEQ   1024
#define HID   1024
#define DI    2048
#define NST   16
#define KCONV 4
#define NLAYER 4
#define ROWS  (BATCH*SEQ)      // 2048
#define LN_EPS 1e-5f
#define KSPL  8                // xproj split-K factor

// ---------------- scratch (device globals; no allocation) ----------------
__device__ float g_x  [ROWS*HID];
__device__ float g_res[ROWS*DI];
__device__ float g_xi [ROWS*DI];
__device__ float g_xi2[ROWS*DI];
__device__ float g_pr [ROWS*64];          // padded proj (stride 64)
__device__ float g_prp[KSPL*ROWS*64];     // split-K partials
__device__ float g_y  [ROWS*DI];
__device__ float g_wp [NLAYER*64*DI];     // zero-padded x_proj weights (fp32, tf32 path)
// half operands
__device__ __half g_xnh [ROWS*HID];
__device__ __half g_yh  [ROWS*DI];
__device__ __half g_xh  [ROWS*HID];
__device__ __half g_t1h [ROWS*HID];
__device__ __half g_wih [NLAYER*2*DI*HID];
__device__ __half g_woh [NLAYER*HID*DI];
__device__ __half g_op1h[HID*HID];
__device__ __half g_op2h[HID*HID];

// ---------------- helpers ----------------
__device__ __forceinline__ float siluf(float v) { return v / (1.f + expf(-v)); }
__device__ __forceinline__ float sigmoidf_(float v) { return 1.f / (1.f + expf(-v)); }
__device__ __forceinline__ float geluf(float v) { return 0.5f * v * (1.f + erff(v * 0.70710678118654752f)); }
__device__ __forceinline__ uint32_t to_tf32u(float x) {
    uint32_t u;
    asm("cvt.rna.tf32.f32 %0, %1;" : "=r"(u) : "f"(x));
    return u;
}
__device__ __forceinline__ uint32_t smem_u32(const void* p) {
    uint32_t a;
    asm("{ .reg .u64 t; cvta.to.shared.u64 t, %1; cvt.u32.u64 %0, t; }" : "=r"(a) : "l"(p));
    return a;
}
__device__ __forceinline__ void cp16(uint32_t d, const void* g) {
    asm volatile("cp.async.cg.shared.global [%0], [%1], 16;" :: "r"(d), "l"(g));
}
__device__ __forceinline__ void ldsm4(uint32_t& r0, uint32_t& r1, uint32_t& r2, uint32_t& r3,
                                      uint32_t a) {
    asm volatile("ldmatrix.sync.aligned.m8n8.x4.shared.b16 {%0,%1,%2,%3}, [%4];"
                 : "=r"(r0), "=r"(r1), "=r"(r2), "=r"(r3) : "r"(a));
}
#define MMA_TF32(acc, a0,a1,a2,a3, b0,b1)                                     \
    asm volatile(                                                             \
        "mma.sync.aligned.m16n8k8.row.col.f32.tf32.tf32.f32 "                 \
        "{%0,%1,%2,%3}, {%4,%5,%6,%7}, {%8,%9}, {%0,%1,%2,%3};"               \
        : "+f"((acc)[0]), "+f"((acc)[1]), "+f"((acc)[2]), "+f"((acc)[3])      \
        : "r"(a0), "r"(a1), "r"(a2), "r"(a3), "r"(b0), "r"(b1))
#define MMA_F16(acc, a0,a1,a2,a3, b0,b1)                                      \
    asm volatile(                                                             \
        "mma.sync.aligned.m16n8k16.row.col.f32.f16.f16.f32 "                  \
        "{%0,%1,%2,%3}, {%4,%5,%6,%7}, {%8,%9}, {%0,%1,%2,%3};"               \
        : "+f"((acc)[0]), "+f"((acc)[1]), "+f"((acc)[2]), "+f"((acc)[3])      \
        : "r"(a0), "r"(a1), "r"(a2), "r"(a3), "r"(b0), "r"(b1))

// ---------------- fused fp32 -> fp16 weight convert (all 4 weight sets) ----------
__global__ void f2h_all(const float* __restrict__ w0, __half* __restrict__ o0, int n0,
                        const float* __restrict__ w1, __half* __restrict__ o1, int n1,
                        const float* __restrict__ w2, __half* __restrict__ o2, int n2,
                        const float* __restrict__ w3, __half* __restrict__ o3, int n3)
{
    int i = blockIdx.x * blockDim.x + threadIdx.x;
    if (i < n0) o0[i] = __float2half_rn(w0[i]);
    i -= n0;
    if (i >= 0 && i < n1) o1[i] = __float2half_rn(w1[i]);
    i -= n1;
    if (i >= 0 && i < n2) o2[i] = __float2half_rn(w2[i]);
    i -= n2;
    if (i >= 0 && i < n3) o3[i] = __float2half_rn(w3[i]);
}

// ---------------- LayerNorm (gate epilogue optional; fp32 or fp16 output) ----------
template<bool GATE, bool OUTH>
__global__ void ln_kernel(const float* __restrict__ in,
                          const float* __restrict__ g,
                          const float* __restrict__ b,
                          const float* __restrict__ gate,
                          void* __restrict__ outv, int cols)
{
    __shared__ float buf[2048];
    __shared__ float red[8];
    __shared__ float s_mu, s_rstd;
    const int row = blockIdx.x;
    const int tid = threadIdx.x;
    const float* pin = in + (size_t)row * cols;

    float s = 0.f;
    for (int c = tid; c < cols; c += 256) { float v = pin[c]; buf[c] = v; s += v; }
    #pragma unroll
    for (int o = 16; o; o >>= 1) s += __shfl_xor_sync(0xffffffffu, s, o);
    if ((tid & 31) == 0) red[tid >> 5] = s;
    __syncthreads();
    if (tid == 0) {
        float t = 0.f;
        #pragma unroll
        for (int i = 0; i < 8; i++) t += red[i];
        s_mu = t / (float)cols;
    }
    __syncthreads();
    const float mu = s_mu;
    float v2 = 0.f;
    for (int c = tid; c < cols; c += 256) { float xc = buf[c] - mu; v2 += xc * xc; }
    #pragma unroll
    for (int o = 16; o; o >>= 1) v2 += __shfl_xor_sync(0xffffffffu, v2, o);
    __syncthreads();
    if ((tid & 31) == 0) red[tid >> 5] = v2;
    __syncthreads();
    if (tid == 0) {
        float t = 0.f;
        #pragma unroll
        for (int i = 0; i < 8; i++) t += red[i];
        s_rstd = 1.f / sqrtf(t / (float)cols + LN_EPS);
    }
    __syncthreads();
    const float rstd = s_rstd;
    for (int c = tid; c < cols; c += 256) {
        float val = (buf[c] - mu) * rstd * g[c] + b[c];
        if (GATE) val *= sigmoidf_(gate[(size_t)row * cols + c]);
        if (OUTH) ((__half*)outv)[(size_t)row * cols + c] = __float2half_rn(val);
        else      ((float*)outv)[(size_t)row * cols + c] = val;
    }
}

// ---------------- fp16 tensor-core GEMM with ldmatrix fragments -------------------
// C = A(MxK) * B(NxK)^T.  128x128 tile, 4 warps (64x64 each), NSTG-stage cp.async.
// EPI: 1 out_proj (C=resid+acc fp32, Ch=half copy) ; 2 gelu(acc+bias) -> Ch half ;
//      3 acc+bias+resid -> C fp32 ; 4 in_proj split (silu->C fp32 | raw->residF)
#define RSTR 40                             // halves per smem row (32 + 8 skew)

template<int EPI, int NSTG>
__global__ __launch_bounds__(128, 2)
void gemm_h(const __half* __restrict__ A, const __half* __restrict__ Bw,
            const float* __restrict__ bias, float* __restrict__ residF,
            float* __restrict__ C, __half* __restrict__ Ch,
            int M, int N, int K)
{
    constexpr int ASTG = 128 * RSTR;        // halves per stage per matrix
    constexpr int STG  = 2 * ASTG;
    extern __shared__ __half smh[];

    const int tid  = threadIdx.x;           // 128
    const int lane = tid & 31;
    const int w    = tid >> 5;
    const int wm   = w & 1;
    const int wn   = w >> 1;
    const int m0 = blockIdx.y * 128;
    const int n0 = blockIdx.x * 128;
    const int lq = lane >> 2;
    const int lr = lane & 3;
    // ldmatrix lane decomposition
    const int l7  = lane & 7;
    const int l8  = (lane >> 3) & 1;
    const int l16 = lane >> 4;

    float acc[4][8][4];
    #pragma unroll
    for (int i = 0; i < 4; i++)
        #pragma unroll
        for (int j = 0; j < 8; j++)
            #pragma unroll
            for (int r = 0; r < 4; r++) acc[i][j][r] = 0.f;

    const int NC = K >> 5;                  // 32 k-halves per chunk

    auto load_stage = [&](int s, int k0) {
        __half* dA = smh + s * STG;
        __half* dB = dA + ASTG;
        #pragma unroll
        for (int i = 0; i < 4; i++) {
            int slot = tid + i * 128;       // 0..511
            int row = slot >> 2, c = slot & 3;
            cp16(smem_u32(dA + row * RSTR + c * 8), A  + (size_t)(m0 + row) * K + k0 + c * 8);
            cp16(smem_u32(dB + row * RSTR + c * 8), Bw + (size_t)(n0 + row) * K + k0 + c * 8);
        }
        asm volatile("cp.async.commit_group;" ::: "memory");
    };

    #pragma unroll
    for (int c = 0; c < NSTG - 1; c++) load_stage(c, c * 32);

    int s = 0, sl = NSTG - 1;
    for (int c = 0; c < NC; c++) {
        if (c <= NC - NSTG + 1) {
            asm volatile("cp.async.wait_group %0;" :: "n"(NSTG - 2) : "memory");
        } else {
            asm volatile("cp.async.wait_group 0;" ::: "memory");
        }
        __syncthreads();
        if (c + NSTG - 1 < NC) load_stage(sl, (c + NSTG - 1) * 32);

        const __half* sA = smh + s * STG;
        const __half* sB = sA + ASTG;
        #pragma unroll
        for (int kk = 0; kk < 32; kk += 16) {
            uint32_t af[4][4], bf[8][2];
            // A fragments: one x4 ldmatrix per 16-row m-tile
            // lanes 0-7: rows+0 k+0 (a0) | 8-15: rows+8 k+0 (a1) |
            // 16-23: rows+0 k+8 (a2)     | 24-31: rows+8 k+8 (a3)
            #pragma unroll
            for (int mt = 0; mt < 4; mt++) {
                int r = wm * 64 + mt * 16 + l7 + l8 * 8;
                uint32_t addr = smem_u32(&sA[r * RSTR + kk + l16 * 8]);
                ldsm4(af[mt][0], af[mt][1], af[mt][2], af[mt][3], addr);
            }
            // B fragments: one x4 ldmatrix per PAIR of 8-row n-tiles
            // lanes 0-7: n+0 k+0 (b[2p][0]) | 8-15: n+0 k+8 (b[2p][1]) |
            // 16-23: n+8 k+0 (b[2p+1][0])   | 24-31: n+8 k+8 (b[2p+1][1])
            #pragma unroll
            for (int p = 0; p < 4; p++) {
                int rn = wn * 64 + p * 16 + l7 + l16 * 8;
                uint32_t addr = smem_u32(&sB[rn * RSTR + kk + l8 * 8]);
                ldsm4(bf[2 * p][0], bf[2 * p][1], bf[2 * p + 1][0], bf[2 * p + 1][1], addr);
            }
            #pragma unroll
            for (int mt = 0; mt < 4; mt++)
                #pragma unroll
                for (int nt = 0; nt < 8; nt++)
                    MMA_F16(acc[mt][nt], af[mt][0], af[mt][1], af[mt][2], af[mt][3],
                            bf[nt][0], bf[nt][1]);
        }
        if (++s == NSTG) s = 0;
        if (++sl == NSTG) sl = 0;
    }

    #pragma unroll
    for (int mt = 0; mt < 4; mt++)
        #pragma unroll
        for (int nt = 0; nt < 8; nt++) {
            int r0 = m0 + wm * 64 + mt * 16 + lq;
            int cc = n0 + wn * 64 + nt * 8 + lr * 2;
            #pragma unroll
            for (int half_i = 0; half_i < 2; half_i++) {
                int m = r0 + half_i * 8;
                float v0 = acc[mt][nt][half_i * 2 + 0];
                float v1 = acc[mt][nt][half_i * 2 + 1];
                if (EPI == 1) {                 // out_proj: x += acc; also half copy
                    float2 rr = *reinterpret_cast<const float2*>(&residF[(size_t)m * N + cc]);
                    float o0 = v0 + rr.x, o1 = v1 + rr.y;
                    *reinterpret_cast<float2*>(&C[(size_t)m * N + cc]) = make_float2(o0, o1);
                    *reinterpret_cast<__half2*>(&Ch[(size_t)m * N + cc]) = __floats2half2_rn(o0, o1);
                } else if (EPI == 2) {          // MLP1: gelu -> half only
                    *reinterpret_cast<__half2*>(&Ch[(size_t)m * N + cc]) =
                        __floats2half2_rn(geluf(v0 + bias[cc]), geluf(v1 + bias[cc + 1]));
                } else if (EPI == 3) {          // MLP2: + bias + resid -> fp32
                    float2 rr = *reinterpret_cast<const float2*>(&residF[(size_t)m * N + cc]);
                    *reinterpret_cast<float2*>(&C[(size_t)m * N + cc]) =
                        make_float2(v0 + bias[cc] + rr.x, v1 + bias[cc + 1] + rr.y);
                } else {                        // EPI 4: in_proj split (no straddle)
                    if (cc < DI)
                        *reinterpret_cast<float2*>(&C[(size_t)m * DI + cc]) =
                            make_float2(siluf(v0), siluf(v1));
                    else
                        *reinterpret_cast<float2*>(&residF[(size_t)m * DI + cc - DI]) =
                            make_float2(v0, v1);
                }
            }
        }
}

// ---------------- xproj split-K GEMM (tf32, fp32 inputs) ----------------
#define SKEWF 36
__global__ __launch_bounds__(256, 2)
void xproj_splitk(const float* __restrict__ A, const float* __restrict__ Bw,
                  float* __restrict__ Cp, int K)
{
    constexpr int TBN  = 64;
    constexpr int NSTG = 4;
    constexpr int NT   = TBN / 32;
    constexpr int WNC  = TBN / 4;
    constexpr int ASTG = 128 * SKEWF;
    constexpr int BSTG = TBN * SKEWF;
    constexpr int STG  = ASTG + BSTG;
    extern __shared__ float sm[];

    const int tid  = threadIdx.x;
    const int lane = tid & 31;
    const int w    = tid >> 5;
    const int wm   = w & 1;
    const int wn   = w >> 1;
    const int m0 = blockIdx.y * 128;
    const int kz = blockIdx.x;
    const int kbase = kz * (K / KSPL);
    const int lq = lane >> 2;
    const int lr = lane & 3;
    float* C = Cp + (size_t)kz * ROWS * 64;

    float acc[4][NT][4];
    #pragma unroll
    for (int i = 0; i < 4; i++)
        #pragma unroll
        for (int j = 0; j < NT; j++)
            #pragma unroll
            for (int r = 0; r < 4; r++) acc[i][j][r] = 0.f;

    const int NC = (K / KSPL) >> 5;

    auto load_stage = [&](int s, int k0) {
        float* dA = sm + s * STG;
        float* dB = dA + ASTG;
        #pragma unroll
        for (int i = 0; i < 4; i++) {
            int slot = tid + i * 256;
            int row = slot >> 3, c4 = (slot & 7) * 4;
            cp16(smem_u32(dA + row * SKEWF + c4), A + (size_t)(m0 + row) * K + kbase + k0 + c4);
        }
        #pragma unroll
        for (int i = 0; i < 2; i++) {
            int slot = tid + i * 256;
            int row = slot >> 3, c4 = (slot & 7) * 4;
            cp16(smem_u32(dB + row * SKEWF + c4), Bw + (size_t)row * K + kbase + k0 + c4);
        }
        asm volatile("cp.async.commit_group;" ::: "memory");
    };

    #pragma unroll
    for (int c = 0; c < NSTG - 1; c++) load_stage(c, c * 32);

    int s = 0, sl = NSTG - 1;
    for (int c = 0; c < NC; c++) {
        if (c <= NC - NSTG + 1) {
            asm volatile("cp.async.wait_group %0;" :: "n"(NSTG - 2) : "memory");
        } else {
            asm volatile("cp.async.wait_group 0;" ::: "memory");
        }
        __syncthreads();
        if (c + NSTG - 1 < NC) load_stage(sl, (c + NSTG - 1) * 32);

        const float* sA = sm + s * STG;
        const float* sB = sA + ASTG;
        #pragma unroll
        for (int kk = 0; kk < 32; kk += 8) {
            uint32_t afr[4][4], bfr[NT][2];
            #pragma unroll
            for (int mt = 0; mt < 4; mt++) {
                int r = wm * 64 + mt * 16 + lq;
                afr[mt][0] = to_tf32u(sA[(r    ) * SKEWF + kk     + lr]);
                afr[mt][1] = to_tf32u(sA[(r + 8) * SKEWF + kk     + lr]);
                afr[mt][2] = to_tf32u(sA[(r    ) * SKEWF + kk + 4 + lr]);
                afr[mt][3] = to_tf32u(sA[(r + 8) * SKEWF + kk + 4 + lr]);
            }
            #pragma unroll
            for (int nt = 0; nt < NT; nt++) {
                int rn = wn * WNC + nt * 8 + lq;
                bfr[nt][0] = to_tf32u(sB[rn * SKEWF + kk     + lr]);
                bfr[nt][1] = to_tf32u(sB[rn * SKEWF + kk + 4 + lr]);
            }
            #pragma unroll
            for (int mt = 0; mt < 4; mt++)
                #pragma unroll
                for (int nt = 0; nt < NT; nt++)
                    MMA_TF32(acc[mt][nt], afr[mt][0], afr[mt][1], afr[mt][2], afr[mt][3],
                             bfr[nt][0], bfr[nt][1]);
        }
        if (++s == NSTG) s = 0;
        if (++sl == NSTG) sl = 0;
    }

    #pragma unroll
    for (int mt = 0; mt < 4; mt++)
        #pragma unroll
        for (int nt = 0; nt < NT; nt++) {
            int r0 = m0 + wm * 64 + mt * 16 + lq;
            int cc = wn * WNC + nt * 8 + lr * 2;
            #pragma unroll
            for (int half_i = 0; half_i < 2; half_i++) {
                int m = r0 + half_i * 8;
                *reinterpret_cast<float2*>(&C[(size_t)m * 64 + cc]) =
                    make_float2(acc[mt][nt][half_i * 2 + 0], acc[mt][nt][half_i * 2 + 1]);
            }
        }
}

// ---------------- split-K reduce ----------------
__global__ void prred_kernel(const float* __restrict__ prp, float* __restrict__ pr)
{
    int i = blockIdx.x * blockDim.x + threadIdx.x;
    if (i >= ROWS * 64) return;
    float s = 0.f;
    #pragma unroll
    for (int z = 0; z < KSPL; z++) s += prp[(size_t)z * ROWS * 64 + i];
    pr[i] = s;
}

// ---------------- fused double causal dwconv (K=4) + silu ----------------
#define CCHUNK 8
__global__ void conv2_kernel(const float* __restrict__ in,
                             const float* __restrict__ w1, const float* __restrict__ b1,
                             const float* __restrict__ w2, const float* __restrict__ b2,
                             float* __restrict__ out)
{
    int idx = blockIdx.x * blockDim.x + threadIdx.x;
    if (idx >= BATCH * DI * (SEQ / CCHUNK)) return;
    int d  = idx % DI;
    int r  = idx / DI;
    int c0 = r % (SEQ / CCHUNK);
    int b  = r / (SEQ / CCHUNK);
    int t0 = c0 * CCHUNK;

    const float wa0 = w1[d*4+0], wa1 = w1[d*4+1], wa2 = w1[d*4+2], wa3 = w1[d*4+3];
    const float wb0 = w2[d*4+0], wb1 = w2[d*4+1], wb2 = w2[d*4+2], wb3 = w2[d*4+3];
    const float bb1 = b1[d], bb2 = b2[d];
    const float* pin  = in  + (size_t)b * SEQ * DI + d;
    float*       pout = out + (size_t)b * SEQ * DI + d;

    float h[3];
    #pragma unroll
    for (int j = 0; j < 3; j++) {
        int t = t0 - 3 + j;
        if (t >= 0) {
            float a = bb1;
            float wv[4] = {wa0, wa1, wa2, wa3};
            #pragma unroll
            for (int k = 0; k < 4; k++) {
                int tt = t - 3 + k;
                if (tt >= 0) a = fmaf(pin[(size_t)tt * DI], wv[k], a);
            }
            h[j] = siluf(a);
        } else h[j] = 0.f;
    }
    float xm3 = (t0 - 3 >= 0) ? pin[(size_t)(t0 - 3) * DI] : 0.f;
    float xm2 = (t0 - 2 >= 0) ? pin[(size_t)(t0 - 2) * DI] : 0.f;
    float xm1 = (t0 - 1 >= 0) ? pin[(size_t)(t0 - 1) * DI] : 0.f;

    #pragma unroll
    for (int t = t0; t < t0 + CCHUNK; t++) {
        float xt = pin[(size_t)t * DI];
        float v1 = fmaf(wa0, xm3, bb1);
        v1 = fmaf(wa1, xm2, v1);
        v1 = fmaf(wa2, xm1, v1); v1 = fmaf(wa3, xt,  v1);
        float s = siluf(v1);
        float v2 = fmaf(wb0, h[0], bb2);
        v2 = fmaf(wb1, h[1], v2);
        v2 = fmaf(wb2, h[2], v2); v2 = fmaf(wb3, s,    v2);
        pout[(size_t)t * DI] = siluf(v2);
        xm3 = xm2; xm2 = xm1; xm1 = xt;
        h[0] = h[1]; h[1] = h[2]; h[2] = s;
    }
}

// ---------------- x_proj weight zero-pad ----------------
__global__ void wpad_kernel(const float* __restrict__ W, float* __restrict__ Wp)
{
    int idx = blockIdx.x * blockDim.x + threadIdx.x;
    if (idx >= NLAYER * 64 * DI) return;
    int k = idx % DI;
    int p = (idx / DI) % 64;
    int l = idx / (DI * 64);
    Wp[idx] = (p < 33) ? W[((size_t)l * 33 + p) * DI + k] : 0.f;
}

// ---------------- selective scan: smem-staged, double-buffered chunks ----------------
#define SCH 64
#define NCHK (SEQ / SCH)
#define SCAN_SMEM ((2*SCH*32 + 2*SCH*64 + SCH*32) * 4)

__global__ __launch_bounds__(256)
void scan_kernel(const float* __restrict__ x, const float* __restrict__ pr,
                 const float* __restrict__ dtw, const float* __restrict__ dtb,
                 const float* __restrict__ Dv, float* __restrict__ y)
{
    extern __shared__ float sm[];
    float* SX = sm;
    float* SP = sm + 2 * SCH * 32;
    float* SY = SP + 2 * SCH * 64;

    const int tid = threadIdx.x;
    const int dd  = tid >> 3;
    const int sub = tid & 7;
    const int nblk = DI / 32;
    const int b  = blockIdx.x / nblk;
    const int d0 = (blockIdx.x % nblk) * 32;
    const int d  = d0 + dd;

    const float wdt = dtw[d], bdt = dtb[d], Dd = Dv[d];
    const float A0 = -(float)(sub * 2 + 1);
    const float A1 = -(float)(sub * 2 + 2);
    float h0 = 0.f, h1 = 0.f;

    const float* xg = x + (size_t)b * SEQ * DI + d0;
    const float* pg = pr + (size_t)b * SEQ * 64;
    float*       yg = y + (size_t)b * SEQ * DI + d0;

    auto load_chunk = [&](int buf, int c) {
        int t0 = c * SCH;
        float* dx = SX + buf * SCH * 32;
        float* dp = SP + buf * SCH * 64;
        #pragma unroll
        for (int i = 0; i < 2; i++) {
            int sl = tid + i * 256;
            int t = sl >> 3, ch = sl & 7;
            cp16(smem_u32(dx + t * 32 + ch * 4), xg + (size_t)(t0 + t) * DI + ch * 4);
        }
        #pragma unroll
        for (int i = 0; i < 4; i++) {
            int sl = tid + i * 256;
            int t = sl >> 4, ch = sl & 15;
            cp16(smem_u32(dp + t * 64 + ch * 4), pg + (size_t)(t0 + t) * 64 + ch * 4);
        }
        asm volatile("cp.async.commit_group;" ::: "memory");
    };

    load_chunk(0, 0);
    load_chunk(1, 1);

    for (int c = 0; c < NCHK; c++) {
        const int buf = c & 1;
        if (c + 1 < NCHK) asm volatile("cp.async.wait_group 1;" ::: "memory");
        else              asm volatile("cp.async.wait_group 0;" ::: "memory");
        __syncthreads();

        const float* cx = SX + buf * SCH * 32;
        const float* cp = SP + buf * SCH * 64;
        #pragma unroll 4
        for (int s = 0; s < SCH; s++) {
            float dtraw = cp[s * 64];
            float xv    = cx[s * 32 + dd];
            float B0 = cp[s * 64 + 1 + 2 * sub], B1 = cp[s * 64 + 2 + 2 * sub];
            float C0 = cp[s * 64 + 17 + 2 * sub], C1 = cp[s * 64 + 18 + 2 * sub];
            float z  = fmaf(dtraw, wdt, bdt);
            float dt = (z > 20.f) ? z : log1pf(expf(z));
            float dtx = dt * xv;
            float t0v = fmaf(h0, A0, dtx * B0); h0 = fmaf(dt, t0v, h0);
            float t1v = fmaf(h1, A1, dtx * B1); h1 = fmaf(dt, t1v, h1);
            float yp = fmaf(h1, C1, h0 * C0);
            yp += __shfl_xor_sync(0xffffffffu, yp, 1);
            yp += __shfl_xor_sync(0xffffffffu, yp, 2);
            yp += __shfl_xor_sync(0xffffffffu, yp, 4);
            if (sub == 0) SY[s * 32 + dd] = fmaf(xv, Dd, yp);
        }
        __syncthreads();

        const int t0 = c * SCH;
        #pragma unroll
        for (int i = 0; i < 8; i++) {
            int sl = tid + i * 256;
            int s = sl >> 5, dd2 = sl & 31;
            yg[(size_t)(t0 + s) * DI + dd2] = SY[s * 32 + dd2];
        }
        if (c + 2 < NCHK) load_chunk(buf, c + 2);
    }
}

// ---------------- host orchestration ----------------
#define SMEM_H(NSTG)      ((NSTG) * 2 * 128 * RSTR * 2)
#define SMEM_X            (4 * (128 + 64) * SKEWF * 4)

extern "C" void kernel_launch(void* const* d_in, const int* in_sizes, int n_in,
                              void* d_out, int out_size)
{
    const float* hidden      = (const float*)d_in[0];
    const float* in_norm_g   = (const float*)d_in[1];
    const float* in_norm_b   = (const float*)d_in[2];
    const float* ln_g        = (const float*)d_in[3];
    const float* ln_b        = (const float*)d_in[4];
    const float* in_proj_w   = (const float*)d_in[5];
    const float* conv_w      = (const float*)d_in[6];
    const float* conv_b      = (const float*)d_in[7];
    const float* x_proj_w    = (const float*)d_in[8];
    const float* dt_proj_w   = (const float*)d_in[9];
    const float* dt_proj_b   = (const float*)d_in[10];
    const float* Dv          = (const float*)d_in[11];
    const float* mamba_ln_g  = (const float*)d_in[12];
    const float* mamba_ln_b  = (const float*)d_in[13];
    const float* out_proj_w  = (const float*)d_in[14];
    const float* op1_w       = (const float*)d_in[15];
    const float* op1_b       = (const float*)d_in[16];
    const float* op2_w       = (const float*)d_in[17];
    const float* op2_b       = (const float*)d_in[18];

    float *x, *res, *xi, *xi2, *pr, *prp, *y, *wp;
    __half *xnh, *yh, *xh, *t1h, *wih, *woh, *op1h, *op2h;
    cudaGetSymbolAddress((void**)&x,    g_x);
    cudaGetSymbolAddress((void**)&res,  g_res);
    cudaGetSymbolAddress((void**)&xi,   g_xi);
    cudaGetSymbolAddress((void**)&xi2,  g_xi2);
    cudaGetSymbolAddress((void**)&pr,   g_pr);
    cudaGetSymbolAddress((void**)&prp,  g_prp);
    cudaGetSymbolAddress((void**)&y,    g_y);
    cudaGetSymbolAddress((void**)&wp,   g_wp);
    cudaGetSymbolAddress((void**)&xnh,  g_xnh);
    cudaGetSymbolAddress((void**)&yh,   g_yh);
    cudaGetSymbolAddress((void**)&xh,   g_xh);
    cudaGetSymbolAddress((void**)&t1h,  g_t1h);
    cudaGetSymbolAddress((void**)&wih,  g_wih);
    cudaGetSymbolAddress((void**)&woh,  g_woh);
    cudaGetSymbolAddress((void**)&op1h, g_op1h);
    cudaGetSymbolAddress((void**)&op2h, g_op2h);

    cudaFuncSetAttribute(gemm_h<1,4>, cudaFuncAttributeMaxDynamicSharedMemorySize, SMEM_H(4));
    cudaFuncSetAttribute(gemm_h<2,4>, cudaFuncAttributeMaxDynamicSharedMemorySize, SMEM_H(4));
    cudaFuncSetAttribute(gemm_h<3,4>, cudaFuncAttributeMaxDynamicSharedMemorySize, SMEM_H(4));
    cudaFuncSetAttribute(gemm_h<4,4>, cudaFuncAttributeMaxDynamicSharedMemorySize, SMEM_H(4));
    cudaFuncSetAttribute(xproj_splitk, cudaFuncAttributeMaxDynamicSharedMemorySize, SMEM_X);
    cudaFuncSetAttribute(scan_kernel, cudaFuncAttributeMaxDynamicSharedMemorySize, SCAN_SMEM);

    // fused weight conversion (one launch)
    {
        int n0 = NLAYER * 2 * DI * HID;
        int n1 = NLAYER * HID * DI;
        int n2 = HID * HID;
        int n3 = HID * HID;
        int tot = n0 + n1 + n2 + n3;
        f2h_all<<<(tot + 255) / 256, 256>>>(in_proj_w, wih, n0, out_proj_w, woh, n1,
                                            op1_w, op1h, n2, op2_w, op2h, n3);
    }
    wpad_kernel<<<(NLAYER * 64 * DI + 255) / 256, 256>>>(x_proj_w, wp);

    // x = LN(hidden)  (fp32 residual)
    ln_kernel<false,false><<<ROWS, 256>>>(hidden, in_norm_g, in_norm_b, nullptr, x, HID);

    for (int l = 0; l < NLAYER; l++) {
        // xnh = half(LN(x))
        ln_kernel<false,true><<<ROWS, 256>>>(x, ln_g + (size_t)l * HID, ln_b + (size_t)l * HID,
                                             nullptr, xnh, HID);
        // in_proj: xi = silu(first half), res = second half  (2048x4096x1024 fp16)
        gemm_h<4,4><<<dim3(2 * DI / 128, ROWS / 128), 128, SMEM_H(4)>>>(
            xnh, wih + (size_t)l * 2 * DI * HID, nullptr, res, xi, nullptr, ROWS, 2 * DI, HID);
        // fused conv1+silu+conv2+silu : xi -> xi2
        conv2_kernel<<<(BATCH * DI * (SEQ / CCHUNK)) / 256, 256>>>(
            xi,
            conv_w + (size_t)(l * 2 + 0) * DI * KCONV, conv_b + (size_t)(l * 2 + 0) * DI,
            conv_w + (size_t)(l * 2 + 1) * DI * KCONV, conv_b + (size_t)(l * 2 + 1) * DI,
            xi2);
        // proj partials (split-K), then reduce
        xproj_splitk<<<dim3(KSPL, ROWS / 128), 256, SMEM_X>>>(
            xi2, wp + (size_t)l * 64 * DI, prp, DI);
        prred_kernel<<<(ROWS * 64 + 255) / 256, 256>>>(prp, pr);
        // selective scan -> y
        scan_kernel<<<BATCH * (DI / 32), 256, SCAN_SMEM>>>(
            xi2, pr, dt_proj_w + (size_t)l * DI, dt_proj_b + (size_t)l * DI,
            Dv + (size_t)l * DI, y);
        // yh = half(LN(y) * sigmoid(res))
        ln_kernel<true,true><<<ROWS, 256>>>(y, mamba_ln_g + (size_t)l * DI,
                                            mamba_ln_b + (size_t)l * DI, res, yh, DI);
        // x = x + yh @ woh^T  (fp32 out + half copy xh)
        gemm_h<1,4><<<dim3(HID / 128, ROWS / 128), 128, SMEM_H(4)>>>(
            yh, woh + (size_t)l * HID * DI, nullptr, x, x, xh, ROWS, HID, DI);
    }

    // t1h = half(gelu(xh @ op1h^T + op1_b))
    gemm_h<2,4><<<dim3(HID / 128, ROWS / 128), 128, SMEM_H(4)>>>(
        xh, op1h, op1_b, nullptr, nullptr, t1h, ROWS, HID, HID);
    // out = t1h @ op2h^T + op2_b + hidden  (fp32)
    gemm_h<3,4><<<dim3(HID / 128, ROWS / 128), 128, SMEM_H(4)>>>(
        t1h, op2h, op2_b, (float*)hidden, (float*)d_out, nullptr, ROWS, HID, HID);
}

// round 13
// speedup vs baseline: 1.4431x; 1.0103x over previous
#include <cuda_runtime.h>
#include <cuda_fp16.h>
#include <math.h>
#include <stdint.h>

#define BATCH 2
#define SEQ   1024
#define HID   1024
#define DI    2048
#define NST   16
#define KCONV 4
#define NLAYER 4
#define ROWS  (BATCH*SEQ)      // 2048
#define LN_EPS 1e-5f
#define KSPL  16               // xproj split-K factor

// ---------------- scratch (device globals; no allocation) ----------------
__device__ float g_x  [ROWS*HID];
__device__ float g_res[ROWS*DI];
__device__ float g_xi [ROWS*DI];
__device__ float g_xi2[ROWS*DI];
__device__ float g_pr [ROWS*64];          // padded proj (stride 64)
__device__ float g_prp[KSPL*ROWS*64];     // split-K partials
__device__ float g_y  [ROWS*DI];
__device__ float g_wp [NLAYER*64*DI];     // zero-padded x_proj weights (fp32, tf32 path)
// half operands
__device__ __half g_xnh [ROWS*HID];
__device__ __half g_yh  [ROWS*DI];
__device__ __half g_xh  [ROWS*HID];
__device__ __half g_t1h [ROWS*HID];
__device__ __half g_wih [NLAYER*2*DI*HID];
__device__ __half g_woh [NLAYER*HID*DI];
__device__ __half g_op1h[HID*HID];
__device__ __half g_op2h[HID*HID];

// ---------------- helpers ----------------
__device__ __forceinline__ float siluf(float v) { return v / (1.f + expf(-v)); }
__device__ __forceinline__ float sigmoidf_(float v) { return 1.f / (1.f + expf(-v)); }
__device__ __forceinline__ float geluf(float v) { return 0.5f * v * (1.f + erff(v * 0.70710678118654752f)); }
__device__ __forceinline__ uint32_t to_tf32u(float x) {
    uint32_t u;
    asm("cvt.rna.tf32.f32 %0, %1;" : "=r"(u) : "f"(x));
    return u;
}
__device__ __forceinline__ uint32_t smem_u32(const void* p) {
    uint32_t a;
    asm("{ .reg .u64 t; cvta.to.shared.u64 t, %1; cvt.u32.u64 %0, t; }" : "=r"(a) : "l"(p));
    return a;
}
__device__ __forceinline__ void cp16(uint32_t d, const void* g) {
    asm volatile("cp.async.cg.shared.global [%0], [%1], 16;" :: "r"(d), "l"(g));
}
__device__ __forceinline__ void ldsm4(uint32_t& r0, uint32_t& r1, uint32_t& r2, uint32_t& r3,
                                      uint32_t a) {
    asm volatile("ldmatrix.sync.aligned.m8n8.x4.shared.b16 {%0,%1,%2,%3}, [%4];"
                 : "=r"(r0), "=r"(r1), "=r"(r2), "=r"(r3) : "r"(a));
}
#define MMA_TF32(acc, a0,a1,a2,a3, b0,b1)                                     \
    asm volatile(                                                             \
        "mma.sync.aligned.m16n8k8.row.col.f32.tf32.tf32.f32 "                 \
        "{%0,%1,%2,%3}, {%4,%5,%6,%7}, {%8,%9}, {%0,%1,%2,%3};"               \
        : "+f"((acc)[0]), "+f"((acc)[1]), "+f"((acc)[2]), "+f"((acc)[3])      \
        : "r"(a0), "r"(a1), "r"(a2), "r"(a3), "r"(b0), "r"(b1))
#define MMA_F16(acc, a0,a1,a2,a3, b0,b1)                                      \
    asm volatile(                                                             \
        "mma.sync.aligned.m16n8k16.row.col.f32.f16.f16.f32 "                  \
        "{%0,%1,%2,%3}, {%4,%5,%6,%7}, {%8,%9}, {%0,%1,%2,%3};"               \
        : "+f"((acc)[0]), "+f"((acc)[1]), "+f"((acc)[2]), "+f"((acc)[3])      \
        : "r"(a0), "r"(a1), "r"(a2), "r"(a3), "r"(b0), "r"(b1))

// ---------------- fused fp32 -> fp16 weight convert ----------------
__global__ void f2h_all(const float* __restrict__ w0, __half* __restrict__ o0, int n0,
                        const float* __restrict__ w1, __half* __restrict__ o1, int n1,
                        const float* __restrict__ w2, __half* __restrict__ o2, int n2,
                        const float* __restrict__ w3, __half* __restrict__ o3, int n3)
{
    int i = blockIdx.x * blockDim.x + threadIdx.x;
    if (i < n0) o0[i] = __float2half_rn(w0[i]);
    i -= n0;
    if (i >= 0 && i < n1) o1[i] = __float2half_rn(w1[i]);
    i -= n1;
    if (i >= 0 && i < n2) o2[i] = __float2half_rn(w2[i]);
    i -= n2;
    if (i >= 0 && i < n3) o3[i] = __float2half_rn(w3[i]);
}

// ---------------- LayerNorm (gate epilogue optional; fp32 or fp16 output) ----------
template<bool GATE, bool OUTH>
__global__ void ln_kernel(const float* __restrict__ in,
                          const float* __restrict__ g,
                          const float* __restrict__ b,
                          const float* __restrict__ gate,
                          void* __restrict__ outv, int cols)
{
    __shared__ float buf[2048];
    __shared__ float red[8];
    __shared__ float s_mu, s_rstd;
    const int row = blockIdx.x;
    const int tid = threadIdx.x;
    const float* pin = in + (size_t)row * cols;

    float s = 0.f;
    for (int c = tid; c < cols; c += 256) { float v = pin[c]; buf[c] = v; s += v; }
    #pragma unroll
    for (int o = 16; o; o >>= 1) s += __shfl_xor_sync(0xffffffffu, s, o);
    if ((tid & 31) == 0) red[tid >> 5] = s;
    __syncthreads();
    if (tid == 0) {
        float t = 0.f;
        #pragma unroll
        for (int i = 0; i < 8; i++) t += red[i];
        s_mu = t / (float)cols;
    }
    __syncthreads();
    const float mu = s_mu;
    float v2 = 0.f;
    for (int c = tid; c < cols; c += 256) { float xc = buf[c] - mu; v2 += xc * xc; }
    #pragma unroll
    for (int o = 16; o; o >>= 1) v2 += __shfl_xor_sync(0xffffffffu, v2, o);
    __syncthreads();
    if ((tid & 31) == 0) red[tid >> 5] = v2;
    __syncthreads();
    if (tid == 0) {
        float t = 0.f;
        #pragma unroll
        for (int i = 0; i < 8; i++) t += red[i];
        s_rstd = 1.f / sqrtf(t / (float)cols + LN_EPS);
    }
    __syncthreads();
    const float rstd = s_rstd;
    for (int c = tid; c < cols; c += 256) {
        float val = (buf[c] - mu) * rstd * g[c] + b[c];
        if (GATE) val *= sigmoidf_(gate[(size_t)row * cols + c]);
        if (OUTH) ((__half*)outv)[(size_t)row * cols + c] = __float2half_rn(val);
        else      ((float*)outv)[(size_t)row * cols + c] = val;
    }
}

// ---------------- fp16 tensor-core GEMM, 8 warps (64x32 each), ldmatrix -----------
// C = A(MxK) * B(NxK)^T.  128x128 tile, NSTG-stage cp.async, fp32 accumulate.
// EPI: 1 out_proj (C=resid+acc fp32, Ch=half copy) ; 2 gelu(acc+bias) -> Ch half ;
//      3 acc+bias+resid -> C fp32 ; 4 in_proj split (silu->C fp32 | raw->residF)
#define RSTR 40                             // halves per smem row (32 + 8 skew)

template<int EPI, int NSTG>
__global__ __launch_bounds__(256, 2)
void gemm_h(const __half* __restrict__ A, const __half* __restrict__ Bw,
            const float* __restrict__ bias, float* __restrict__ residF,
            float* __restrict__ C, __half* __restrict__ Ch,
            int M, int N, int K)
{
    constexpr int ASTG = 128 * RSTR;        // halves per stage per matrix
    constexpr int STG  = 2 * ASTG;
    extern __shared__ __half smh[];

    const int tid  = threadIdx.x;           // 256
    const int lane = tid & 31;
    const int w    = tid >> 5;               // 0..7
    const int wm   = w & 1;                  // 2 in M (64 rows)
    const int wn   = w >> 1;                 // 4 in N (32 cols)
    const int m0 = blockIdx.y * 128;
    const int n0 = blockIdx.x * 128;
    const int lq = lane >> 2;
    const int lr = lane & 3;
    const int l7  = lane & 7;
    const int l8  = (lane >> 3) & 1;
    const int l16 = lane >> 4;

    float acc[4][4][4];
    #pragma unroll
    for (int i = 0; i < 4; i++)
        #pragma unroll
        for (int j = 0; j < 4; j++)
            #pragma unroll
            for (int r = 0; r < 4; r++) acc[i][j][r] = 0.f;

    const int NC = K >> 5;                  // 32 k-halves per chunk

    auto load_stage = [&](int s, int k0) {
        __half* dA = smh + s * STG;
        __half* dB = dA + ASTG;
        #pragma unroll
        for (int i = 0; i < 2; i++) {
            int slot = tid + i * 256;       // 0..511
            int row = slot >> 2, c = slot & 3;
            cp16(smem_u32(dA + row * RSTR + c * 8), A  + (size_t)(m0 + row) * K + k0 + c * 8);
            cp16(smem_u32(dB + row * RSTR + c * 8), Bw + (size_t)(n0 + row) * K + k0 + c * 8);
        }
        asm volatile("cp.async.commit_group;" ::: "memory");
    };

    #pragma unroll
    for (int c = 0; c < NSTG - 1; c++) load_stage(c, c * 32);

    int s = 0, sl = NSTG - 1;
    for (int c = 0; c < NC; c++) {
        if (c <= NC - NSTG + 1) {
            asm volatile("cp.async.wait_group %0;" :: "n"(NSTG - 2) : "memory");
        } else {
            asm volatile("cp.async.wait_group 0;" ::: "memory");
        }
        __syncthreads();
        if (c + NSTG - 1 < NC) load_stage(sl, (c + NSTG - 1) * 32);

        const __half* sA = smh + s * STG;
        const __half* sB = sA + ASTG;
        #pragma unroll
        for (int kk = 0; kk < 32; kk += 16) {
            uint32_t af[4][4], bf[4][2];
            #pragma unroll
            for (int mt = 0; mt < 4; mt++) {
                int r = wm * 64 + mt * 16 + l7 + l8 * 8;
                uint32_t addr = smem_u32(&sA[r * RSTR + kk + l16 * 8]);
                ldsm4(af[mt][0], af[mt][1], af[mt][2], af[mt][3], addr);
            }
            #pragma unroll
            for (int p = 0; p < 2; p++) {
                int rn = wn * 32 + p * 16 + l7 + l16 * 8;
                uint32_t addr = smem_u32(&sB[rn * RSTR + kk + l8 * 8]);
                ldsm4(bf[2 * p][0], bf[2 * p][1], bf[2 * p + 1][0], bf[2 * p + 1][1], addr);
            }
            #pragma unroll
            for (int mt = 0; mt < 4; mt++)
                #pragma unroll
                for (int nt = 0; nt < 4; nt++)
                    MMA_F16(acc[mt][nt], af[mt][0], af[mt][1], af[mt][2], af[mt][3],
                            bf[nt][0], bf[nt][1]);
        }
        if (++s == NSTG) s = 0;
        if (++sl == NSTG) sl = 0;
    }

    #pragma unroll
    for (int mt = 0; mt < 4; mt++)
        #pragma unroll
        for (int nt = 0; nt < 4; nt++) {
            int r0 = m0 + wm * 64 + mt * 16 + lq;
            int cc = n0 + wn * 32 + nt * 8 + lr * 2;
            #pragma unroll
            for (int half_i = 0; half_i < 2; half_i++) {
                int m = r0 + half_i * 8;
                float v0 = acc[mt][nt][half_i * 2 + 0];
                float v1 = acc[mt][nt][half_i * 2 + 1];
                if (EPI == 1) {                 // out_proj: x += acc; also half copy
                    float2 rr = *reinterpret_cast<const float2*>(&residF[(size_t)m * N + cc]);
                    float o0 = v0 + rr.x, o1 = v1 + rr.y;
                    *reinterpret_cast<float2*>(&C[(size_t)m * N + cc]) = make_float2(o0, o1);
                    *reinterpret_cast<__half2*>(&Ch[(size_t)m * N + cc]) = __floats2half2_rn(o0, o1);
                } else if (EPI == 2) {          // MLP1: gelu -> half only
                    *reinterpret_cast<__half2*>(&Ch[(size_t)m * N + cc]) =
                        __floats2half2_rn(geluf(v0 + bias[cc]), geluf(v1 + bias[cc + 1]));
                } else if (EPI == 3) {          // MLP2: + bias + resid -> fp32
                    float2 rr = *reinterpret_cast<const float2*>(&residF[(size_t)m * N + cc]);
                    *reinterpret_cast<float2*>(&C[(size_t)m * N + cc]) =
                        make_float2(v0 + bias[cc] + rr.x, v1 + bias[cc + 1] + rr.y);
                } else {                        // EPI 4: in_proj split (no straddle)
                    if (cc < DI)
                        *reinterpret_cast<float2*>(&C[(size_t)m * DI + cc]) =
                            make_float2(siluf(v0), siluf(v1));
                    else
                        *reinterpret_cast<float2*>(&residF[(size_t)m * DI + cc - DI]) =
                            make_float2(v0, v1);
                }
            }
        }
}

// ---------------- xproj split-K GEMM (tf32, fp32 inputs) ----------------
#define SKEWF 36
__global__ __launch_bounds__(256, 2)
void xproj_splitk(const float* __restrict__ A, const float* __restrict__ Bw,
                  float* __restrict__ Cp, int K)
{
    constexpr int TBN  = 64;
    constexpr int NSTG = 4;
    constexpr int NT   = TBN / 32;
    constexpr int WNC  = TBN / 4;
    constexpr int ASTG = 128 * SKEWF;
    constexpr int BSTG = TBN * SKEWF;
    constexpr int STG  = ASTG + BSTG;
    extern __shared__ float sm[];

    const int tid  = threadIdx.x;
    const int lane = tid & 31;
    const int w    = tid >> 5;
    const int wm   = w & 1;
    const int wn   = w >> 1;
    const int m0 = blockIdx.y * 128;
    const int kz = blockIdx.x;
    const int kbase = kz * (K / KSPL);
    const int lq = lane >> 2;
    const int lr = lane & 3;
    float* C = Cp + (size_t)kz * ROWS * 64;

    float acc[4][NT][4];
    #pragma unroll
    for (int i = 0; i < 4; i++)
        #pragma unroll
        for (int j = 0; j < NT; j++)
            #pragma unroll
            for (int r = 0; r < 4; r++) acc[i][j][r] = 0.f;

    const int NC = (K / KSPL) >> 5;          // 4

    auto load_stage = [&](int s, int k0) {
        float* dA = sm + s * STG;
        float* dB = dA + ASTG;
        #pragma unroll
        for (int i = 0; i < 4; i++) {
            int slot = tid + i * 256;
            int row = slot >> 3, c4 = (slot & 7) * 4;
            cp16(smem_u32(dA + row * SKEWF + c4), A + (size_t)(m0 + row) * K + kbase + k0 + c4);
        }
        #pragma unroll
        for (int i = 0; i < 2; i++) {
            int slot = tid + i * 256;
            int row = slot >> 3, c4 = (slot & 7) * 4;
            cp16(smem_u32(dB + row * SKEWF + c4), Bw + (size_t)row * K + kbase + k0 + c4);
        }
        asm volatile("cp.async.commit_group;" ::: "memory");
    };

    #pragma unroll
    for (int c = 0; c < NSTG - 1; c++) load_stage(c, c * 32);

    int s = 0, sl = NSTG - 1;
    for (int c = 0; c < NC; c++) {
        if (c <= NC - NSTG + 1) {
            asm volatile("cp.async.wait_group %0;" :: "n"(NSTG - 2) : "memory");
        } else {
            asm volatile("cp.async.wait_group 0;" ::: "memory");
        }
        __syncthreads();
        if (c + NSTG - 1 < NC) load_stage(sl, (c + NSTG - 1) * 32);

        const float* sA = sm + s * STG;
        const float* sB = sA + ASTG;
        #pragma unroll
        for (int kk = 0; kk < 32; kk += 8) {
            uint32_t afr[4][4], bfr[NT][2];
            #pragma unroll
            for (int mt = 0; mt < 4; mt++) {
                int r = wm * 64 + mt * 16 + lq;
                afr[mt][0] = to_tf32u(sA[(r    ) * SKEWF + kk     + lr]);
                afr[mt][1] = to_tf32u(sA[(r + 8) * SKEWF + kk     + lr]);
                afr[mt][2] = to_tf32u(sA[(r    ) * SKEWF + kk + 4 + lr]);
                afr[mt][3] = to_tf32u(sA[(r + 8) * SKEWF + kk + 4 + lr]);
            }
            #pragma unroll
            for (int nt = 0; nt < NT; nt++) {
                int rn = wn * WNC + nt * 8 + lq;
                bfr[nt][0] = to_tf32u(sB[rn * SKEWF + kk     + lr]);
                bfr[nt][1] = to_tf32u(sB[rn * SKEWF + kk + 4 + lr]);
            }
            #pragma unroll
            for (int mt = 0; mt < 4; mt++)
                #pragma unroll
                for (int nt = 0; nt < NT; nt++)
                    MMA_TF32(acc[mt][nt], afr[mt][0], afr[mt][1], afr[mt][2], afr[mt][3],
                             bfr[nt][0], bfr[nt][1]);
        }
        if (++s == NSTG) s = 0;
        if (++sl == NSTG) sl = 0;
    }

    #pragma unroll
    for (int mt = 0; mt < 4; mt++)
        #pragma unroll
        for (int nt = 0; nt < NT; nt++) {
            int r0 = m0 + wm * 64 + mt * 16 + lq;
            int cc = wn * WNC + nt * 8 + lr * 2;
            #pragma unroll
            for (int half_i = 0; half_i < 2; half_i++) {
                int m = r0 + half_i * 8;
                *reinterpret_cast<float2*>(&C[(size_t)m * 64 + cc]) =
                    make_float2(acc[mt][nt][half_i * 2 + 0], acc[mt][nt][half_i * 2 + 1]);
            }
        }
}

// ---------------- split-K reduce ----------------
__global__ void prred_kernel(const float* __restrict__ prp, float* __restrict__ pr)
{
    int i = blockIdx.x * blockDim.x + threadIdx.x;
    if (i >= ROWS * 64) return;
    float s = 0.f;
    #pragma unroll
    for (int z = 0; z < KSPL; z++) s += prp[(size_t)z * ROWS * 64 + i];
    pr[i] = s;
}

// ---------------- fused double causal dwconv (K=4) + silu ----------------
#define CCHUNK 8
__global__ void conv2_kernel(const float* __restrict__ in,
                             const float* __restrict__ w1, const float* __restrict__ b1,
                             const float* __restrict__ w2, const float* __restrict__ b2,
                             float* __restrict__ out)
{
    int idx = blockIdx.x * blockDim.x + threadIdx.x;
    if (idx >= BATCH * DI * (SEQ / CCHUNK)) return;
    int d  = idx % DI;
    int r  = idx / DI;
    int c0 = r % (SEQ / CCHUNK);
    int b  = r / (SEQ / CCHUNK);
    int t0 = c0 * CCHUNK;

    const float wa0 = w1[d*4+0], wa1 = w1[d*4+1], wa2 = w1[d*4+2], wa3 = w1[d*4+3];
    const float wb0 = w2[d*4+0], wb1 = w2[d*4+1], wb2 = w2[d*4+2], wb3 = w2[d*4+3];
    const float bb1 = b1[d], bb2 = b2[d];
    const float* pin  = in  + (size_t)b * SEQ * DI + d;
    float*       pout = out + (size_t)b * SEQ * DI + d;

    float h[3];
    #pragma unroll
    for (int j = 0; j < 3; j++) {
        int t = t0 - 3 + j;
        if (t >= 0) {
            float a = bb1;
            float wv[4] = {wa0, wa1, wa2, wa3};
            #pragma unroll
            for (int k = 0; k < 4; k++) {
                int tt = t - 3 + k;
                if (tt >= 0) a = fmaf(pin[(size_t)tt * DI], wv[k], a);
            }
            h[j] = siluf(a);
        } else h[j] = 0.f;
    }
    float xm3 = (t0 - 3 >= 0) ? pin[(size_t)(t0 - 3) * DI] : 0.f;
    float xm2 = (t0 - 2 >= 0) ? pin[(size_t)(t0 - 2) * DI] : 0.f;
    float xm1 = (t0 - 1 >= 0) ? pin[(size_t)(t0 - 1) * DI] : 0.f;

    #pragma unroll
    for (int t = t0; t < t0 + CCHUNK; t++) {
        float xt = pin[(size_t)t * DI];
        float v1 = fmaf(wa0, xm3, bb1);
        v1 = fmaf(wa1, xm2, v1);
        v1 = fmaf(wa2, xm1, v1); v1 = fmaf(wa3, xt,  v1);
        float s = siluf(v1);
        float v2 = fmaf(wb0, h[0], bb2);
        v2 = fmaf(wb1, h[1], v2);
        v2 = fmaf(wb2, h[2], v2); v2 = fmaf(wb3, s,    v2);
        pout[(size_t)t * DI] = siluf(v2);
        xm3 = xm2; xm2 = xm1; xm1 = xt;
        h[0] = h[1]; h[1] = h[2]; h[2] = s;
    }
}

// ---------------- x_proj weight zero-pad ----------------
__global__ void wpad_kernel(const float* __restrict__ W, float* __restrict__ Wp)
{
    int idx = blockIdx.x * blockDim.x + threadIdx.x;
    if (idx >= NLAYER * 64 * DI) return;
    int k = idx % DI;
    int p = (idx / DI) % 64;
    int l = idx / (DI * 64);
    Wp[idx] = (p < 33) ? W[((size_t)l * 33 + p) * DI + k] : 0.f;
}

// ---------------- selective scan: 16 channels/block, smem-staged ----------------
#define SCH 64
#define NCHK (SEQ / SCH)
#define SCAN_SMEM ((2*SCH*16 + 2*SCH*64 + SCH*16) * 4)

__global__ __launch_bounds__(128)
void scan_kernel(const float* __restrict__ x, const float* __restrict__ pr,
                 const float* __restrict__ dtw, const float* __restrict__ dtb,
                 const float* __restrict__ Dv, float* __restrict__ y)
{
    extern __shared__ float sm[];
    float* SX = sm;                     // [2][SCH][16]
    float* SP = sm + 2 * SCH * 16;      // [2][SCH][64]
    float* SY = SP + 2 * SCH * 64;      // [SCH][16]

    const int tid = threadIdx.x;        // 128
    const int dd  = tid >> 3;           // 0..15
    const int sub = tid & 7;
    const int nblk = DI / 16;           // 128
    const int b  = blockIdx.x / nblk;
    const int d0 = (blockIdx.x % nblk) * 16;
    const int d  = d0 + dd;

    const float wdt = dtw[d], bdt = dtb[d], Dd = Dv[d];
    const float A0 = -(float)(sub * 2 + 1);
    const float A1 = -(float)(sub * 2 + 2);
    float h0 = 0.f, h1 = 0.f;

    const float* xg = x + (size_t)b * SEQ * DI + d0;
    const float* pg = pr + (size_t)b * SEQ * 64;
    float*       yg = y + (size_t)b * SEQ * DI + d0;

    auto load_chunk = [&](int buf, int c) {
        int t0 = c * SCH;
        float* dx = SX + buf * SCH * 16;
        float* dp = SP + buf * SCH * 64;
        // SX: 64*16/4 = 256 cp16 slots
        #pragma unroll
        for (int i = 0; i < 2; i++) {
            int slv = tid + i * 128;
            int t = slv >> 2, ch = slv & 3;
            cp16(smem_u32(dx + t * 16 + ch * 4), xg + (size_t)(t0 + t) * DI + ch * 4);
        }
        // SP: 64*64/4 = 1024 slots
        #pragma unroll
        for (int i = 0; i < 8; i++) {
            int slv = tid + i * 128;
            int t = slv >> 4, ch = slv & 15;
            cp16(smem_u32(dp + t * 64 + ch * 4), pg + (size_t)(t0 + t) * 64 + ch * 4);
        }
        asm volatile("cp.async.commit_group;" ::: "memory");
    };

    load_chunk(0, 0);
    load_chunk(1, 1);

    for (int c = 0; c < NCHK; c++) {
        const int buf = c & 1;
        if (c + 1 < NCHK) asm volatile("cp.async.wait_group 1;" ::: "memory");
        else              asm volatile("cp.async.wait_group 0;" ::: "memory");
        __syncthreads();

        const float* cx = SX + buf * SCH * 16;
        const float* cp = SP + buf * SCH * 64;
        #pragma unroll 4
        for (int s = 0; s < SCH; s++) {
            float dtraw = cp[s * 64];
            float xv    = cx[s * 16 + dd];
            float B0 = cp[s * 64 + 1 + 2 * sub], B1 = cp[s * 64 + 2 + 2 * sub];
            float C0 = cp[s * 64 + 17 + 2 * sub], C1 = cp[s * 64 + 18 + 2 * sub];
            float z  = fmaf(dtraw, wdt, bdt);
            float dt = (z > 20.f) ? z : log1pf(expf(z));
            float dtx = dt * xv;
            float t0v = fmaf(h0, A0, dtx * B0); h0 = fmaf(dt, t0v, h0);
            float t1v = fmaf(h1, A1, dtx * B1); h1 = fmaf(dt, t1v, h1);
            float yp = fmaf(h1, C1, h0 * C0);
            yp += __shfl_xor_sync(0xffffffffu, yp, 1);
            yp += __shfl_xor_sync(0xffffffffu, yp, 2);
            yp += __shfl_xor_sync(0xffffffffu, yp, 4);
            if (sub == 0) SY[s * 16 + dd] = fmaf(xv, Dd, yp);
        }
        __syncthreads();

        const int t0 = c * SCH;
        #pragma unroll
        for (int i = 0; i < 8; i++) {
            int slv = tid + i * 128;
            int s = slv >> 4, dd2 = slv & 15;
            yg[(size_t)(t0 + s) * DI + dd2] = SY[s * 16 + dd2];
        }
        if (c + 2 < NCHK) load_chunk(buf, c + 2);
    }
}

// ---------------- host orchestration ----------------
#define SMEM_H(NSTG)      ((NSTG) * 2 * 128 * RSTR * 2)
#define SMEM_X            (4 * (128 + 64) * SKEWF * 4)

extern "C" void kernel_launch(void* const* d_in, const int* in_sizes, int n_in,
                              void* d_out, int out_size)
{
    const float* hidden      = (const float*)d_in[0];
    const float* in_norm_g   = (const float*)d_in[1];
    const float* in_norm_b   = (const float*)d_in[2];
    const float* ln_g        = (const float*)d_in[3];
    const float* ln_b        = (const float*)d_in[4];
    const float* in_proj_w   = (const float*)d_in[5];
    const float* conv_w      = (const float*)d_in[6];
    const float* conv_b      = (const float*)d_in[7];
    const float* x_proj_w    = (const float*)d_in[8];
    const float* dt_proj_w   = (const float*)d_in[9];
    const float* dt_proj_b   = (const float*)d_in[10];
    const float* Dv          = (const float*)d_in[11];
    const float* mamba_ln_g  = (const float*)d_in[12];
    const float* mamba_ln_b  = (const float*)d_in[13];
    const float* out_proj_w  = (const float*)d_in[14];
    const float* op1_w       = (const float*)d_in[15];
    const float* op1_b       = (const float*)d_in[16];
    const float* op2_w       = (const float*)d_in[17];
    const float* op2_b       = (const float*)d_in[18];

    float *x, *res, *xi, *xi2, *pr, *prp, *y, *wp;
    __half *xnh, *yh, *xh, *t1h, *wih, *woh, *op1h, *op2h;
    cudaGetSymbolAddress((void**)&x,    g_x);
    cudaGetSymbolAddress((void**)&res,  g_res);
    cudaGetSymbolAddress((void**)&xi,   g_xi);
    cudaGetSymbolAddress((void**)&xi2,  g_xi2);
    cudaGetSymbolAddress((void**)&pr,   g_pr);
    cudaGetSymbolAddress((void**)&prp,  g_prp);
    cudaGetSymbolAddress((void**)&y,    g_y);
    cudaGetSymbolAddress((void**)&wp,   g_wp);
    cudaGetSymbolAddress((void**)&xnh,  g_xnh);
    cudaGetSymbolAddress((void**)&yh,   g_yh);
    cudaGetSymbolAddress((void**)&xh,   g_xh);
    cudaGetSymbolAddress((void**)&t1h,  g_t1h);
    cudaGetSymbolAddress((void**)&wih,  g_wih);
    cudaGetSymbolAddress((void**)&woh,  g_woh);
    cudaGetSymbolAddress((void**)&op1h, g_op1h);
    cudaGetSymbolAddress((void**)&op2h, g_op2h);

    cudaFuncSetAttribute(gemm_h<1,4>, cudaFuncAttributeMaxDynamicSharedMemorySize, SMEM_H(4));
    cudaFuncSetAttribute(gemm_h<2,4>, cudaFuncAttributeMaxDynamicSharedMemorySize, SMEM_H(4));
    cudaFuncSetAttribute(gemm_h<3,4>, cudaFuncAttributeMaxDynamicSharedMemorySize, SMEM_H(4));
    cudaFuncSetAttribute(gemm_h<4,4>, cudaFuncAttributeMaxDynamicSharedMemorySize, SMEM_H(4));
    cudaFuncSetAttribute(xproj_splitk, cudaFuncAttributeMaxDynamicSharedMemorySize, SMEM_X);
    cudaFuncSetAttribute(scan_kernel, cudaFuncAttributeMaxDynamicSharedMemorySize, SCAN_SMEM);

    // fused weight conversion (one launch)
    {
        int n0 = NLAYER * 2 * DI * HID;
        int n1 = NLAYER * HID * DI;
        int n2 = HID * HID;
        int n3 = HID * HID;
        int tot = n0 + n1 + n2 + n3;
        f2h_all<<<(tot + 255) / 256, 256>>>(in_proj_w, wih, n0, out_proj_w, woh, n1,
                                            op1_w, op1h, n2, op2_w, op2h, n3);
    }
    wpad_kernel<<<(NLAYER * 64 * DI + 255) / 256, 256>>>(x_proj_w, wp);

    // x = LN(hidden)  (fp32 residual)
    ln_kernel<false,false><<<ROWS, 256>>>(hidden, in_norm_g, in_norm_b, nullptr, x, HID);

    for (int l = 0; l < NLAYER; l++) {
        // xnh = half(LN(x))
        ln_kernel<false,true><<<ROWS, 256>>>(x, ln_g + (size_t)l * HID, ln_b + (size_t)l * HID,
                                             nullptr, xnh, HID);
        // in_proj: xi = silu(first half), res = second half  (2048x4096x1024 fp16)
        gemm_h<4,4><<<dim3(2 * DI / 128, ROWS / 128), 256, SMEM_H(4)>>>(
            xnh, wih + (size_t)l * 2 * DI * HID, nullptr, res, xi, nullptr, ROWS, 2 * DI, HID);
        // fused conv1+silu+conv2+silu : xi -> xi2
        conv2_kernel<<<(BATCH * DI * (SEQ / CCHUNK)) / 256, 256>>>(
            xi,
            conv_w + (size_t)(l * 2 + 0) * DI * KCONV, conv_b + (size_t)(l * 2 + 0) * DI,
            conv_w + (size_t)(l * 2 + 1) * DI * KCONV, conv_b + (size_t)(l * 2 + 1) * DI,
            xi2);
        // proj partials (split-K over 256 CTAs), then reduce
        xproj_splitk<<<dim3(KSPL, ROWS / 128), 256, SMEM_X>>>(
            xi2, wp + (size_t)l * 64 * DI, prp, DI);
        prred_kernel<<<(ROWS * 64 + 255) / 256, 256>>>(prp, pr);
        // selective scan -> y
        scan_kernel<<<BATCH * (DI / 16), 128, SCAN_SMEM>>>(
            xi2, pr, dt_proj_w + (size_t)l * DI, dt_proj_b + (size_t)l * DI,
            Dv + (size_t)l * DI, y);
        // yh = half(LN(y) * sigmoid(res))
        ln_kernel<true,true><<<ROWS, 256>>>(y, mamba_ln_g + (size_t)l * DI,
                                            mamba_ln_b + (size_t)l * DI, res, yh, DI);
        // x = x + yh @ woh^T  (fp32 out + half copy xh)
        gemm_h<1,4><<<dim3(HID / 128, ROWS / 128), 256, SMEM_H(4)>>>(
            yh, woh + (size_t)l * HID * DI, nullptr, x, x, xh, ROWS, HID, DI);
    }

    // t1h = half(gelu(xh @ op1h^T + op1_b))
    gemm_h<2,4><<<dim3(HID / 128, ROWS / 128), 256, SMEM_H(4)>>>(
        xh, op1h, op1_b, nullptr, nullptr, t1h, ROWS, HID, HID);
    // out = t1h @ op2h^T + op2_b + hidden  (fp32)
    gemm_h<3,4><<<dim3(HID / 128, ROWS / 128), 256, SMEM_H(4)>>>(
        t1h, op2h, op2_b, (float*)hidden, (float*)d_out, nullptr, ROWS, HID, HID);
}

// round 14
// speedup vs baseline: 1.4675x; 1.0169x over previous
#include <cuda_runtime.h>
#include <cuda_fp16.h>
#include <math.h>
#include <stdint.h>

#define BATCH 2
#define SEQ   1024
#define HID   1024
#define DI    2048
#define NST   16
#define KCONV 4
#define NLAYER 4
#define ROWS  (BATCH*SEQ)      // 2048
#define LN_EPS 1e-5f
#define KSPL  16               // xproj split-K factor

// ---------------- scratch (device globals; no allocation) ----------------
__device__ float g_x  [ROWS*HID];
__device__ float g_res[ROWS*DI];
__device__ float g_xi [ROWS*DI];
__device__ float g_xi2[ROWS*DI];
__device__ float g_pr [ROWS*64];          // padded proj (stride 64)
__device__ float g_prp[KSPL*ROWS*64];     // split-K partials
__device__ float g_y  [ROWS*DI];
__device__ float g_wp [NLAYER*64*DI];     // zero-padded x_proj weights (fp32, tf32 path)
// half operands
__device__ __half g_xnh [ROWS*HID];
__device__ __half g_yh  [ROWS*DI];
__device__ __half g_xh  [ROWS*HID];
__device__ __half g_t1h [ROWS*HID];
__device__ __half g_wih [NLAYER*2*DI*HID];
__device__ __half g_woh [NLAYER*HID*DI];
__device__ __half g_op1h[HID*HID];
__device__ __half g_op2h[HID*HID];

// ---------------- helpers ----------------
__device__ __forceinline__ float siluf(float v) { return v / (1.f + expf(-v)); }
__device__ __forceinline__ float sigmoidf_(float v) { return 1.f / (1.f + expf(-v)); }
__device__ __forceinline__ float geluf(float v) { return 0.5f * v * (1.f + erff(v * 0.70710678118654752f)); }
__device__ __forceinline__ uint32_t to_tf32u(float x) {
    uint32_t u;
    asm("cvt.rna.tf32.f32 %0, %1;" : "=r"(u) : "f"(x));
    return u;
}
__device__ __forceinline__ uint32_t smem_u32(const void* p) {
    uint32_t a;
    asm("{ .reg .u64 t; cvta.to.shared.u64 t, %1; cvt.u32.u64 %0, t; }" : "=r"(a) : "l"(p));
    return a;
}
__device__ __forceinline__ void cp16(uint32_t d, const void* g) {
    asm volatile("cp.async.cg.shared.global [%0], [%1], 16;" :: "r"(d), "l"(g));
}
__device__ __forceinline__ void ldsm4(uint32_t& r0, uint32_t& r1, uint32_t& r2, uint32_t& r3,
                                      uint32_t a) {
    asm volatile("ldmatrix.sync.aligned.m8n8.x4.shared.b16 {%0,%1,%2,%3}, [%4];"
                 : "=r"(r0), "=r"(r1), "=r"(r2), "=r"(r3) : "r"(a));
}
#define MMA_TF32(acc, a0,a1,a2,a3, b0,b1)                                     \
    asm volatile(                                                             \
        "mma.sync.aligned.m16n8k8.row.col.f32.tf32.tf32.f32 "                 \
        "{%0,%1,%2,%3}, {%4,%5,%6,%7}, {%8,%9}, {%0,%1,%2,%3};"               \
        : "+f"((acc)[0]), "+f"((acc)[1]), "+f"((acc)[2]), "+f"((acc)[3])      \
        : "r"(a0), "r"(a1), "r"(a2), "r"(a3), "r"(b0), "r"(b1))
#define MMA_F16(acc, a0,a1,a2,a3, b0,b1)                                      \
    asm volatile(                                                             \
        "mma.sync.aligned.m16n8k16.row.col.f32.f16.f16.f32 "                  \
        "{%0,%1,%2,%3}, {%4,%5,%6,%7}, {%8,%9}, {%0,%1,%2,%3};"               \
        : "+f"((acc)[0]), "+f"((acc)[1]), "+f"((acc)[2]), "+f"((acc)[3])      \
        : "r"(a0), "r"(a1), "r"(a2), "r"(a3), "r"(b0), "r"(b1))

// ---------------- fused fp32 -> fp16 weight convert ----------------
__global__ void f2h_all(const float* __restrict__ w0, __half* __restrict__ o0, int n0,
                        const float* __restrict__ w1, __half* __restrict__ o1, int n1,
                        const float* __restrict__ w2, __half* __restrict__ o2, int n2,
                        const float* __restrict__ w3, __half* __restrict__ o3, int n3)
{
    int i = blockIdx.x * blockDim.x + threadIdx.x;
    if (i < n0) o0[i] = __float2half_rn(w0[i]);
    i -= n0;
    if (i >= 0 && i < n1) o1[i] = __float2half_rn(w1[i]);
    i -= n1;
    if (i >= 0 && i < n2) o2[i] = __float2half_rn(w2[i]);
    i -= n2;
    if (i >= 0 && i < n3) o3[i] = __float2half_rn(w3[i]);
}

// ---------------- LayerNorm (gate epilogue optional; fp32 or fp16 output) ----------
template<bool GATE, bool OUTH>
__global__ void ln_kernel(const float* __restrict__ in,
                          const float* __restrict__ g,
                          const float* __restrict__ b,
                          const float* __restrict__ gate,
                          void* __restrict__ outv, int cols)
{
    __shared__ float buf[2048];
    __shared__ float red[8];
    __shared__ float s_mu, s_rstd;
    const int row = blockIdx.x;
    const int tid = threadIdx.x;
    const float* pin = in + (size_t)row * cols;

    float s = 0.f;
    for (int c = tid; c < cols; c += 256) { float v = pin[c]; buf[c] = v; s += v; }
    #pragma unroll
    for (int o = 16; o; o >>= 1) s += __shfl_xor_sync(0xffffffffu, s, o);
    if ((tid & 31) == 0) red[tid >> 5] = s;
    __syncthreads();
    if (tid == 0) {
        float t = 0.f;
        #pragma unroll
        for (int i = 0; i < 8; i++) t += red[i];
        s_mu = t / (float)cols;
    }
    __syncthreads();
    const float mu = s_mu;
    float v2 = 0.f;
    for (int c = tid; c < cols; c += 256) { float xc = buf[c] - mu; v2 += xc * xc; }
    #pragma unroll
    for (int o = 16; o; o >>= 1) v2 += __shfl_xor_sync(0xffffffffu, v2, o);
    __syncthreads();
    if ((tid & 31) == 0) red[tid >> 5] = v2;
    __syncthreads();
    if (tid == 0) {
        float t = 0.f;
        #pragma unroll
        for (int i = 0; i < 8; i++) t += red[i];
        s_rstd = 1.f / sqrtf(t / (float)cols + LN_EPS);
    }
    __syncthreads();
    const float rstd = s_rstd;
    for (int c = tid; c < cols; c += 256) {
        float val = (buf[c] - mu) * rstd * g[c] + b[c];
        if (GATE) val *= sigmoidf_(gate[(size_t)row * cols + c]);
        if (OUTH) ((__half*)outv)[(size_t)row * cols + c] = __float2half_rn(val);
        else      ((float*)outv)[(size_t)row * cols + c] = val;
    }
}

// ---------------- fp16 tensor-core GEMM, 8 warps, ldmatrix, templated TBN ---------
// C = A(MxK) * B(NxK)^T.  128xTBN tile, NSTG-stage cp.async, fp32 accumulate.
// TBN=128: warps 2(M)x4(N), 64x32 each.  TBN=64: warps 4(M)x2(N), 32x32 each.
// EPI: 1 out_proj (C=resid+acc fp32, Ch=half copy) ; 2 gelu(acc+bias) -> Ch half ;
//      3 acc+bias+resid -> C fp32 ; 4 in_proj split (silu->C fp32 | raw->residF)
#define RSTR 40                             // halves per smem row (32 + 8 skew)

template<int EPI, int TBN, int NSTG>
__global__ __launch_bounds__(256, 2)
void gemm_h(const __half* __restrict__ A, const __half* __restrict__ Bw,
            const float* __restrict__ bias, float* __restrict__ residF,
            float* __restrict__ C, __half* __restrict__ Ch,
            int M, int N, int K)
{
    constexpr int WMW   = (TBN == 128) ? 2 : 4;   // warps along M
    constexpr int MROWS = 128 / WMW;              // rows per warp
    constexpr int MT    = MROWS / 16;             // m16 tiles per warp (4 or 2)
    constexpr int ASTG  = 128 * RSTR;
    constexpr int BSTG  = TBN * RSTR;
    constexpr int STG   = ASTG + BSTG;
    extern __shared__ __half smh[];

    const int tid  = threadIdx.x;           // 256
    const int lane = tid & 31;
    const int w    = tid >> 5;               // 0..7
    const int wm   = w & (WMW - 1);
    const int wn   = w / WMW;                 // 0..(8/WMW-1), 32 cols each
    const int m0 = blockIdx.y * 128;
    const int n0 = blockIdx.x * TBN;
    const int lq = lane >> 2;
    const int lr = lane & 3;
    const int l7  = lane & 7;
    const int l8  = (lane >> 3) & 1;
    const int l16 = lane >> 4;

    float acc[MT][4][4];
    #pragma unroll
    for (int i = 0; i < MT; i++)
        #pragma unroll
        for (int j = 0; j < 4; j++)
            #pragma unroll
            for (int r = 0; r < 4; r++) acc[i][j][r] = 0.f;

    const int NC = K >> 5;                  // 32 k-halves per chunk

    auto load_stage = [&](int s, int k0) {
        __half* dA = smh + s * STG;
        __half* dB = dA + ASTG;
        #pragma unroll
        for (int i = 0; i < 2; i++) {                 // A: 512 slots
            int slot = tid + i * 256;
            int row = slot >> 2, c = slot & 3;
            cp16(smem_u32(dA + row * RSTR + c * 8), A + (size_t)(m0 + row) * K + k0 + c * 8);
        }
        #pragma unroll
        for (int i = 0; i < TBN * 4 / 256; i++) {     // B: TBN*4 slots
            int slot = tid + i * 256;
            int row = slot >> 2, c = slot & 3;
            cp16(smem_u32(dB + row * RSTR + c * 8), Bw + (size_t)(n0 + row) * K + k0 + c * 8);
        }
        asm volatile("cp.async.commit_group;" ::: "memory");
    };

    #pragma unroll
    for (int c = 0; c < NSTG - 1; c++) load_stage(c, c * 32);

    int s = 0, sl = NSTG - 1;
    for (int c = 0; c < NC; c++) {
        if (c <= NC - NSTG + 1) {
            asm volatile("cp.async.wait_group %0;" :: "n"(NSTG - 2) : "memory");
        } else {
            asm volatile("cp.async.wait_group 0;" ::: "memory");
        }
        __syncthreads();
        if (c + NSTG - 1 < NC) load_stage(sl, (c + NSTG - 1) * 32);

        const __half* sA = smh + s * STG;
        const __half* sB = sA + ASTG;
        #pragma unroll
        for (int kk = 0; kk < 32; kk += 16) {
            uint32_t af[MT][4], bf[4][2];
            #pragma unroll
            for (int mt = 0; mt < MT; mt++) {
                int r = wm * MROWS + mt * 16 + l7 + l8 * 8;
                uint32_t addr = smem_u32(&sA[r * RSTR + kk + l16 * 8]);
                ldsm4(af[mt][0], af[mt][1], af[mt][2], af[mt][3], addr);
            }
            #pragma unroll
            for (int p = 0; p < 2; p++) {
                int rn = wn * 32 + p * 16 + l7 + l16 * 8;
                uint32_t addr = smem_u32(&sB[rn * RSTR + kk + l8 * 8]);
                ldsm4(bf[2 * p][0], bf[2 * p][1], bf[2 * p + 1][0], bf[2 * p + 1][1], addr);
            }
            #pragma unroll
            for (int mt = 0; mt < MT; mt++)
                #pragma unroll
                for (int nt = 0; nt < 4; nt++)
                    MMA_F16(acc[mt][nt], af[mt][0], af[mt][1], af[mt][2], af[mt][3],
                            bf[nt][0], bf[nt][1]);
        }
        if (++s == NSTG) s = 0;
        if (++sl == NSTG) sl = 0;
    }

    #pragma unroll
    for (int mt = 0; mt < MT; mt++)
        #pragma unroll
        for (int nt = 0; nt < 4; nt++) {
            int r0 = m0 + wm * MROWS + mt * 16 + lq;
            int cc = n0 + wn * 32 + nt * 8 + lr * 2;
            #pragma unroll
            for (int half_i = 0; half_i < 2; half_i++) {
                int m = r0 + half_i * 8;
                float v0 = acc[mt][nt][half_i * 2 + 0];
                float v1 = acc[mt][nt][half_i * 2 + 1];
                if (EPI == 1) {                 // out_proj: x += acc; also half copy
                    float2 rr = *reinterpret_cast<const float2*>(&residF[(size_t)m * N + cc]);
                    float o0 = v0 + rr.x, o1 = v1 + rr.y;
                    *reinterpret_cast<float2*>(&C[(size_t)m * N + cc]) = make_float2(o0, o1);
                    *reinterpret_cast<__half2*>(&Ch[(size_t)m * N + cc]) = __floats2half2_rn(o0, o1);
                } else if (EPI == 2) {          // MLP1: gelu -> half only
                    *reinterpret_cast<__half2*>(&Ch[(size_t)m * N + cc]) =
                        __floats2half2_rn(geluf(v0 + bias[cc]), geluf(v1 + bias[cc + 1]));
                } else if (EPI == 3) {          // MLP2: + bias + resid -> fp32
                    float2 rr = *reinterpret_cast<const float2*>(&residF[(size_t)m * N + cc]);
                    *reinterpret_cast<float2*>(&C[(size_t)m * N + cc]) =
                        make_float2(v0 + bias[cc] + rr.x, v1 + bias[cc + 1] + rr.y);
                } else {                        // EPI 4: in_proj split (no straddle)
                    if (cc < DI)
                        *reinterpret_cast<float2*>(&C[(size_t)m * DI + cc]) =
                            make_float2(siluf(v0), siluf(v1));
                    else
                        *reinterpret_cast<float2*>(&residF[(size_t)m * DI + cc - DI]) =
                            make_float2(v0, v1);
                }
            }
        }
}

// ---------------- xproj split-K GEMM (tf32, fp32 inputs) ----------------
#define SKEWF 36
__global__ __launch_bounds__(256, 2)
void xproj_splitk(const float* __restrict__ A, const float* __restrict__ Bw,
                  float* __restrict__ Cp, int K)
{
    constexpr int TBN  = 64;
    constexpr int NSTG = 4;
    constexpr int NT   = TBN / 32;
    constexpr int WNC  = TBN / 4;
    constexpr int ASTG = 128 * SKEWF;
    constexpr int BSTG = TBN * SKEWF;
    constexpr int STG  = ASTG + BSTG;
    extern __shared__ float sm[];

    const int tid  = threadIdx.x;
    const int lane = tid & 31;
    const int w    = tid >> 5;
    const int wm   = w & 1;
    const int wn   = w >> 1;
    const int m0 = blockIdx.y * 128;
    const int kz = blockIdx.x;
    const int kbase = kz * (K / KSPL);
    const int lq = lane >> 2;
    const int lr = lane & 3;
    float* C = Cp + (size_t)kz * ROWS * 64;

    float acc[4][NT][4];
    #pragma unroll
    for (int i = 0; i < 4; i++)
        #pragma unroll
        for (int j = 0; j < NT; j++)
            #pragma unroll
            for (int r = 0; r < 4; r++) acc[i][j][r] = 0.f;

    const int NC = (K / KSPL) >> 5;          // 4

    auto load_stage = [&](int s, int k0) {
        float* dA = sm + s * STG;
        float* dB = dA + ASTG;
        #pragma unroll
        for (int i = 0; i < 4; i++) {
            int slot = tid + i * 256;
            int row = slot >> 3, c4 = (slot & 7) * 4;
            cp16(smem_u32(dA + row * SKEWF + c4), A + (size_t)(m0 + row) * K + kbase + k0 + c4);
        }
        #pragma unroll
        for (int i = 0; i < 2; i++) {
            int slot = tid + i * 256;
            int row = slot >> 3, c4 = (slot & 7) * 4;
            cp16(smem_u32(dB + row * SKEWF + c4), Bw + (size_t)row * K + kbase + k0 + c4);
        }
        asm volatile("cp.async.commit_group;" ::: "memory");
    };

    #pragma unroll
    for (int c = 0; c < NSTG - 1; c++) load_stage(c, c * 32);

    int s = 0, sl = NSTG - 1;
    for (int c = 0; c < NC; c++) {
        if (c <= NC - NSTG + 1) {
            asm volatile("cp.async.wait_group %0;" :: "n"(NSTG - 2) : "memory");
        } else {
            asm volatile("cp.async.wait_group 0;" ::: "memory");
        }
        __syncthreads();
        if (c + NSTG - 1 < NC) load_stage(sl, (c + NSTG - 1) * 32);

        const float* sA = sm + s * STG;
        const float* sB = sA + ASTG;
        #pragma unroll
        for (int kk = 0; kk < 32; kk += 8) {
            uint32_t afr[4][4], bfr[NT][2];
            #pragma unroll
            for (int mt = 0; mt < 4; mt++) {
                int r = wm * 64 + mt * 16 + lq;
                afr[mt][0] = to_tf32u(sA[(r    ) * SKEWF + kk     + lr]);
                afr[mt][1] = to_tf32u(sA[(r + 8) * SKEWF + kk     + lr]);
                afr[mt][2] = to_tf32u(sA[(r    ) * SKEWF + kk + 4 + lr]);
                afr[mt][3] = to_tf32u(sA[(r + 8) * SKEWF + kk + 4 + lr]);
            }
            #pragma unroll
            for (int nt = 0; nt < NT; nt++) {
                int rn = wn * WNC + nt * 8 + lq;
                bfr[nt][0] = to_tf32u(sB[rn * SKEWF + kk     + lr]);
                bfr[nt][1] = to_tf32u(sB[rn * SKEWF + kk + 4 + lr]);
            }
            #pragma unroll
            for (int mt = 0; mt < 4; mt++)
                #pragma unroll
                for (int nt = 0; nt < NT; nt++)
                    MMA_TF32(acc[mt][nt], afr[mt][0], afr[mt][1], afr[mt][2], afr[mt][3],
                             bfr[nt][0], bfr[nt][1]);
        }
        if (++s == NSTG) s = 0;
        if (++sl == NSTG) sl = 0;
    }

    #pragma unroll
    for (int mt = 0; mt < 4; mt++)
        #pragma unroll
        for (int nt = 0; nt < NT; nt++) {
            int r0 = m0 + wm * 64 + mt * 16 + lq;
            int cc = wn * WNC + nt * 8 + lr * 2;
            #pragma unroll
            for (int half_i = 0; half_i < 2; half_i++) {
                int m = r0 + half_i * 8;
                *reinterpret_cast<float2*>(&C[(size_t)m * 64 + cc]) =
                    make_float2(acc[mt][nt][half_i * 2 + 0], acc[mt][nt][half_i * 2 + 1]);
            }
        }
}

// ---------------- split-K reduce ----------------
__global__ void prred_kernel(const float* __restrict__ prp, float* __restrict__ pr)
{
    int i = blockIdx.x * blockDim.x + threadIdx.x;
    if (i >= ROWS * 64) return;
    float s = 0.f;
    #pragma unroll
    for (int z = 0; z < KSPL; z++) s += prp[(size_t)z * ROWS * 64 + i];
    pr[i] = s;
}

// ---------------- fused double causal dwconv (K=4) + silu ----------------
#define CCHUNK 8
__global__ void conv2_kernel(const float* __restrict__ in,
                             const float* __restrict__ w1, const float* __restrict__ b1,
                             const float* __restrict__ w2, const float* __restrict__ b2,
                             float* __restrict__ out)
{
    int idx = blockIdx.x * blockDim.x + threadIdx.x;
    if (idx >= BATCH * DI * (SEQ / CCHUNK)) return;
    int d  = idx % DI;
    int r  = idx / DI;
    int c0 = r % (SEQ / CCHUNK);
    int b  = r / (SEQ / CCHUNK);
    int t0 = c0 * CCHUNK;

    const float wa0 = w1[d*4+0], wa1 = w1[d*4+1], wa2 = w1[d*4+2], wa3 = w1[d*4+3];
    const float wb0 = w2[d*4+0], wb1 = w2[d*4+1], wb2 = w2[d*4+2], wb3 = w2[d*4+3];
    const float bb1 = b1[d], bb2 = b2[d];
    const float* pin  = in  + (size_t)b * SEQ * DI + d;
    float*       pout = out + (size_t)b * SEQ * DI + d;

    float h[3];
    #pragma unroll
    for (int j = 0; j < 3; j++) {
        int t = t0 - 3 + j;
        if (t >= 0) {
            float a = bb1;
            float wv[4] = {wa0, wa1, wa2, wa3};
            #pragma unroll
            for (int k = 0; k < 4; k++) {
                int tt = t - 3 + k;
                if (tt >= 0) a = fmaf(pin[(size_t)tt * DI], wv[k], a);
            }
            h[j] = siluf(a);
        } else h[j] = 0.f;
    }
    float xm3 = (t0 - 3 >= 0) ? pin[(size_t)(t0 - 3) * DI] : 0.f;
    float xm2 = (t0 - 2 >= 0) ? pin[(size_t)(t0 - 2) * DI] : 0.f;
    float xm1 = (t0 - 1 >= 0) ? pin[(size_t)(t0 - 1) * DI] : 0.f;

    #pragma unroll
    for (int t = t0; t < t0 + CCHUNK; t++) {
        float xt = pin[(size_t)t * DI];
        float v1 = fmaf(wa0, xm3, bb1);
        v1 = fmaf(wa1, xm2, v1);
        v1 = fmaf(wa2, xm1, v1); v1 = fmaf(wa3, xt,  v1);
        float s = siluf(v1);
        float v2 = fmaf(wb0, h[0], bb2);
        v2 = fmaf(wb1, h[1], v2);
        v2 = fmaf(wb2, h[2], v2); v2 = fmaf(wb3, s,    v2);
        pout[(size_t)t * DI] = siluf(v2);
        xm3 = xm2; xm2 = xm1; xm1 = xt;
        h[0] = h[1]; h[1] = h[2]; h[2] = s;
    }
}

// ---------------- x_proj weight zero-pad ----------------
__global__ void wpad_kernel(const float* __restrict__ W, float* __restrict__ Wp)
{
    int idx = blockIdx.x * blockDim.x + threadIdx.x;
    if (idx >= NLAYER * 64 * DI) return;
    int k = idx % DI;
    int p = (idx / DI) % 64;
    int l = idx / (DI * 64);
    Wp[idx] = (p < 33) ? W[((size_t)l * 33 + p) * DI + k] : 0.f;
}

// ---------------- selective scan: 16 channels/block, smem-staged ----------------
#define SCH 64
#define NCHK (SEQ / SCH)
#define SCAN_SMEM ((2*SCH*16 + 2*SCH*64 + SCH*16) * 4)

__global__ __launch_bounds__(128)
void scan_kernel(const float* __restrict__ x, const float* __restrict__ pr,
                 const float* __restrict__ dtw, const float* __restrict__ dtb,
                 const float* __restrict__ Dv, float* __restrict__ y)
{
    extern __shared__ float sm[];
    float* SX = sm;                     // [2][SCH][16]
    float* SP = sm + 2 * SCH * 16;      // [2][SCH][64]
    float* SY = SP + 2 * SCH * 64;      // [SCH][16]

    const int tid = threadIdx.x;        // 128
    const int dd  = tid >> 3;           // 0..15
    const int sub = tid & 7;
    const int nblk = DI / 16;           // 128
    const int b  = blockIdx.x / nblk;
    const int d0 = (blockIdx.x % nblk) * 16;
    const int d  = d0 + dd;

    const float wdt = dtw[d], bdt = dtb[d], Dd = Dv[d];
    const float A0 = -(float)(sub * 2 + 1);
    const float A1 = -(float)(sub * 2 + 2);
    float h0 = 0.f, h1 = 0.f;

    const float* xg = x + (size_t)b * SEQ * DI + d0;
    const float* pg = pr + (size_t)b * SEQ * 64;
    float*       yg = y + (size_t)b * SEQ * DI + d0;

    auto load_chunk = [&](int buf, int c) {
        int t0 = c * SCH;
        float* dx = SX + buf * SCH * 16;
        float* dp = SP + buf * SCH * 64;
        #pragma unroll
        for (int i = 0; i < 2; i++) {
            int slv = tid + i * 128;
            int t = slv >> 2, ch = slv & 3;
            cp16(smem_u32(dx + t * 16 + ch * 4), xg + (size_t)(t0 + t) * DI + ch * 4);
        }
        #pragma unroll
        for (int i = 0; i < 8; i++) {
            int slv = tid + i * 128;
            int t = slv >> 4, ch = slv & 15;
            cp16(smem_u32(dp + t * 64 + ch * 4), pg + (size_t)(t0 + t) * 64 + ch * 4);
        }
        asm volatile("cp.async.commit_group;" ::: "memory");
    };

    load_chunk(0, 0);
    load_chunk(1, 1);

    for (int c = 0; c < NCHK; c++) {
        const int buf = c & 1;
        if (c + 1 < NCHK) asm volatile("cp.async.wait_group 1;" ::: "memory");
        else              asm volatile("cp.async.wait_group 0;" ::: "memory");
        __syncthreads();

        const float* cx = SX + buf * SCH * 16;
        const float* cp = SP + buf * SCH * 64;
        #pragma unroll 4
        for (int s = 0; s < SCH; s++) {
            float dtraw = cp[s * 64];
            float xv    = cx[s * 16 + dd];
            float B0 = cp[s * 64 + 1 + 2 * sub], B1 = cp[s * 64 + 2 + 2 * sub];
            float C0 = cp[s * 64 + 17 + 2 * sub], C1 = cp[s * 64 + 18 + 2 * sub];
            float z  = fmaf(dtraw, wdt, bdt);
            float dt = (z > 20.f) ? z : log1pf(expf(z));
            float dtx = dt * xv;
            float t0v = fmaf(h0, A0, dtx * B0); h0 = fmaf(dt, t0v, h0);
            float t1v = fmaf(h1, A1, dtx * B1); h1 = fmaf(dt, t1v, h1);
            float yp = fmaf(h1, C1, h0 * C0);
            yp += __shfl_xor_sync(0xffffffffu, yp, 1);
            yp += __shfl_xor_sync(0xffffffffu, yp, 2);
            yp += __shfl_xor_sync(0xffffffffu, yp, 4);
            if (sub == 0) SY[s * 16 + dd] = fmaf(xv, Dd, yp);
        }
        __syncthreads();

        const int t0 = c * SCH;
        #pragma unroll
        for (int i = 0; i < 8; i++) {
            int slv = tid + i * 128;
            int s = slv >> 4, dd2 = slv & 15;
            yg[(size_t)(t0 + s) * DI + dd2] = SY[s * 16 + dd2];
        }
        if (c + 2 < NCHK) load_chunk(buf, c + 2);
    }
}

// ---------------- host orchestration ----------------
#define SMEM_H128 (4 * (128 + 128) * RSTR * 2)
#define SMEM_H64  (4 * (128 +  64) * RSTR * 2)
#define SMEM_X    (4 * (128 + 64) * SKEWF * 4)

extern "C" void kernel_launch(void* const* d_in, const int* in_sizes, int n_in,
                              void* d_out, int out_size)
{
    const float* hidden      = (const float*)d_in[0];
    const float* in_norm_g   = (const float*)d_in[1];
    const float* in_norm_b   = (const float*)d_in[2];
    const float* ln_g        = (const float*)d_in[3];
    const float* ln_b        = (const float*)d_in[4];
    const float* in_proj_w   = (const float*)d_in[5];
    const float* conv_w      = (const float*)d_in[6];
    const float* conv_b      = (const float*)d_in[7];
    const float* x_proj_w    = (const float*)d_in[8];
    const float* dt_proj_w   = (const float*)d_in[9];
    const float* dt_proj_b   = (const float*)d_in[10];
    const float* Dv          = (const float*)d_in[11];
    const float* mamba_ln_g  = (const float*)d_in[12];
    const float* mamba_ln_b  = (const float*)d_in[13];
    const float* out_proj_w  = (const float*)d_in[14];
    const float* op1_w       = (const float*)d_in[15];
    const float* op1_b       = (const float*)d_in[16];
    const float* op2_w       = (const float*)d_in[17];
    const float* op2_b       = (const float*)d_in[18];

    float *x, *res, *xi, *xi2, *pr, *prp, *y, *wp;
    __half *xnh, *yh, *xh, *t1h, *wih, *woh, *op1h, *op2h;
    cudaGetSymbolAddress((void**)&x,    g_x);
    cudaGetSymbolAddress((void**)&res,  g_res);
    cudaGetSymbolAddress((void**)&xi,   g_xi);
    cudaGetSymbolAddress((void**)&xi2,  g_xi2);
    cudaGetSymbolAddress((void**)&pr,   g_pr);
    cudaGetSymbolAddress((void**)&prp,  g_prp);
    cudaGetSymbolAddress((void**)&y,    g_y);
    cudaGetSymbolAddress((void**)&wp,   g_wp);
    cudaGetSymbolAddress((void**)&xnh,  g_xnh);
    cudaGetSymbolAddress((void**)&yh,   g_yh);
    cudaGetSymbolAddress((void**)&xh,   g_xh);
    cudaGetSymbolAddress((void**)&t1h,  g_t1h);
    cudaGetSymbolAddress((void**)&wih,  g_wih);
    cudaGetSymbolAddress((void**)&woh,  g_woh);
    cudaGetSymbolAddress((void**)&op1h, g_op1h);
    cudaGetSymbolAddress((void**)&op2h, g_op2h);

    cudaFuncSetAttribute(gemm_h<4,128,4>, cudaFuncAttributeMaxDynamicSharedMemorySize, SMEM_H128);
    cudaFuncSetAttribute(gemm_h<1,64,4>,  cudaFuncAttributeMaxDynamicSharedMemorySize, SMEM_H64);
    cudaFuncSetAttribute(gemm_h<2,64,4>,  cudaFuncAttributeMaxDynamicSharedMemorySize, SMEM_H64);
    cudaFuncSetAttribute(gemm_h<3,64,4>,  cudaFuncAttributeMaxDynamicSharedMemorySize, SMEM_H64);
    cudaFuncSetAttribute(xproj_splitk, cudaFuncAttributeMaxDynamicSharedMemorySize, SMEM_X);
    cudaFuncSetAttribute(scan_kernel, cudaFuncAttributeMaxDynamicSharedMemorySize, SCAN_SMEM);

    // fused weight conversion (one launch)
    {
        int n0 = NLAYER * 2 * DI * HID;
        int n1 = NLAYER * HID * DI;
        int n2 = HID * HID;
        int n3 = HID * HID;
        int tot = n0 + n1 + n2 + n3;
        f2h_all<<<(tot + 255) / 256, 256>>>(in_proj_w, wih, n0, out_proj_w, woh, n1,
                                            op1_w, op1h, n2, op2_w, op2h, n3);
    }
    wpad_kernel<<<(NLAYER * 64 * DI + 255) / 256, 256>>>(x_proj_w, wp);

    // x = LN(hidden)  (fp32 residual)
    ln_kernel<false,false><<<ROWS, 256>>>(hidden, in_norm_g, in_norm_b, nullptr, x, HID);

    for (int l = 0; l < NLAYER; l++) {
        // xnh = half(LN(x))
        ln_kernel<false,true><<<ROWS, 256>>>(x, ln_g + (size_t)l * HID, ln_b + (size_t)l * HID,
                                             nullptr, xnh, HID);
        // in_proj: xi = silu(first half), res = second half  (2048x4096x1024 fp16)
        gemm_h<4,128,4><<<dim3(2 * DI / 128, ROWS / 128), 256, SMEM_H128>>>(
            xnh, wih + (size_t)l * 2 * DI * HID, nullptr, res, xi, nullptr, ROWS, 2 * DI, HID);
        // fused conv1+silu+conv2+silu : xi -> xi2
        conv2_kernel<<<(BATCH * DI * (SEQ / CCHUNK)) / 256, 256>>>(
            xi,
            conv_w + (size_t)(l * 2 + 0) * DI * KCONV, conv_b + (size_t)(l * 2 + 0) * DI,
            conv_w + (size_t)(l * 2 + 1) * DI * KCONV, conv_b + (size_t)(l * 2 + 1) * DI,
            xi2);
        // proj partials (split-K over 256 CTAs), then reduce
        xproj_splitk<<<dim3(KSPL, ROWS / 128), 256, SMEM_X>>>(
            xi2, wp + (size_t)l * 64 * DI, prp, DI);
        prred_kernel<<<(ROWS * 64 + 255) / 256, 256>>>(prp, pr);
        // selective scan -> y
        scan_kernel<<<BATCH * (DI / 16), 128, SCAN_SMEM>>>(
            xi2, pr, dt_proj_w + (size_t)l * DI, dt_proj_b + (size_t)l * DI,
            Dv + (size_t)l * DI, y);
        // yh = half(LN(y) * sigmoid(res))
        ln_kernel<true,true><<<ROWS, 256>>>(y, mamba_ln_g + (size_t)l * DI,
                                            mamba_ln_b + (size_t)l * DI, res, yh, DI);
        // x = x + yh @ woh^T  (fp32 out + half copy xh) — 256 CTAs
        gemm_h<1,64,4><<<dim3(HID / 64, ROWS / 128), 256, SMEM_H64>>>(
            yh, woh + (size_t)l * HID * DI, nullptr, x, x, xh, ROWS, HID, DI);
    }

    // t1h = half(gelu(xh @ op1h^T + op1_b)) — 256 CTAs
    gemm_h<2,64,4><<<dim3(HID / 64, ROWS / 128), 256, SMEM_H64>>>(
        xh, op1h, op1_b, nullptr, nullptr, t1h, ROWS, HID, HID);
    // out = t1h @ op2h^T + op2_b + hidden  (fp32) — 256 CTAs
    gemm_h<3,64,4><<<dim3(HID / 64, ROWS / 128), 256, SMEM_H64>>>(
        t1h, op2h, op2_b, (float*)hidden, (float*)d_out, nullptr, ROWS, HID, HID);
}

// round 15
// speedup vs baseline: 1.5627x; 1.0649x over previous
#include <cuda_runtime.h>
#include <cuda_fp16.h>
#include <math.h>
#include <stdint.h>

#define BATCH 2
#define SEQ   1024
#define HID   1024
#define DI    2048
#define NST   16
#define KCONV 4
#define NLAYER 4
#define ROWS  (BATCH*SEQ)      // 2048
#define LN_EPS 1e-5f
#define KSPL  16               // xproj split-K factor

// ---------------- scratch (device globals; no allocation) ----------------
__device__ float g_x  [ROWS*HID];
__device__ float g_res[ROWS*DI];
__device__ float g_xi [ROWS*DI];
__device__ float g_xi2[ROWS*DI];
__device__ float g_pr [ROWS*64];          // padded proj (stride 64, permuted layout)
__device__ float g_prp[KSPL*ROWS*64];     // split-K partials
__device__ float g_y  [ROWS*DI];
__device__ float g_wp [NLAYER*64*DI];     // zero-padded permuted x_proj weights
// half operands
__device__ __half g_xnh [ROWS*HID];
__device__ __half g_yh  [ROWS*DI];
__device__ __half g_xh  [ROWS*HID];
__device__ __half g_t1h [ROWS*HID];
__device__ __half g_wih [NLAYER*2*DI*HID];
__device__ __half g_woh [NLAYER*HID*DI];
__device__ __half g_op1h[HID*HID];
__device__ __half g_op2h[HID*HID];

// ---------------- helpers ----------------
__device__ __forceinline__ float siluf(float v) { return v / (1.f + expf(-v)); }
__device__ __forceinline__ float sigmoidf_(float v) { return 1.f / (1.f + expf(-v)); }
__device__ __forceinline__ float geluf(float v) { return 0.5f * v * (1.f + erff(v * 0.70710678118654752f)); }
__device__ __forceinline__ uint32_t to_tf32u(float x) {
    uint32_t u;
    asm("cvt.rna.tf32.f32 %0, %1;" : "=r"(u) : "f"(x));
    return u;
}
__device__ __forceinline__ uint32_t smem_u32(const void* p) {
    uint32_t a;
    asm("{ .reg .u64 t; cvta.to.shared.u64 t, %1; cvt.u32.u64 %0, t; }" : "=r"(a) : "l"(p));
    return a;
}
__device__ __forceinline__ void cp16(uint32_t d, const void* g) {
    asm volatile("cp.async.cg.shared.global [%0], [%1], 16;" :: "r"(d), "l"(g));
}
__device__ __forceinline__ void ldsm4(uint32_t& r0, uint32_t& r1, uint32_t& r2, uint32_t& r3,
                                      uint32_t a) {
    asm volatile("ldmatrix.sync.aligned.m8n8.x4.shared.b16 {%0,%1,%2,%3}, [%4];"
                 : "=r"(r0), "=r"(r1), "=r"(r2), "=r"(r3) : "r"(a));
}
#define MMA_TF32(acc, a0,a1,a2,a3, b0,b1)                                     \
    asm volatile(                                                             \
        "mma.sync.aligned.m16n8k8.row.col.f32.tf32.tf32.f32 "                 \
        "{%0,%1,%2,%3}, {%4,%5,%6,%7}, {%8,%9}, {%0,%1,%2,%3};"               \
        : "+f"((acc)[0]), "+f"((acc)[1]), "+f"((acc)[2]), "+f"((acc)[3])      \
        : "r"(a0), "r"(a1), "r"(a2), "r"(a3), "r"(b0), "r"(b1))
#define MMA_F16(acc, a0,a1,a2,a3, b0,b1)                                      \
    asm volatile(                                                             \
        "mma.sync.aligned.m16n8k16.row.col.f32.f16.f16.f32 "                  \
        "{%0,%1,%2,%3}, {%4,%5,%6,%7}, {%8,%9}, {%0,%1,%2,%3};"               \
        : "+f"((acc)[0]), "+f"((acc)[1]), "+f"((acc)[2]), "+f"((acc)[3])      \
        : "r"(a0), "r"(a1), "r"(a2), "r"(a3), "r"(b0), "r"(b1))

// ---------------- fused fp32 -> fp16 weight convert ----------------
__global__ void f2h_all(const float* __restrict__ w0, __half* __restrict__ o0, int n0,
                        const float* __restrict__ w1, __half* __restrict__ o1, int n1,
                        const float* __restrict__ w2, __half* __restrict__ o2, int n2,
                        const float* __restrict__ w3, __half* __restrict__ o3, int n3)
{
    int i = blockIdx.x * blockDim.x + threadIdx.x;
    if (i < n0) o0[i] = __float2half_rn(w0[i]);
    i -= n0;
    if (i >= 0 && i < n1) o1[i] = __float2half_rn(w1[i]);
    i -= n1;
    if (i >= 0 && i < n2) o2[i] = __float2half_rn(w2[i]);
    i -= n2;
    if (i >= 0 && i < n3) o3[i] = __float2half_rn(w3[i]);
}

// ---------------- one-pass LayerNorm (gate optional; fp32/fp16 out) ----------------
template<bool GATE, bool OUTH>
__global__ void ln_kernel(const float* __restrict__ in,
                          const float* __restrict__ g,
                          const float* __restrict__ b,
                          const float* __restrict__ gate,
                          void* __restrict__ outv, int cols)
{
    __shared__ float buf[2048];
    __shared__ float red[16];
    __shared__ float s_mu, s_rstd;
    const int row = blockIdx.x;
    const int tid = threadIdx.x;
    const float* pin = in + (size_t)row * cols;

    float s = 0.f, s2 = 0.f;
    for (int c = tid; c < cols; c += 256) {
        float v = pin[c];
        buf[c] = v;
        s += v;
        s2 = fmaf(v, v, s2);
    }
    #pragma unroll
    for (int o = 16; o; o >>= 1) {
        s  += __shfl_xor_sync(0xffffffffu, s,  o);
        s2 += __shfl_xor_sync(0xffffffffu, s2, o);
    }
    if ((tid & 31) == 0) { red[tid >> 5] = s; red[8 + (tid >> 5)] = s2; }
    __syncthreads();
    if (tid == 0) {
        float t = 0.f, t2 = 0.f;
        #pragma unroll
        for (int i = 0; i < 8; i++) { t += red[i]; t2 += red[8 + i]; }
        float mu = t / (float)cols;
        float var = t2 / (float)cols - mu * mu;
        s_mu = mu;
        s_rstd = rsqrtf(var + LN_EPS);
    }
    __syncthreads();
    const float mu = s_mu;
    const float rstd = s_rstd;
    for (int c = tid; c < cols; c += 256) {
        float val = (buf[c] - mu) * rstd * g[c] + b[c];
        if (GATE) val *= sigmoidf_(gate[(size_t)row * cols + c]);
        if (OUTH) ((__half*)outv)[(size_t)row * cols + c] = __float2half_rn(val);
        else      ((float*)outv)[(size_t)row * cols + c] = val;
    }
}

// ---------------- fp16 tensor-core GEMM, 8 warps, ldmatrix, templated TBN ---------
// C = A(MxK) * B(NxK)^T.  128xTBN tile, NSTG-stage cp.async, fp32 accumulate.
// EPI: 1 out_proj (C=resid+acc fp32, Ch=half copy) ; 2 gelu(acc+bias) -> Ch half ;
//      3 acc+bias+resid -> C fp32 ; 4 in_proj split (silu->C fp32 | raw->residF)
#define RSTR 40                             // halves per smem row (32 + 8 skew)

template<int EPI, int TBN, int NSTG>
__global__ __launch_bounds__(256, 2)
void gemm_h(const __half* __restrict__ A, const __half* __restrict__ Bw,
            const float* __restrict__ bias, float* __restrict__ residF,
            float* __restrict__ C, __half* __restrict__ Ch,
            int M, int N, int K)
{
    constexpr int WMW   = (TBN == 128) ? 2 : 4;
    constexpr int MROWS = 128 / WMW;
    constexpr int MT    = MROWS / 16;
    constexpr int ASTG  = 128 * RSTR;
    constexpr int BSTG  = TBN * RSTR;
    constexpr int STG   = ASTG + BSTG;
    extern __shared__ __half smh[];

    const int tid  = threadIdx.x;
    const int lane = tid & 31;
    const int w    = tid >> 5;
    const int wm   = w & (WMW - 1);
    const int wn   = w / WMW;
    const int m0 = blockIdx.y * 128;
    const int n0 = blockIdx.x * TBN;
    const int lq = lane >> 2;
    const int lr = lane & 3;
    const int l7  = lane & 7;
    const int l8  = (lane >> 3) & 1;
    const int l16 = lane >> 4;

    float acc[MT][4][4];
    #pragma unroll
    for (int i = 0; i < MT; i++)
        #pragma unroll
        for (int j = 0; j < 4; j++)
            #pragma unroll
            for (int r = 0; r < 4; r++) acc[i][j][r] = 0.f;

    const int NC = K >> 5;

    auto load_stage = [&](int s, int k0) {
        __half* dA = smh + s * STG;
        __half* dB = dA + ASTG;
        #pragma unroll
        for (int i = 0; i < 2; i++) {
            int slot = tid + i * 256;
            int row = slot >> 2, c = slot & 3;
            cp16(smem_u32(dA + row * RSTR + c * 8), A + (size_t)(m0 + row) * K + k0 + c * 8);
        }
        #pragma unroll
        for (int i = 0; i < TBN * 4 / 256; i++) {
            int slot = tid + i * 256;
            int row = slot >> 2, c = slot & 3;
            cp16(smem_u32(dB + row * RSTR + c * 8), Bw + (size_t)(n0 + row) * K + k0 + c * 8);
        }
        asm volatile("cp.async.commit_group;" ::: "memory");
    };

    #pragma unroll
    for (int c = 0; c < NSTG - 1; c++) load_stage(c, c * 32);

    int s = 0, sl = NSTG - 1;
    for (int c = 0; c < NC; c++) {
        if (c <= NC - NSTG + 1) {
            asm volatile("cp.async.wait_group %0;" :: "n"(NSTG - 2) : "memory");
        } else {
            asm volatile("cp.async.wait_group 0;" ::: "memory");
        }
        __syncthreads();
        if (c + NSTG - 1 < NC) load_stage(sl, (c + NSTG - 1) * 32);

        const __half* sA = smh + s * STG;
        const __half* sB = sA + ASTG;
        #pragma unroll
        for (int kk = 0; kk < 32; kk += 16) {
            uint32_t af[MT][4], bf[4][2];
            #pragma unroll
            for (int mt = 0; mt < MT; mt++) {
                int r = wm * MROWS + mt * 16 + l7 + l8 * 8;
                uint32_t addr = smem_u32(&sA[r * RSTR + kk + l16 * 8]);
                ldsm4(af[mt][0], af[mt][1], af[mt][2], af[mt][3], addr);
            }
            #pragma unroll
            for (int p = 0; p < 2; p++) {
                int rn = wn * 32 + p * 16 + l7 + l16 * 8;
                uint32_t addr = smem_u32(&sB[rn * RSTR + kk + l8 * 8]);
                ldsm4(bf[2 * p][0], bf[2 * p][1], bf[2 * p + 1][0], bf[2 * p + 1][1], addr);
            }
            #pragma unroll
            for (int mt = 0; mt < MT; mt++)
                #pragma unroll
                for (int nt = 0; nt < 4; nt++)
                    MMA_F16(acc[mt][nt], af[mt][0], af[mt][1], af[mt][2], af[mt][3],
                            bf[nt][0], bf[nt][1]);
        }
        if (++s == NSTG) s = 0;
        if (++sl == NSTG) sl = 0;
    }

    #pragma unroll
    for (int mt = 0; mt < MT; mt++)
        #pragma unroll
        for (int nt = 0; nt < 4; nt++) {
            int r0 = m0 + wm * MROWS + mt * 16 + lq;
            int cc = n0 + wn * 32 + nt * 8 + lr * 2;
            #pragma unroll
            for (int half_i = 0; half_i < 2; half_i++) {
                int m = r0 + half_i * 8;
                float v0 = acc[mt][nt][half_i * 2 + 0];
                float v1 = acc[mt][nt][half_i * 2 + 1];
                if (EPI == 1) {
                    float2 rr = *reinterpret_cast<const float2*>(&residF[(size_t)m * N + cc]);
                    float o0 = v0 + rr.x, o1 = v1 + rr.y;
                    *reinterpret_cast<float2*>(&C[(size_t)m * N + cc]) = make_float2(o0, o1);
                    *reinterpret_cast<__half2*>(&Ch[(size_t)m * N + cc]) = __floats2half2_rn(o0, o1);
                } else if (EPI == 2) {
                    *reinterpret_cast<__half2*>(&Ch[(size_t)m * N + cc]) =
                        __floats2half2_rn(geluf(v0 + bias[cc]), geluf(v1 + bias[cc + 1]));
                } else if (EPI == 3) {
                    float2 rr = *reinterpret_cast<const float2*>(&residF[(size_t)m * N + cc]);
                    *reinterpret_cast<float2*>(&C[(size_t)m * N + cc]) =
                        make_float2(v0 + bias[cc] + rr.x, v1 + bias[cc + 1] + rr.y);
                } else {                        // EPI 4
                    if (cc < DI)
                        *reinterpret_cast<float2*>(&C[(size_t)m * DI + cc]) =
                            make_float2(siluf(v0), siluf(v1));
                    else
                        *reinterpret_cast<float2*>(&residF[(size_t)m * DI + cc - DI]) =
                            make_float2(v0, v1);
                }
            }
        }
}

// ---------------- xproj split-K GEMM (tf32, fp32 inputs) ----------------
#define SKEWF 36
__global__ __launch_bounds__(256, 2)
void xproj_splitk(const float* __restrict__ A, const float* __restrict__ Bw,
                  float* __restrict__ Cp, int K)
{
    constexpr int TBN  = 64;
    constexpr int NSTG = 4;
    constexpr int NT   = TBN / 32;
    constexpr int WNC  = TBN / 4;
    constexpr int ASTG = 128 * SKEWF;
    constexpr int BSTG = TBN * SKEWF;
    constexpr int STG  = ASTG + BSTG;
    extern __shared__ float sm[];

    const int tid  = threadIdx.x;
    const int lane = tid & 31;
    const int w    = tid >> 5;
    const int wm   = w & 1;
    const int wn   = w >> 1;
    const int m0 = blockIdx.y * 128;
    const int kz = blockIdx.x;
    const int kbase = kz * (K / KSPL);
    const int lq = lane >> 2;
    const int lr = lane & 3;
    float* C = Cp + (size_t)kz * ROWS * 64;

    float acc[4][NT][4];
    #pragma unroll
    for (int i = 0; i < 4; i++)
        #pragma unroll
        for (int j = 0; j < NT; j++)
            #pragma unroll
            for (int r = 0; r < 4; r++) acc[i][j][r] = 0.f;

    const int NC = (K / KSPL) >> 5;          // 4

    auto load_stage = [&](int s, int k0) {
        float* dA = sm + s * STG;
        float* dB = dA + ASTG;
        #pragma unroll
        for (int i = 0; i < 4; i++) {
            int slot = tid + i * 256;
            int row = slot >> 3, c4 = (slot & 7) * 4;
            cp16(smem_u32(dA + row * SKEWF + c4), A + (size_t)(m0 + row) * K + kbase + k0 + c4);
        }
        #pragma unroll
        for (int i = 0; i < 2; i++) {
            int slot = tid + i * 256;
            int row = slot >> 3, c4 = (slot & 7) * 4;
            cp16(smem_u32(dB + row * SKEWF + c4), Bw + (size_t)row * K + kbase + k0 + c4);
        }
        asm volatile("cp.async.commit_group;" ::: "memory");
    };

    #pragma unroll
    for (int c = 0; c < NSTG - 1; c++) load_stage(c, c * 32);

    int s = 0, sl = NSTG - 1;
    for (int c = 0; c < NC; c++) {
        if (c <= NC - NSTG + 1) {
            asm volatile("cp.async.wait_group %0;" :: "n"(NSTG - 2) : "memory");
        } else {
            asm volatile("cp.async.wait_group 0;" ::: "memory");
        }
        __syncthreads();
        if (c + NSTG - 1 < NC) load_stage(sl, (c + NSTG - 1) * 32);

        const float* sA = sm + s * STG;
        const float* sB = sA + ASTG;
        #pragma unroll
        for (int kk = 0; kk < 32; kk += 8) {
            uint32_t afr[4][4], bfr[NT][2];
            #pragma unroll
            for (int mt = 0; mt < 4; mt++) {
                int r = wm * 64 + mt * 16 + lq;
                afr[mt][0] = to_tf32u(sA[(r    ) * SKEWF + kk     + lr]);
                afr[mt][1] = to_tf32u(sA[(r + 8) * SKEWF + kk     + lr]);
                afr[mt][2] = to_tf32u(sA[(r    ) * SKEWF + kk + 4 + lr]);
                afr[mt][3] = to_tf32u(sA[(r + 8) * SKEWF + kk + 4 + lr]);
            }
            #pragma unroll
            for (int nt = 0; nt < NT; nt++) {
                int rn = wn * WNC + nt * 8 + lq;
                bfr[nt][0] = to_tf32u(sB[rn * SKEWF + kk     + lr]);
                bfr[nt][1] = to_tf32u(sB[rn * SKEWF + kk + 4 + lr]);
            }
            #pragma unroll
            for (int mt = 0; mt < 4; mt++)
                #pragma unroll
                for (int nt = 0; nt < NT; nt++)
                    MMA_TF32(acc[mt][nt], afr[mt][0], afr[mt][1], afr[mt][2], afr[mt][3],
                             bfr[nt][0], bfr[nt][1]);
        }
        if (++s == NSTG) s = 0;
        if (++sl == NSTG) sl = 0;
    }

    #pragma unroll
    for (int mt = 0; mt < 4; mt++)
        #pragma unroll
        for (int nt = 0; nt < NT; nt++) {
            int r0 = m0 + wm * 64 + mt * 16 + lq;
            int cc = wn * WNC + nt * 8 + lr * 2;
            #pragma unroll
            for (int half_i = 0; half_i < 2; half_i++) {
                int m = r0 + half_i * 8;
                *reinterpret_cast<float2*>(&C[(size_t)m * 64 + cc]) =
                    make_float2(acc[mt][nt][half_i * 2 + 0], acc[mt][nt][half_i * 2 + 1]);
            }
        }
}

// ---------------- split-K reduce ----------------
__global__ void prred_kernel(const float* __restrict__ prp, float* __restrict__ pr)
{
    int i = blockIdx.x * blockDim.x + threadIdx.x;
    if (i >= ROWS * 64) return;
    float s = 0.f;
    #pragma unroll
    for (int z = 0; z < KSPL; z++) s += prp[(size_t)z * ROWS * 64 + i];
    pr[i] = s;
}

// ---------------- fused double causal dwconv (K=4) + silu ----------------
#define CCHUNK 8
__global__ void conv2_kernel(const float* __restrict__ in,
                             const float* __restrict__ w1, const float* __restrict__ b1,
                             const float* __restrict__ w2, const float* __restrict__ b2,
                             float* __restrict__ out)
{
    int idx = blockIdx.x * blockDim.x + threadIdx.x;
    if (idx >= BATCH * DI * (SEQ / CCHUNK)) return;
    int d  = idx % DI;
    int r  = idx / DI;
    int c0 = r % (SEQ / CCHUNK);
    int b  = r / (SEQ / CCHUNK);
    int t0 = c0 * CCHUNK;

    const float wa0 = w1[d*4+0], wa1 = w1[d*4+1], wa2 = w1[d*4+2], wa3 = w1[d*4+3];
    const float wb0 = w2[d*4+0], wb1 = w2[d*4+1], wb2 = w2[d*4+2], wb3 = w2[d*4+3];
    const float bb1 = b1[d], bb2 = b2[d];
    const float* pin  = in  + (size_t)b * SEQ * DI + d;
    float*       pout = out + (size_t)b * SEQ * DI + d;

    float h[3];
    #pragma unroll
    for (int j = 0; j < 3; j++) {
        int t = t0 - 3 + j;
        if (t >= 0) {
            float a = bb1;
            float wv[4] = {wa0, wa1, wa2, wa3};
            #pragma unroll
            for (int k = 0; k < 4; k++) {
                int tt = t - 3 + k;
                if (tt >= 0) a = fmaf(pin[(size_t)tt * DI], wv[k], a);
            }
            h[j] = siluf(a);
        } else h[j] = 0.f;
    }
    float xm3 = (t0 - 3 >= 0) ? pin[(size_t)(t0 - 3) * DI] : 0.f;
    float xm2 = (t0 - 2 >= 0) ? pin[(size_t)(t0 - 2) * DI] : 0.f;
    float xm1 = (t0 - 1 >= 0) ? pin[(size_t)(t0 - 1) * DI] : 0.f;

    #pragma unroll
    for (int t = t0; t < t0 + CCHUNK; t++) {
        float xt = pin[(size_t)t * DI];
        float v1 = fmaf(wa0, xm3, bb1);
        v1 = fmaf(wa1, xm2, v1);
        v1 = fmaf(wa2, xm1, v1); v1 = fmaf(wa3, xt,  v1);
        float s = siluf(v1);
        float v2 = fmaf(wb0, h[0], bb2);
        v2 = fmaf(wb1, h[1], v2);
        v2 = fmaf(wb2, h[2], v2); v2 = fmaf(wb3, s,    v2);
        pout[(size_t)t * DI] = siluf(v2);
        xm3 = xm2; xm2 = xm1; xm1 = xt;
        h[0] = h[1]; h[1] = h[2]; h[2] = s;
    }
}

// ---------------- x_proj weight zero-pad, PERMUTED layout -------------------------
// q=0 <- p=0 (dt) ; q in [2,34) <- p=q-1 (B at q=2..17, C at q=18..33) ; else 0.
__global__ void wpad_kernel(const float* __restrict__ W, float* __restrict__ Wp)
{
    int idx = blockIdx.x * blockDim.x + threadIdx.x;
    if (idx >= NLAYER * 64 * DI) return;
    int k = idx % DI;
    int q = (idx / DI) % 64;
    int l = idx / (DI * 64);
    float v = 0.f;
    if (q == 0) v = W[(size_t)l * 33 * DI + k];
    else if (q >= 2 && q < 34) v = W[((size_t)l * 33 + (q - 1)) * DI + k];
    Wp[idx] = v;
}

// ---------------- selective scan: 16 ch/block, 4 subs x 4 states ----------------
#define SCH 64
#define NCHK (SEQ / SCH)
#define SCAN_SMEM ((2*SCH*16 + 2*SCH*64 + SCH*16) * 4)

__global__ __launch_bounds__(64)
void scan_kernel(const float* __restrict__ x, const float* __restrict__ pr,
                 const float* __restrict__ dtw, const float* __restrict__ dtb,
                 const float* __restrict__ Dv, float* __restrict__ y)
{
    extern __shared__ float sm[];
    float* SX = sm;                     // [2][SCH][16]
    float* SP = sm + 2 * SCH * 16;      // [2][SCH][64]
    float* SY = SP + 2 * SCH * 64;      // [SCH][16]

    const int tid = threadIdx.x;        // 64
    const int dd  = tid >> 2;           // 0..15
    const int sub = tid & 3;            // 0..3
    const int nblk = DI / 16;           // 128
    const int b  = blockIdx.x / nblk;
    const int d0 = (blockIdx.x % nblk) * 16;
    const int d  = d0 + dd;

    const float wdt = dtw[d], bdt = dtb[d], Dd = Dv[d];
    const float A0 = -(float)(sub * 4 + 1);
    const float A1 = -(float)(sub * 4 + 2);
    const float A2 = -(float)(sub * 4 + 3);
    const float A3 = -(float)(sub * 4 + 4);
    float h0 = 0.f, h1 = 0.f, h2 = 0.f, h3 = 0.f;

    const float* xg = x + (size_t)b * SEQ * DI + d0;
    const float* pg = pr + (size_t)b * SEQ * 64;
    float*       yg = y + (size_t)b * SEQ * DI + d0;

    auto load_chunk = [&](int buf, int c) {
        int t0 = c * SCH;
        float* dx = SX + buf * SCH * 16;
        float* dp = SP + buf * SCH * 64;
        #pragma unroll
        for (int i = 0; i < 4; i++) {              // SX: 256 slots
            int slv = tid + i * 64;
            int t = slv >> 2, ch = slv & 3;
            cp16(smem_u32(dx + t * 16 + ch * 4), xg + (size_t)(t0 + t) * DI + ch * 4);
        }
        #pragma unroll
        for (int i = 0; i < 16; i++) {             // SP: 1024 slots
            int slv = tid + i * 64;
            int t = slv >> 4, ch = slv & 15;
            cp16(smem_u32(dp + t * 64 + ch * 4), pg + (size_t)(t0 + t) * 64 + ch * 4);
        }
        asm volatile("cp.async.commit_group;" ::: "memory");
    };

    load_chunk(0, 0);
    load_chunk(1, 1);

    for (int c = 0; c < NCHK; c++) {
        const int buf = c & 1;
        if (c + 1 < NCHK) asm volatile("cp.async.wait_group 1;" ::: "memory");
        else              asm volatile("cp.async.wait_group 0;" ::: "memory");
        __syncthreads();

        const float* cx = SX + buf * SCH * 16;
        const float* cp = SP + buf * SCH * 64;
        #pragma unroll 4
        for (int s = 0; s < SCH; s++) {
            float dtraw = cp[s * 64];
            float xv    = cx[s * 16 + dd];
            float2 b01 = *reinterpret_cast<const float2*>(&cp[s * 64 + 2  + 4 * sub]);
            float2 b23 = *reinterpret_cast<const float2*>(&cp[s * 64 + 4  + 4 * sub]);
            float2 c01 = *reinterpret_cast<const float2*>(&cp[s * 64 + 18 + 4 * sub]);
            float2 c23 = *reinterpret_cast<const float2*>(&cp[s * 64 + 20 + 4 * sub]);
            float z  = fmaf(dtraw, wdt, bdt);
            float dt = (z > 20.f) ? z : log1pf(expf(z));
            float dtx = dt * xv;
            float t0v = fmaf(h0, A0, dtx * b01.x); h0 = fmaf(dt, t0v, h0);
            float t1v = fmaf(h1, A1, dtx * b01.y); h1 = fmaf(dt, t1v, h1);
            float t2v = fmaf(h2, A2, dtx * b23.x); h2 = fmaf(dt, t2v, h2);
            float t3v = fmaf(h3, A3, dtx * b23.y); h3 = fmaf(dt, t3v, h3);
            float yp = h0 * c01.x;
            yp = fmaf(h1, c01.y, yp);
            yp = fmaf(h2, c23.x, yp);
            yp = fmaf(h3, c23.y, yp);
            yp += __shfl_xor_sync(0xffffffffu, yp, 1);
            yp += __shfl_xor_sync(0xffffffffu, yp, 2);
            if (sub == 0) SY[s * 16 + dd] = fmaf(xv, Dd, yp);
        }
        __syncthreads();

        const int t0 = c * SCH;
        #pragma unroll
        for (int i = 0; i < 16; i++) {
            int slv = tid + i * 64;
            int s = slv >> 4, dd2 = slv & 15;
            yg[(size_t)(t0 + s) * DI + dd2] = SY[s * 16 + dd2];
        }
        if (c + 2 < NCHK) load_chunk(buf, c + 2);
    }
}

// ---------------- host orchestration ----------------
#define SMEM_H128 (4 * (128 + 128) * RSTR * 2)
#define SMEM_H64  (4 * (128 +  64) * RSTR * 2)
#define SMEM_X    (4 * (128 + 64) * SKEWF * 4)

extern "C" void kernel_launch(void* const* d_in, const int* in_sizes, int n_in,
                              void* d_out, int out_size)
{
    const float* hidden      = (const float*)d_in[0];
    const float* in_norm_g   = (const float*)d_in[1];
    const float* in_norm_b   = (const float*)d_in[2];
    const float* ln_g        = (const float*)d_in[3];
    const float* ln_b        = (const float*)d_in[4];
    const float* in_proj_w   = (const float*)d_in[5];
    const float* conv_w      = (const float*)d_in[6];
    const float* conv_b      = (const float*)d_in[7];
    const float* x_proj_w    = (const float*)d_in[8];
    const float* dt_proj_w   = (const float*)d_in[9];
    const float* dt_proj_b   = (const float*)d_in[10];
    const float* Dv          = (const float*)d_in[11];
    const float* mamba_ln_g  = (const float*)d_in[12];
    const float* mamba_ln_b  = (const float*)d_in[13];
    const float* out_proj_w  = (const float*)d_in[14];
    const float* op1_w       = (const float*)d_in[15];
    const float* op1_b       = (const float*)d_in[16];
    const float* op2_w       = (const float*)d_in[17];
    const float* op2_b       = (const float*)d_in[18];

    float *x, *res, *xi, *xi2, *pr, *prp, *y, *wp;
    __half *xnh, *yh, *xh, *t1h, *wih, *woh, *op1h, *op2h;
    cudaGetSymbolAddress((void**)&x,    g_x);
    cudaGetSymbolAddress((void**)&res,  g_res);
    cudaGetSymbolAddress((void**)&xi,   g_xi);
    cudaGetSymbolAddress((void**)&xi2,  g_xi2);
    cudaGetSymbolAddress((void**)&pr,   g_pr);
    cudaGetSymbolAddress((void**)&prp,  g_prp);
    cudaGetSymbolAddress((void**)&y,    g_y);
    cudaGetSymbolAddress((void**)&wp,   g_wp);
    cudaGetSymbolAddress((void**)&xnh,  g_xnh);
    cudaGetSymbolAddress((void**)&yh,   g_yh);
    cudaGetSymbolAddress((void**)&xh,   g_xh);
    cudaGetSymbolAddress((void**)&t1h,  g_t1h);
    cudaGetSymbolAddress((void**)&wih,  g_wih);
    cudaGetSymbolAddress((void**)&woh,  g_woh);
    cudaGetSymbolAddress((void**)&op1h, g_op1h);
    cudaGetSymbolAddress((void**)&op2h, g_op2h);

    cudaFuncSetAttribute(gemm_h<4,128,4>, cudaFuncAttributeMaxDynamicSharedMemorySize, SMEM_H128);
    cudaFuncSetAttribute(gemm_h<1,64,4>,  cudaFuncAttributeMaxDynamicSharedMemorySize, SMEM_H64);
    cudaFuncSetAttribute(gemm_h<2,64,4>,  cudaFuncAttributeMaxDynamicSharedMemorySize, SMEM_H64);
    cudaFuncSetAttribute(gemm_h<3,64,4>,  cudaFuncAttributeMaxDynamicSharedMemorySize, SMEM_H64);
    cudaFuncSetAttribute(xproj_splitk, cudaFuncAttributeMaxDynamicSharedMemorySize, SMEM_X);
    cudaFuncSetAttribute(scan_kernel, cudaFuncAttributeMaxDynamicSharedMemorySize, SCAN_SMEM);

    // fused weight conversion (one launch)
    {
        int n0 = NLAYER * 2 * DI * HID;
        int n1 = NLAYER * HID * DI;
        int n2 = HID * HID;
        int n3 = HID * HID;
        int tot = n0 + n1 + n2 + n3;
        f2h_all<<<(tot + 255) / 256, 256>>>(in_proj_w, wih, n0, out_proj_w, woh, n1,
                                            op1_w, op1h, n2, op2_w, op2h, n3);
    }
    wpad_kernel<<<(NLAYER * 64 * DI + 255) / 256, 256>>>(x_proj_w, wp);

    // x = LN(hidden)  (fp32 residual)
    ln_kernel<false,false><<<ROWS, 256>>>(hidden, in_norm_g, in_norm_b, nullptr, x, HID);

    for (int l = 0; l < NLAYER; l++) {
        // xnh = half(LN(x))
        ln_kernel<false,true><<<ROWS, 256>>>(x, ln_g + (size_t)l * HID, ln_b + (size_t)l * HID,
                                             nullptr, xnh, HID);
        // in_proj: xi = silu(first half), res = second half  (2048x4096x1024 fp16)
        gemm_h<4,128,4><<<dim3(2 * DI / 128, ROWS / 128), 256, SMEM_H128>>>(
            xnh, wih + (size_t)l * 2 * DI * HID, nullptr, res, xi, nullptr, ROWS, 2 * DI, HID);
        // fused conv1+silu+conv2+silu : xi -> xi2
        conv2_kernel<<<(BATCH * DI * (SEQ / CCHUNK)) / 256, 256>>>(
            xi,
            conv_w + (size_t)(l * 2 + 0) * DI * KCONV, conv_b + (size_t)(l * 2 + 0) * DI,
            conv_w + (size_t)(l * 2 + 1) * DI * KCONV, conv_b + (size_t)(l * 2 + 1) * DI,
            xi2);
        // proj partials (split-K over 256 CTAs), then reduce
        xproj_splitk<<<dim3(KSPL, ROWS / 128), 256, SMEM_X>>>(
            xi2, wp + (size_t)l * 64 * DI, prp, DI);
        prred_kernel<<<(ROWS * 64 + 255) / 256, 256>>>(prp, pr);
        // selective scan -> y
        scan_kernel<<<BATCH * (DI / 16), 64, SCAN_SMEM>>>(
            xi2, pr, dt_proj_w + (size_t)l * DI, dt_proj_b + (size_t)l * DI,
            Dv + (size_t)l * DI, y);
        // yh = half(LN(y) * sigmoid(res))
        ln_kernel<true,true><<<ROWS, 256>>>(y, mamba_ln_g + (size_t)l * DI,
                                            mamba_ln_b + (size_t)l * DI, res, yh, DI);
        // x = x + yh @ woh^T  (fp32 out + half copy xh) — 256 CTAs
        gemm_h<1,64,4><<<dim3(HID / 64, ROWS / 128), 256, SMEM_H64>>>(
            yh, woh + (size_t)l * HID * DI, nullptr, x, x, xh, ROWS, HID, DI);
    }

    // t1h = half(gelu(xh @ op1h^T + op1_b)) — 256 CTAs
    gemm_h<2,64,4><<<dim3(HID / 64, ROWS / 128), 256, SMEM_H64>>>(
        xh, op1h, op1_b, nullptr, nullptr, t1h, ROWS, HID, HID);
    // out = t1h @ op2h^T + op2_b + hidden  (fp32) — 256 CTAs
    gemm_h<3,64,4><<<dim3(HID / 64, ROWS / 128), 256, SMEM_H64>>>(
        t1h, op2h, op2_b, (float*)hidden, (float*)d_out, nullptr, ROWS, HID, HID);
}

// round 16
// speedup vs baseline: 1.5769x; 1.0091x over previous
#include <cuda_runtime.h>
#include <cuda_fp16.h>
#include <math.h>
#include <stdint.h>

#define BATCH 2
#define SEQ   1024
#define HID   1024
#define DI    2048
#define NST   16
#define KCONV 4
#define NLAYER 4
#define ROWS  (BATCH*SEQ)      // 2048
#define LN_EPS 1e-5f
#define KSPL  16               // xproj split-K factor

// ---------------- scratch (device globals; no allocation) ----------------
__device__ float g_x  [ROWS*HID];
__device__ float g_res[ROWS*DI];
__device__ float g_xi [ROWS*DI];
__device__ float g_xi2[ROWS*DI];
__device__ float g_pr [ROWS*64];          // padded proj (stride 64, permuted layout)
__device__ float g_prp[KSPL*ROWS*64];     // split-K partials
__device__ float g_y  [ROWS*DI];
// half operands
__device__ __half g_xi2h[ROWS*DI];        // half copy of conv output (xproj A)
__device__ __half g_wph [NLAYER*64*DI];   // zero-padded permuted x_proj weights (half)
__device__ __half g_xnh [ROWS*HID];
__device__ __half g_yh  [ROWS*DI];
__device__ __half g_xh  [ROWS*HID];
__device__ __half g_t1h [ROWS*HID];
__device__ __half g_wih [NLAYER*2*DI*HID];
__device__ __half g_woh [NLAYER*HID*DI];
__device__ __half g_op1h[HID*HID];
__device__ __half g_op2h[HID*HID];

// ---------------- helpers ----------------
__device__ __forceinline__ float siluf(float v) { return v / (1.f + expf(-v)); }
__device__ __forceinline__ float sigmoidf_(float v) { return 1.f / (1.f + expf(-v)); }
__device__ __forceinline__ float geluf(float v) { return 0.5f * v * (1.f + erff(v * 0.70710678118654752f)); }
__device__ __forceinline__ uint32_t smem_u32(const void* p) {
    uint32_t a;
    asm("{ .reg .u64 t; cvta.to.shared.u64 t, %1; cvt.u32.u64 %0, t; }" : "=r"(a) : "l"(p));
    return a;
}
__device__ __forceinline__ void cp16(uint32_t d, const void* g) {
    asm volatile("cp.async.cg.shared.global [%0], [%1], 16;" :: "r"(d), "l"(g));
}
__device__ __forceinline__ void ldsm4(uint32_t& r0, uint32_t& r1, uint32_t& r2, uint32_t& r3,
                                      uint32_t a) {
    asm volatile("ldmatrix.sync.aligned.m8n8.x4.shared.b16 {%0,%1,%2,%3}, [%4];"
                 : "=r"(r0), "=r"(r1), "=r"(r2), "=r"(r3) : "r"(a));
}
#define MMA_F16(acc, a0,a1,a2,a3, b0,b1)                                      \
    asm volatile(                                                             \
        "mma.sync.aligned.m16n8k16.row.col.f32.f16.f16.f32 "                  \
        "{%0,%1,%2,%3}, {%4,%5,%6,%7}, {%8,%9}, {%0,%1,%2,%3};"               \
        : "+f"((acc)[0]), "+f"((acc)[1]), "+f"((acc)[2]), "+f"((acc)[3])      \
        : "r"(a0), "r"(a1), "r"(a2), "r"(a3), "r"(b0), "r"(b1))

// ---------------- fused fp32 -> fp16 weight convert ----------------
__global__ void f2h_all(const float* __restrict__ w0, __half* __restrict__ o0, int n0,
                        const float* __restrict__ w1, __half* __restrict__ o1, int n1,
                        const float* __restrict__ w2, __half* __restrict__ o2, int n2,
                        const float* __restrict__ w3, __half* __restrict__ o3, int n3)
{
    int i = blockIdx.x * blockDim.x + threadIdx.x;
    if (i < n0) o0[i] = __float2half_rn(w0[i]);
    i -= n0;
    if (i >= 0 && i < n1) o1[i] = __float2half_rn(w1[i]);
    i -= n1;
    if (i >= 0 && i < n2) o2[i] = __float2half_rn(w2[i]);
    i -= n2;
    if (i >= 0 && i < n3) o3[i] = __float2half_rn(w3[i]);
}

// ---------------- one-pass LayerNorm (gate optional; fp32/fp16 out) ----------------
template<bool GATE, bool OUTH>
__global__ void ln_kernel(const float* __restrict__ in,
                          const float* __restrict__ g,
                          const float* __restrict__ b,
                          const float* __restrict__ gate,
                          void* __restrict__ outv, int cols)
{
    __shared__ float buf[2048];
    __shared__ float red[16];
    __shared__ float s_mu, s_rstd;
    const int row = blockIdx.x;
    const int tid = threadIdx.x;
    const float* pin = in + (size_t)row * cols;

    float s = 0.f, s2 = 0.f;
    for (int c = tid; c < cols; c += 256) {
        float v = pin[c];
        buf[c] = v;
        s += v;
        s2 = fmaf(v, v, s2);
    }
    #pragma unroll
    for (int o = 16; o; o >>= 1) {
        s  += __shfl_xor_sync(0xffffffffu, s,  o);
        s2 += __shfl_xor_sync(0xffffffffu, s2, o);
    }
    if ((tid & 31) == 0) { red[tid >> 5] = s; red[8 + (tid >> 5)] = s2; }
    __syncthreads();
    if (tid == 0) {
        float t = 0.f, t2 = 0.f;
        #pragma unroll
        for (int i = 0; i < 8; i++) { t += red[i]; t2 += red[8 + i]; }
        float mu = t / (float)cols;
        float var = t2 / (float)cols - mu * mu;
        s_mu = mu;
        s_rstd = rsqrtf(var + LN_EPS);
    }
    __syncthreads();
    const float mu = s_mu;
    const float rstd = s_rstd;
    for (int c = tid; c < cols; c += 256) {
        float val = (buf[c] - mu) * rstd * g[c] + b[c];
        if (GATE) val *= sigmoidf_(gate[(size_t)row * cols + c]);
        if (OUTH) ((__half*)outv)[(size_t)row * cols + c] = __float2half_rn(val);
        else      ((float*)outv)[(size_t)row * cols + c] = val;
    }
}

// ---------------- fp16 tensor-core GEMM, 8 warps, ldmatrix, templated TBN ---------
// C = A(MxK) * B(NxK)^T.  128xTBN tile, NSTG-stage cp.async, fp32 accumulate.
// EPI: 1 out_proj (C=resid+acc fp32, Ch=half copy) ; 2 gelu(acc+bias) -> Ch half ;
//      3 acc+bias+resid -> C fp32 ; 4 in_proj split (silu->C fp32 | raw->residF)
#define RSTR 40                             // halves per smem row (32 + 8 skew)

template<int EPI, int TBN, int NSTG>
__global__ __launch_bounds__(256, 2)
void gemm_h(const __half* __restrict__ A, const __half* __restrict__ Bw,
            const float* __restrict__ bias, float* __restrict__ residF,
            float* __restrict__ C, __half* __restrict__ Ch,
            int M, int N, int K)
{
    constexpr int WMW   = (TBN == 128) ? 2 : 4;
    constexpr int MROWS = 128 / WMW;
    constexpr int MT    = MROWS / 16;
    constexpr int ASTG  = 128 * RSTR;
    constexpr int BSTG  = TBN * RSTR;
    constexpr int STG   = ASTG + BSTG;
    extern __shared__ __half smh[];

    const int tid  = threadIdx.x;
    const int lane = tid & 31;
    const int w    = tid >> 5;
    const int wm   = w & (WMW - 1);
    const int wn   = w / WMW;
    const int m0 = blockIdx.y * 128;
    const int n0 = blockIdx.x * TBN;
    const int lq = lane >> 2;
    const int lr = lane & 3;
    const int l7  = lane & 7;
    const int l8  = (lane >> 3) & 1;
    const int l16 = lane >> 4;

    float acc[MT][4][4];
    #pragma unroll
    for (int i = 0; i < MT; i++)
        #pragma unroll
        for (int j = 0; j < 4; j++)
            #pragma unroll
            for (int r = 0; r < 4; r++) acc[i][j][r] = 0.f;

    const int NC = K >> 5;

    auto load_stage = [&](int s, int k0) {
        __half* dA = smh + s * STG;
        __half* dB = dA + ASTG;
        #pragma unroll
        for (int i = 0; i < 2; i++) {
            int slot = tid + i * 256;
            int row = slot >> 2, c = slot & 3;
            cp16(smem_u32(dA + row * RSTR + c * 8), A + (size_t)(m0 + row) * K + k0 + c * 8);
        }
        #pragma unroll
        for (int i = 0; i < TBN * 4 / 256; i++) {
            int slot = tid + i * 256;
            int row = slot >> 2, c = slot & 3;
            cp16(smem_u32(dB + row * RSTR + c * 8), Bw + (size_t)(n0 + row) * K + k0 + c * 8);
        }
        asm volatile("cp.async.commit_group;" ::: "memory");
    };

    #pragma unroll
    for (int c = 0; c < NSTG - 1; c++) load_stage(c, c * 32);

    int s = 0, sl = NSTG - 1;
    for (int c = 0; c < NC; c++) {
        if (c <= NC - NSTG + 1) {
            asm volatile("cp.async.wait_group %0;" :: "n"(NSTG - 2) : "memory");
        } else {
            asm volatile("cp.async.wait_group 0;" ::: "memory");
        }
        __syncthreads();
        if (c + NSTG - 1 < NC) load_stage(sl, (c + NSTG - 1) * 32);

        const __half* sA = smh + s * STG;
        const __half* sB = sA + ASTG;
        #pragma unroll
        for (int kk = 0; kk < 32; kk += 16) {
            uint32_t af[MT][4], bf[4][2];
            #pragma unroll
            for (int mt = 0; mt < MT; mt++) {
                int r = wm * MROWS + mt * 16 + l7 + l8 * 8;
                uint32_t addr = smem_u32(&sA[r * RSTR + kk + l16 * 8]);
                ldsm4(af[mt][0], af[mt][1], af[mt][2], af[mt][3], addr);
            }
            #pragma unroll
            for (int p = 0; p < 2; p++) {
                int rn = wn * 32 + p * 16 + l7 + l16 * 8;
                uint32_t addr = smem_u32(&sB[rn * RSTR + kk + l8 * 8]);
                ldsm4(bf[2 * p][0], bf[2 * p][1], bf[2 * p + 1][0], bf[2 * p + 1][1], addr);
            }
            #pragma unroll
            for (int mt = 0; mt < MT; mt++)
                #pragma unroll
                for (int nt = 0; nt < 4; nt++)
                    MMA_F16(acc[mt][nt], af[mt][0], af[mt][1], af[mt][2], af[mt][3],
                            bf[nt][0], bf[nt][1]);
        }
        if (++s == NSTG) s = 0;
        if (++sl == NSTG) sl = 0;
    }

    #pragma unroll
    for (int mt = 0; mt < MT; mt++)
        #pragma unroll
        for (int nt = 0; nt < 4; nt++) {
            int r0 = m0 + wm * MROWS + mt * 16 + lq;
            int cc = n0 + wn * 32 + nt * 8 + lr * 2;
            #pragma unroll
            for (int half_i = 0; half_i < 2; half_i++) {
                int m = r0 + half_i * 8;
                float v0 = acc[mt][nt][half_i * 2 + 0];
                float v1 = acc[mt][nt][half_i * 2 + 1];
                if (EPI == 1) {
                    float2 rr = *reinterpret_cast<const float2*>(&residF[(size_t)m * N + cc]);
                    float o0 = v0 + rr.x, o1 = v1 + rr.y;
                    *reinterpret_cast<float2*>(&C[(size_t)m * N + cc]) = make_float2(o0, o1);
                    *reinterpret_cast<__half2*>(&Ch[(size_t)m * N + cc]) = __floats2half2_rn(o0, o1);
                } else if (EPI == 2) {
                    *reinterpret_cast<__half2*>(&Ch[(size_t)m * N + cc]) =
                        __floats2half2_rn(geluf(v0 + bias[cc]), geluf(v1 + bias[cc + 1]));
                } else if (EPI == 3) {
                    float2 rr = *reinterpret_cast<const float2*>(&residF[(size_t)m * N + cc]);
                    *reinterpret_cast<float2*>(&C[(size_t)m * N + cc]) =
                        make_float2(v0 + bias[cc] + rr.x, v1 + bias[cc + 1] + rr.y);
                } else {                        // EPI 4
                    if (cc < DI)
                        *reinterpret_cast<float2*>(&C[(size_t)m * DI + cc]) =
                            make_float2(siluf(v0), siluf(v1));
                    else
                        *reinterpret_cast<float2*>(&residF[(size_t)m * DI + cc - DI]) =
                            make_float2(v0, v1);
                }
            }
        }
}

// ---------------- xproj split-K GEMM, fp16 (A=xi2h, B=wph) ----------------
// 128x64 tile, K-chunk = K/KSPL, 4-stage, fp32 partials to Cp[kz].
__global__ __launch_bounds__(256, 2)
void xproj_splitk_h(const __half* __restrict__ A, const __half* __restrict__ Bw,
                    float* __restrict__ Cp, int K)
{
    constexpr int NSTG = 4;
    constexpr int ASTG = 128 * RSTR;
    constexpr int BSTG = 64 * RSTR;
    constexpr int STG  = ASTG + BSTG;
    extern __shared__ __half smh[];

    const int tid  = threadIdx.x;           // 256
    const int lane = tid & 31;
    const int w    = tid >> 5;
    const int wm   = w & 3;                  // 4 warps in M (32 rows each)
    const int wn   = w >> 2;                 // 2 warps in N (32 cols each)
    const int m0 = blockIdx.y * 128;
    const int kz = blockIdx.x;
    const int kbase = kz * (K / KSPL);
    const int lq = lane >> 2;
    const int lr = lane & 3;
    const int l7  = lane & 7;
    const int l8  = (lane >> 3) & 1;
    const int l16 = lane >> 4;
    float* C = Cp + (size_t)kz * ROWS * 64;

    float acc[2][4][4];
    #pragma unroll
    for (int i = 0; i < 2; i++)
        #pragma unroll
        for (int j = 0; j < 4; j++)
            #pragma unroll
            for (int r = 0; r < 4; r++) acc[i][j][r] = 0.f;

    const int NC = (K / KSPL) >> 5;          // 4

    auto load_stage = [&](int s, int k0) {
        __half* dA = smh + s * STG;
        __half* dB = dA + ASTG;
        #pragma unroll
        for (int i = 0; i < 2; i++) {                 // A: 512 slots
            int slot = tid + i * 256;
            int row = slot >> 2, c = slot & 3;
            cp16(smem_u32(dA + row * RSTR + c * 8), A + (size_t)(m0 + row) * K + kbase + k0 + c * 8);
        }
        {                                             // B: 256 slots
            int row = tid >> 2, c = tid & 3;
            cp16(smem_u32(dB + row * RSTR + c * 8), Bw + (size_t)row * K + kbase + k0 + c * 8);
        }
        asm volatile("cp.async.commit_group;" ::: "memory");
    };

    #pragma unroll
    for (int c = 0; c < NSTG - 1; c++) load_stage(c, c * 32);

    int s = 0, sl = NSTG - 1;
    for (int c = 0; c < NC; c++) {
        if (c <= NC - NSTG + 1) {
            asm volatile("cp.async.wait_group %0;" :: "n"(NSTG - 2) : "memory");
        } else {
            asm volatile("cp.async.wait_group 0;" ::: "memory");
        }
        __syncthreads();
        if (c + NSTG - 1 < NC) load_stage(sl, (c + NSTG - 1) * 32);

        const __half* sA = smh + s * STG;
        const __half* sB = sA + ASTG;
        #pragma unroll
        for (int kk = 0; kk < 32; kk += 16) {
            uint32_t af[2][4], bf[4][2];
            #pragma unroll
            for (int mt = 0; mt < 2; mt++) {
                int r = wm * 32 + mt * 16 + l7 + l8 * 8;
                uint32_t addr = smem_u32(&sA[r * RSTR + kk + l16 * 8]);
                ldsm4(af[mt][0], af[mt][1], af[mt][2], af[mt][3], addr);
            }
            #pragma unroll
            for (int p = 0; p < 2; p++) {
                int rn = wn * 32 + p * 16 + l7 + l16 * 8;
                uint32_t addr = smem_u32(&sB[rn * RSTR + kk + l8 * 8]);
                ldsm4(bf[2 * p][0], bf[2 * p][1], bf[2 * p + 1][0], bf[2 * p + 1][1], addr);
            }
            #pragma unroll
            for (int mt = 0; mt < 2; mt++)
                #pragma unroll
                for (int nt = 0; nt < 4; nt++)
                    MMA_F16(acc[mt][nt], af[mt][0], af[mt][1], af[mt][2], af[mt][3],
                            bf[nt][0], bf[nt][1]);
        }
        if (++s == NSTG) s = 0;
        if (++sl == NSTG) sl = 0;
    }

    #pragma unroll
    for (int mt = 0; mt < 2; mt++)
        #pragma unroll
        for (int nt = 0; nt < 4; nt++) {
            int r0 = m0 + wm * 32 + mt * 16 + lq;
            int cc = wn * 32 + nt * 8 + lr * 2;
            #pragma unroll
            for (int half_i = 0; half_i < 2; half_i++) {
                int m = r0 + half_i * 8;
                *reinterpret_cast<float2*>(&C[(size_t)m * 64 + cc]) =
                    make_float2(acc[mt][nt][half_i * 2 + 0], acc[mt][nt][half_i * 2 + 1]);
            }
        }
}

// ---------------- split-K reduce ----------------
__global__ void prred_kernel(const float* __restrict__ prp, float* __restrict__ pr)
{
    int i = blockIdx.x * blockDim.x + threadIdx.x;
    if (i >= ROWS * 64) return;
    float s = 0.f;
    #pragma unroll
    for (int z = 0; z < KSPL; z++) s += prp[(size_t)z * ROWS * 64 + i];
    pr[i] = s;
}

// ---------------- fused double causal dwconv (K=4) + silu, dual output -----------
#define CCHUNK 8
__global__ void conv2_kernel(const float* __restrict__ in,
                             const float* __restrict__ w1, const float* __restrict__ b1,
                             const float* __restrict__ w2, const float* __restrict__ b2,
                             float* __restrict__ out, __half* __restrict__ outh)
{
    int idx = blockIdx.x * blockDim.x + threadIdx.x;
    if (idx >= BATCH * DI * (SEQ / CCHUNK)) return;
    int d  = idx % DI;
    int r  = idx / DI;
    int c0 = r % (SEQ / CCHUNK);
    int b  = r / (SEQ / CCHUNK);
    int t0 = c0 * CCHUNK;

    const float wa0 = w1[d*4+0], wa1 = w1[d*4+1], wa2 = w1[d*4+2], wa3 = w1[d*4+3];
    const float wb0 = w2[d*4+0], wb1 = w2[d*4+1], wb2 = w2[d*4+2], wb3 = w2[d*4+3];
    const float bb1 = b1[d], bb2 = b2[d];
    const float* pin  = in  + (size_t)b * SEQ * DI + d;
    float*       pout = out + (size_t)b * SEQ * DI + d;
    __half*      ph   = outh + (size_t)b * SEQ * DI + d;

    float h[3];
    #pragma unroll
    for (int j = 0; j < 3; j++) {
        int t = t0 - 3 + j;
        if (t >= 0) {
            float a = bb1;
            float wv[4] = {wa0, wa1, wa2, wa3};
            #pragma unroll
            for (int k = 0; k < 4; k++) {
                int tt = t - 3 + k;
                if (tt >= 0) a = fmaf(pin[(size_t)tt * DI], wv[k], a);
            }
            h[j] = siluf(a);
        } else h[j] = 0.f;
    }
    float xm3 = (t0 - 3 >= 0) ? pin[(size_t)(t0 - 3) * DI] : 0.f;
    float xm2 = (t0 - 2 >= 0) ? pin[(size_t)(t0 - 2) * DI] : 0.f;
    float xm1 = (t0 - 1 >= 0) ? pin[(size_t)(t0 - 1) * DI] : 0.f;

    #pragma unroll
    for (int t = t0; t < t0 + CCHUNK; t++) {
        float xt = pin[(size_t)t * DI];
        float v1 = fmaf(wa0, xm3, bb1);
        v1 = fmaf(wa1, xm2, v1);
        v1 = fmaf(wa2, xm1, v1); v1 = fmaf(wa3, xt,  v1);
        float s = siluf(v1);
        float v2 = fmaf(wb0, h[0], bb2);
        v2 = fmaf(wb1, h[1], v2);
        v2 = fmaf(wb2, h[2], v2); v2 = fmaf(wb3, s,    v2);
        float o = siluf(v2);
        pout[(size_t)t * DI] = o;
        ph[(size_t)t * DI] = __float2half_rn(o);
        xm3 = xm2; xm2 = xm1; xm1 = xt;
        h[0] = h[1]; h[1] = h[2]; h[2] = s;
    }
}

// ---------------- x_proj weight zero-pad, PERMUTED, half output -------------------
// q=0 <- p=0 (dt) ; q in [2,34) <- p=q-1 (B at 2..17, C at 18..33) ; else 0.
__global__ void wpad_kernel(const float* __restrict__ W, __half* __restrict__ Wp)
{
    int idx = blockIdx.x * blockDim.x + threadIdx.x;
    if (idx >= NLAYER * 64 * DI) return;
    int k = idx % DI;
    int q = (idx / DI) % 64;
    int l = idx / (DI * 64);
    float v = 0.f;
    if (q == 0) v = W[(size_t)l * 33 * DI + k];
    else if (q >= 2 && q < 34) v = W[((size_t)l * 33 + (q - 1)) * DI + k];
    Wp[idx] = __float2half_rn(v);
}

// ---------------- selective scan: 16 ch/block, 4 subs x 4 states ----------------
#define SCH 64
#define NCHK (SEQ / SCH)
#define SCAN_SMEM ((2*SCH*16 + 2*SCH*64 + SCH*16) * 4)

__global__ __launch_bounds__(64)
void scan_kernel(const float* __restrict__ x, const float* __restrict__ pr,
                 const float* __restrict__ dtw, const float* __restrict__ dtb,
                 const float* __restrict__ Dv, float* __restrict__ y)
{
    extern __shared__ float sm[];
    float* SX = sm;                     // [2][SCH][16]
    float* SP = sm + 2 * SCH * 16;      // [2][SCH][64]
    float* SY = SP + 2 * SCH * 64;      // [SCH][16]

    const int tid = threadIdx.x;        // 64
    const int dd  = tid >> 2;           // 0..15
    const int sub = tid & 3;            // 0..3
    const int nblk = DI / 16;           // 128
    const int b  = blockIdx.x / nblk;
    const int d0 = (blockIdx.x % nblk) * 16;
    const int d  = d0 + dd;

    const float wdt = dtw[d], bdt = dtb[d], Dd = Dv[d];
    const float A0 = -(float)(sub * 4 + 1);
    const float A1 = -(float)(sub * 4 + 2);
    const float A2 = -(float)(sub * 4 + 3);
    const float A3 = -(float)(sub * 4 + 4);
    float h0 = 0.f, h1 = 0.f, h2 = 0.f, h3 = 0.f;

    const float* xg = x + (size_t)b * SEQ * DI + d0;
    const float* pg = pr + (size_t)b * SEQ * 64;
    float*       yg = y + (size_t)b * SEQ * DI + d0;

    auto load_chunk = [&](int buf, int c) {
        int t0 = c * SCH;
        float* dx = SX + buf * SCH * 16;
        float* dp = SP + buf * SCH * 64;
        #pragma unroll
        for (int i = 0; i < 4; i++) {
            int slv = tid + i * 64;
            int t = slv >> 2, ch = slv & 3;
            cp16(smem_u32(dx + t * 16 + ch * 4), xg + (size_t)(t0 + t) * DI + ch * 4);
        }
        #pragma unroll
        for (int i = 0; i < 16; i++) {
            int slv = tid + i * 64;
            int t = slv >> 4, ch = slv & 15;
            cp16(smem_u32(dp + t * 64 + ch * 4), pg + (size_t)(t0 + t) * 64 + ch * 4);
        }
        asm volatile("cp.async.commit_group;" ::: "memory");
    };

    load_chunk(0, 0);
    load_chunk(1, 1);

    for (int c = 0; c < NCHK; c++) {
        const int buf = c & 1;
        if (c + 1 < NCHK) asm volatile("cp.async.wait_group 1;" ::: "memory");
        else              asm volatile("cp.async.wait_group 0;" ::: "memory");
        __syncthreads();

        const float* cx = SX + buf * SCH * 16;
        const float* cp = SP + buf * SCH * 64;
        #pragma unroll 4
        for (int s = 0; s < SCH; s++) {
            float dtraw = cp[s * 64];
            float xv    = cx[s * 16 + dd];
            float2 b01 = *reinterpret_cast<const float2*>(&cp[s * 64 + 2  + 4 * sub]);
            float2 b23 = *reinterpret_cast<const float2*>(&cp[s * 64 + 4  + 4 * sub]);
            float2 c01 = *reinterpret_cast<const float2*>(&cp[s * 64 + 18 + 4 * sub]);
            float2 c23 = *reinterpret_cast<const float2*>(&cp[s * 64 + 20 + 4 * sub]);
            float z  = fmaf(dtraw, wdt, bdt);
            float dt = (z > 20.f) ? z : log1pf(expf(z));
            float dtx = dt * xv;
            float t0v = fmaf(h0, A0, dtx * b01.x); h0 = fmaf(dt, t0v, h0);
            float t1v = fmaf(h1, A1, dtx * b01.y); h1 = fmaf(dt, t1v, h1);
            float t2v = fmaf(h2, A2, dtx * b23.x); h2 = fmaf(dt, t2v, h2);
            float t3v = fmaf(h3, A3, dtx * b23.y); h3 = fmaf(dt, t3v, h3);
            float yp = h0 * c01.x;
            yp = fmaf(h1, c01.y, yp);
            yp = fmaf(h2, c23.x, yp);
            yp = fmaf(h3, c23.y, yp);
            yp += __shfl_xor_sync(0xffffffffu, yp, 1);
            yp += __shfl_xor_sync(0xffffffffu, yp, 2);
            if (sub == 0) SY[s * 16 + dd] = fmaf(xv, Dd, yp);
        }
        __syncthreads();

        const int t0 = c * SCH;
        #pragma unroll
        for (int i = 0; i < 16; i++) {
            int slv = tid + i * 64;
            int s = slv >> 4, dd2 = slv & 15;
            yg[(size_t)(t0 + s) * DI + dd2] = SY[s * 16 + dd2];
        }
        if (c + 2 < NCHK) load_chunk(buf, c + 2);
    }
}

// ---------------- host orchestration ----------------
#define SMEM_H128 (4 * (128 + 128) * RSTR * 2)
#define SMEM_H64  (4 * (128 +  64) * RSTR * 2)

extern "C" void kernel_launch(void* const* d_in, const int* in_sizes, int n_in,
                              void* d_out, int out_size)
{
    const float* hidden      = (const float*)d_in[0];
    const float* in_norm_g   = (const float*)d_in[1];
    const float* in_norm_b   = (const float*)d_in[2];
    const float* ln_g        = (const float*)d_in[3];
    const float* ln_b        = (const float*)d_in[4];
    const float* in_proj_w   = (const float*)d_in[5];
    const float* conv_w      = (const float*)d_in[6];
    const float* conv_b      = (const float*)d_in[7];
    const float* x_proj_w    = (const float*)d_in[8];
    const float* dt_proj_w   = (const float*)d_in[9];
    const float* dt_proj_b   = (const float*)d_in[10];
    const float* Dv          = (const float*)d_in[11];
    const float* mamba_ln_g  = (const float*)d_in[12];
    const float* mamba_ln_b  = (const float*)d_in[13];
    const float* out_proj_w  = (const float*)d_in[14];
    const float* op1_w       = (const float*)d_in[15];
    const float* op1_b       = (const float*)d_in[16];
    const float* op2_w       = (const float*)d_in[17];
    const float* op2_b       = (const float*)d_in[18];

    float *x, *res, *xi, *xi2, *pr, *prp, *y;
    __half *xi2h, *wph, *xnh, *yh, *xh, *t1h, *wih, *woh, *op1h, *op2h;
    cudaGetSymbolAddress((void**)&x,    g_x);
    cudaGetSymbolAddress((void**)&res,  g_res);
    cudaGetSymbolAddress((void**)&xi,   g_xi);
    cudaGetSymbolAddress((void**)&xi2,  g_xi2);
    cudaGetSymbolAddress((void**)&pr,   g_pr);
    cudaGetSymbolAddress((void**)&prp,  g_prp);
    cudaGetSymbolAddress((void**)&y,    g_y);
    cudaGetSymbolAddress((void**)&xi2h, g_xi2h);
    cudaGetSymbolAddress((void**)&wph,  g_wph);
    cudaGetSymbolAddress((void**)&xnh,  g_xnh);
    cudaGetSymbolAddress((void**)&yh,   g_yh);
    cudaGetSymbolAddress((void**)&xh,   g_xh);
    cudaGetSymbolAddress((void**)&t1h,  g_t1h);
    cudaGetSymbolAddress((void**)&wih,  g_wih);
    cudaGetSymbolAddress((void**)&woh,  g_woh);
    cudaGetSymbolAddress((void**)&op1h, g_op1h);
    cudaGetSymbolAddress((void**)&op2h, g_op2h);

    cudaFuncSetAttribute(gemm_h<4,128,4>, cudaFuncAttributeMaxDynamicSharedMemorySize, SMEM_H128);
    cudaFuncSetAttribute(gemm_h<1,64,4>,  cudaFuncAttributeMaxDynamicSharedMemorySize, SMEM_H64);
    cudaFuncSetAttribute(gemm_h<2,64,4>,  cudaFuncAttributeMaxDynamicSharedMemorySize, SMEM_H64);
    cudaFuncSetAttribute(gemm_h<3,64,4>,  cudaFuncAttributeMaxDynamicSharedMemorySize, SMEM_H64);
    cudaFuncSetAttribute(xproj_splitk_h,  cudaFuncAttributeMaxDynamicSharedMemorySize, SMEM_H64);
    cudaFuncSetAttribute(scan_kernel, cudaFuncAttributeMaxDynamicSharedMemorySize, SCAN_SMEM);

    // fused weight conversion (one launch)
    {
        int n0 = NLAYER * 2 * DI * HID;
        int n1 = NLAYER * HID * DI;
        int n2 = HID * HID;
        int n3 = HID * HID;
        int tot = n0 + n1 + n2 + n3;
        f2h_all<<<(tot + 255) / 256, 256>>>(in_proj_w, wih, n0, out_proj_w, woh, n1,
                                            op1_w, op1h, n2, op2_w, op2h, n3);
    }
    wpad_kernel<<<(NLAYER * 64 * DI + 255) / 256, 256>>>(x_proj_w, wph);

    // x = LN(hidden)  (fp32 residual)
    ln_kernel<false,false><<<ROWS, 256>>>(hidden, in_norm_g, in_norm_b, nullptr, x, HID);

    for (int l = 0; l < NLAYER; l++) {
        // xnh = half(LN(x))
        ln_kernel<false,true><<<ROWS, 256>>>(x, ln_g + (size_t)l * HID, ln_b + (size_t)l * HID,
                                             nullptr, xnh, HID);
        // in_proj: xi = silu(first half), res = second half  (2048x4096x1024 fp16)
        gemm_h<4,128,4><<<dim3(2 * DI / 128, ROWS / 128), 256, SMEM_H128>>>(
            xnh, wih + (size_t)l * 2 * DI * HID, nullptr, res, xi, nullptr, ROWS, 2 * DI, HID);
        // fused conv1+silu+conv2+silu : xi -> xi2 (fp32) + xi2h (fp16)
        conv2_kernel<<<(BATCH * DI * (SEQ / CCHUNK)) / 256, 256>>>(
            xi,
            conv_w + (size_t)(l * 2 + 0) * DI * KCONV, conv_b + (size_t)(l * 2 + 0) * DI,
            conv_w + (size_t)(l * 2 + 1) * DI * KCONV, conv_b + (size_t)(l * 2 + 1) * DI,
            xi2, xi2h);
        // proj partials (fp16 split-K over 256 CTAs), then reduce
        xproj_splitk_h<<<dim3(KSPL, ROWS / 128), 256, SMEM_H64>>>(
            xi2h, wph + (size_t)l * 64 * DI, prp, DI);
        prred_kernel<<<(ROWS * 64 + 255) / 256, 256>>>(prp, pr);
        // selective scan -> y
        scan_kernel<<<BATCH * (DI / 16), 64, SCAN_SMEM>>>(
            xi2, pr, dt_proj_w + (size_t)l * DI, dt_proj_b + (size_t)l * DI,
            Dv + (size_t)l * DI, y);
        // yh = half(LN(y) * sigmoid(res))
        ln_kernel<true,true><<<ROWS, 256>>>(y, mamba_ln_g + (size_t)l * DI,
                                            mamba_ln_b + (size_t)l * DI, res, yh, DI);
        // x = x + yh @ woh^T  (fp32 out + half copy xh) — 256 CTAs
        gemm_h<1,64,4><<<dim3(HID / 64, ROWS / 128), 256, SMEM_H64>>>(
            yh, woh + (size_t)l * HID * DI, nullptr, x, x, xh, ROWS, HID, DI);
    }

    // t1h = half(gelu(xh @ op1h^T + op1_b)) — 256 CTAs
    gemm_h<2,64,4><<<dim3(HID / 64, ROWS / 128), 256, SMEM_H64>>>(
        xh, op1h, op1_b, nullptr, nullptr, t1h, ROWS, HID, HID);
    // out = t1h @ op2h^T + op2_b + hidden  (fp32) — 256 CTAs
    gemm_h<3,64,4><<<dim3(HID / 64, ROWS / 128), 256, SMEM_H64>>>(
        t1h, op2h, op2_b, (float*)hidden, (float*)d_out, nullptr, ROWS, HID, HID);
}

// round 17
// speedup vs baseline: 1.8984x; 1.2039x over previous
#include <cuda_runtime.h>
#include <cuda_fp16.h>
#include <math.h>
#include <stdint.h>

#define BATCH 2
#define SEQ   1024
#define HID   1024
#define DI    2048
#define NST   16
#define KCONV 4
#define NLAYER 4
#define ROWS  (BATCH*SEQ)      // 2048
#define LN_EPS 1e-5f
#define KSPL  16               // xproj split-K factor

// ---------------- scratch (device globals; no allocation) ----------------
__device__ float g_x  [ROWS*HID];
__device__ float g_res[ROWS*DI];
__device__ float g_xi [ROWS*DI];
__device__ float g_xi2[ROWS*DI];
__device__ float g_pr [ROWS*64];          // padded proj (stride 64, permuted layout)
__device__ float g_prp[KSPL*ROWS*64];     // split-K partials
__device__ float g_y  [ROWS*DI];
// half operands
__device__ __half g_xi2h[ROWS*DI];
__device__ __half g_wph [NLAYER*64*DI];
__device__ __half g_xnh [ROWS*HID];
__device__ __half g_yh  [ROWS*DI];
__device__ __half g_xh  [ROWS*HID];
__device__ __half g_t1h [ROWS*HID];
__device__ __half g_wih [NLAYER*2*DI*HID];
__device__ __half g_woh [NLAYER*HID*DI];
__device__ __half g_op1h[HID*HID];
__device__ __half g_op2h[HID*HID];

// ---------------- helpers ----------------
__device__ __forceinline__ float siluf(float v) { return v / (1.f + expf(-v)); }
__device__ __forceinline__ float sigmoidf_(float v) { return 1.f / (1.f + expf(-v)); }
__device__ __forceinline__ float geluf(float v) { return 0.5f * v * (1.f + erff(v * 0.70710678118654752f)); }
__device__ __forceinline__ uint32_t smem_u32(const void* p) {
    uint32_t a;
    asm("{ .reg .u64 t; cvta.to.shared.u64 t, %1; cvt.u32.u64 %0, t; }" : "=r"(a) : "l"(p));
    return a;
}
__device__ __forceinline__ void cp16(uint32_t d, const void* g) {
    asm volatile("cp.async.cg.shared.global [%0], [%1], 16;" :: "r"(d), "l"(g));
}
__device__ __forceinline__ void ldsm4(uint32_t& r0, uint32_t& r1, uint32_t& r2, uint32_t& r3,
                                      uint32_t a) {
    asm volatile("ldmatrix.sync.aligned.m8n8.x4.shared.b16 {%0,%1,%2,%3}, [%4];"
                 : "=r"(r0), "=r"(r1), "=r"(r2), "=r"(r3) : "r"(a));
}
#define MMA_F16(acc, a0,a1,a2,a3, b0,b1)                                      \
    asm volatile(                                                             \
        "mma.sync.aligned.m16n8k16.row.col.f32.f16.f16.f32 "                  \
        "{%0,%1,%2,%3}, {%4,%5,%6,%7}, {%8,%9}, {%0,%1,%2,%3};"               \
        : "+f"((acc)[0]), "+f"((acc)[1]), "+f"((acc)[2]), "+f"((acc)[3])      \
        : "r"(a0), "r"(a1), "r"(a2), "r"(a3), "r"(b0), "r"(b1))

// ---------------- fused fp32 -> fp16 weight convert ----------------
__global__ void f2h_all(const float* __restrict__ w0, __half* __restrict__ o0, int n0,
                        const float* __restrict__ w1, __half* __restrict__ o1, int n1,
                        const float* __restrict__ w2, __half* __restrict__ o2, int n2,
                        const float* __restrict__ w3, __half* __restrict__ o3, int n3)
{
    int i = blockIdx.x * blockDim.x + threadIdx.x;
    if (i < n0) o0[i] = __float2half_rn(w0[i]);
    i -= n0;
    if (i >= 0 && i < n1) o1[i] = __float2half_rn(w1[i]);
    i -= n1;
    if (i >= 0 && i < n2) o2[i] = __float2half_rn(w2[i]);
    i -= n2;
    if (i >= 0 && i < n3) o3[i] = __float2half_rn(w3[i]);
}

// ---------------- one-pass LayerNorm, float4 vectorized ----------------
template<bool GATE, bool OUTH>
__global__ void ln_kernel(const float* __restrict__ in,
                          const float* __restrict__ g,
                          const float* __restrict__ b,
                          const float* __restrict__ gate,
                          void* __restrict__ outv, int cols)
{
    __shared__ float4 buf[512];         // up to 2048 floats
    __shared__ float red[16];
    __shared__ float s_mu, s_rstd;
    const int row = blockIdx.x;
    const int tid = threadIdx.x;
    const int n4 = cols >> 2;
    const float4* pin = reinterpret_cast<const float4*>(in + (size_t)row * cols);

    float s = 0.f, s2 = 0.f;
    for (int c = tid; c < n4; c += 256) {
        float4 v = pin[c];
        buf[c] = v;
        s += v.x + v.y + v.z + v.w;
        s2 = fmaf(v.x, v.x, s2);
        s2 = fmaf(v.y, v.y, s2);
        s2 = fmaf(v.z, v.z, s2);
        s2 = fmaf(v.w, v.w, s2);
    }
    #pragma unroll
    for (int o = 16; o; o >>= 1) {
        s  += __shfl_xor_sync(0xffffffffu, s,  o);
        s2 += __shfl_xor_sync(0xffffffffu, s2, o);
    }
    if ((tid & 31) == 0) { red[tid >> 5] = s; red[8 + (tid >> 5)] = s2; }
    __syncthreads();
    if (tid == 0) {
        float t = 0.f, t2 = 0.f;
        #pragma unroll
        for (int i = 0; i < 8; i++) { t += red[i]; t2 += red[8 + i]; }
        float mu = t / (float)cols;
        float var = t2 / (float)cols - mu * mu;
        s_mu = mu;
        s_rstd = rsqrtf(var + LN_EPS);
    }
    __syncthreads();
    const float mu = s_mu;
    const float rstd = s_rstd;
    const float4* g4 = reinterpret_cast<const float4*>(g);
    const float4* b4 = reinterpret_cast<const float4*>(b);
    const float4* gt4 = GATE ? reinterpret_cast<const float4*>(gate + (size_t)row * cols) : nullptr;
    for (int c = tid; c < n4; c += 256) {
        float4 v = buf[c];
        float4 gg = g4[c];
        float4 bb = b4[c];
        float o0 = fmaf((v.x - mu) * rstd, gg.x, bb.x);
        float o1 = fmaf((v.y - mu) * rstd, gg.y, bb.y);
        float o2 = fmaf((v.z - mu) * rstd, gg.z, bb.z);
        float o3 = fmaf((v.w - mu) * rstd, gg.w, bb.w);
        if (GATE) {
            float4 gt = gt4[c];
            o0 *= sigmoidf_(gt.x); o1 *= sigmoidf_(gt.y);
            o2 *= sigmoidf_(gt.z); o3 *= sigmoidf_(gt.w);
        }
        if (OUTH) {
            __half2* ph = reinterpret_cast<__half2*>((__half*)outv + (size_t)row * cols);
            ph[c * 2    ] = __floats2half2_rn(o0, o1);
            ph[c * 2 + 1] = __floats2half2_rn(o2, o3);
        } else {
            reinterpret_cast<float4*>((float*)outv + (size_t)row * cols)[c] =
                make_float4(o0, o1, o2, o3);
        }
    }
}

// ---------------- fp16 tensor-core GEMM, 8 warps, ldmatrix, templated TBN ---------
#define RSTR 40

template<int EPI, int TBN, int NSTG>
__global__ __launch_bounds__(256, 2)
void gemm_h(const __half* __restrict__ A, const __half* __restrict__ Bw,
            const float* __restrict__ bias, float* __restrict__ residF,
            float* __restrict__ C, __half* __restrict__ Ch,
            int M, int N, int K)
{
    constexpr int WMW   = (TBN == 128) ? 2 : 4;
    constexpr int MROWS = 128 / WMW;
    constexpr int MT    = MROWS / 16;
    constexpr int ASTG  = 128 * RSTR;
    constexpr int BSTG  = TBN * RSTR;
    constexpr int STG   = ASTG + BSTG;
    extern __shared__ __half smh[];

    const int tid  = threadIdx.x;
    const int lane = tid & 31;
    const int w    = tid >> 5;
    const int wm   = w & (WMW - 1);
    const int wn   = w / WMW;
    const int m0 = blockIdx.y * 128;
    const int n0 = blockIdx.x * TBN;
    const int lq = lane >> 2;
    const int lr = lane & 3;
    const int l7  = lane & 7;
    const int l8  = (lane >> 3) & 1;
    const int l16 = lane >> 4;

    float acc[MT][4][4];
    #pragma unroll
    for (int i = 0; i < MT; i++)
        #pragma unroll
        for (int j = 0; j < 4; j++)
            #pragma unroll
            for (int r = 0; r < 4; r++) acc[i][j][r] = 0.f;

    const int NC = K >> 5;

    auto load_stage = [&](int s, int k0) {
        __half* dA = smh + s * STG;
        __half* dB = dA + ASTG;
        #pragma unroll
        for (int i = 0; i < 2; i++) {
            int slot = tid + i * 256;
            int row = slot >> 2, c = slot & 3;
            cp16(smem_u32(dA + row * RSTR + c * 8), A + (size_t)(m0 + row) * K + k0 + c * 8);
        }
        #pragma unroll
        for (int i = 0; i < TBN * 4 / 256; i++) {
            int slot = tid + i * 256;
            int row = slot >> 2, c = slot & 3;
            cp16(smem_u32(dB + row * RSTR + c * 8), Bw + (size_t)(n0 + row) * K + k0 + c * 8);
        }
        asm volatile("cp.async.commit_group;" ::: "memory");
    };

    #pragma unroll
    for (int c = 0; c < NSTG - 1; c++) load_stage(c, c * 32);

    int s = 0, sl = NSTG - 1;
    for (int c = 0; c < NC; c++) {
        if (c <= NC - NSTG + 1) {
            asm volatile("cp.async.wait_group %0;" :: "n"(NSTG - 2) : "memory");
        } else {
            asm volatile("cp.async.wait_group 0;" ::: "memory");
        }
        __syncthreads();
        if (c + NSTG - 1 < NC) load_stage(sl, (c + NSTG - 1) * 32);

        const __half* sA = smh + s * STG;
        const __half* sB = sA + ASTG;
        #pragma unroll
        for (int kk = 0; kk < 32; kk += 16) {
            uint32_t af[MT][4], bf[4][2];
            #pragma unroll
            for (int mt = 0; mt < MT; mt++) {
                int r = wm * MROWS + mt * 16 + l7 + l8 * 8;
                uint32_t addr = smem_u32(&sA[r * RSTR + kk + l16 * 8]);
                ldsm4(af[mt][0], af[mt][1], af[mt][2], af[mt][3], addr);
            }
            #pragma unroll
            for (int p = 0; p < 2; p++) {
                int rn = wn * 32 + p * 16 + l7 + l16 * 8;
                uint32_t addr = smem_u32(&sB[rn * RSTR + kk + l8 * 8]);
                ldsm4(bf[2 * p][0], bf[2 * p][1], bf[2 * p + 1][0], bf[2 * p + 1][1], addr);
            }
            #pragma unroll
            for (int mt = 0; mt < MT; mt++)
                #pragma unroll
                for (int nt = 0; nt < 4; nt++)
                    MMA_F16(acc[mt][nt], af[mt][0], af[mt][1], af[mt][2], af[mt][3],
                            bf[nt][0], bf[nt][1]);
        }
        if (++s == NSTG) s = 0;
        if (++sl == NSTG) sl = 0;
    }

    #pragma unroll
    for (int mt = 0; mt < MT; mt++)
        #pragma unroll
        for (int nt = 0; nt < 4; nt++) {
            int r0 = m0 + wm * MROWS + mt * 16 + lq;
            int cc = n0 + wn * 32 + nt * 8 + lr * 2;
            #pragma unroll
            for (int half_i = 0; half_i < 2; half_i++) {
                int m = r0 + half_i * 8;
                float v0 = acc[mt][nt][half_i * 2 + 0];
                float v1 = acc[mt][nt][half_i * 2 + 1];
                if (EPI == 1) {
                    float2 rr = *reinterpret_cast<const float2*>(&residF[(size_t)m * N + cc]);
                    float o0 = v0 + rr.x, o1 = v1 + rr.y;
                    *reinterpret_cast<float2*>(&C[(size_t)m * N + cc]) = make_float2(o0, o1);
                    *reinterpret_cast<__half2*>(&Ch[(size_t)m * N + cc]) = __floats2half2_rn(o0, o1);
                } else if (EPI == 2) {
                    *reinterpret_cast<__half2*>(&Ch[(size_t)m * N + cc]) =
                        __floats2half2_rn(geluf(v0 + bias[cc]), geluf(v1 + bias[cc + 1]));
                } else if (EPI == 3) {
                    float2 rr = *reinterpret_cast<const float2*>(&residF[(size_t)m * N + cc]);
                    *reinterpret_cast<float2*>(&C[(size_t)m * N + cc]) =
                        make_float2(v0 + bias[cc] + rr.x, v1 + bias[cc + 1] + rr.y);
                } else {                        // EPI 4
                    if (cc < DI)
                        *reinterpret_cast<float2*>(&C[(size_t)m * DI + cc]) =
                            make_float2(siluf(v0), siluf(v1));
                    else
                        *reinterpret_cast<float2*>(&residF[(size_t)m * DI + cc - DI]) =
                            make_float2(v0, v1);
                }
            }
        }
}

// ---------------- xproj split-K GEMM, fp16 ----------------
__global__ __launch_bounds__(256, 2)
void xproj_splitk_h(const __half* __restrict__ A, const __half* __restrict__ Bw,
                    float* __restrict__ Cp, int K)
{
    constexpr int NSTG = 4;
    constexpr int ASTG = 128 * RSTR;
    constexpr int BSTG = 64 * RSTR;
    constexpr int STG  = ASTG + BSTG;
    extern __shared__ __half smh[];

    const int tid  = threadIdx.x;
    const int lane = tid & 31;
    const int w    = tid >> 5;
    const int wm   = w & 3;
    const int wn   = w >> 2;
    const int m0 = blockIdx.y * 128;
    const int kz = blockIdx.x;
    const int kbase = kz * (K / KSPL);
    const int lq = lane >> 2;
    const int lr = lane & 3;
    const int l7  = lane & 7;
    const int l8  = (lane >> 3) & 1;
    const int l16 = lane >> 4;
    float* C = Cp + (size_t)kz * ROWS * 64;

    float acc[2][4][4];
    #pragma unroll
    for (int i = 0; i < 2; i++)
        #pragma unroll
        for (int j = 0; j < 4; j++)
            #pragma unroll
            for (int r = 0; r < 4; r++) acc[i][j][r] = 0.f;

    const int NC = (K / KSPL) >> 5;

    auto load_stage = [&](int s, int k0) {
        __half* dA = smh + s * STG;
        __half* dB = dA + ASTG;
        #pragma unroll
        for (int i = 0; i < 2; i++) {
            int slot = tid + i * 256;
            int row = slot >> 2, c = slot & 3;
            cp16(smem_u32(dA + row * RSTR + c * 8), A + (size_t)(m0 + row) * K + kbase + k0 + c * 8);
        }
        {
            int row = tid >> 2, c = tid & 3;
            cp16(smem_u32(dB + row * RSTR + c * 8), Bw + (size_t)row * K + kbase + k0 + c * 8);
        }
        asm volatile("cp.async.commit_group;" ::: "memory");
    };

    #pragma unroll
    for (int c = 0; c < NSTG - 1; c++) load_stage(c, c * 32);

    int s = 0, sl = NSTG - 1;
    for (int c = 0; c < NC; c++) {
        if (c <= NC - NSTG + 1) {
            asm volatile("cp.async.wait_group %0;" :: "n"(NSTG - 2) : "memory");
        } else {
            asm volatile("cp.async.wait_group 0;" ::: "memory");
        }
        __syncthreads();
        if (c + NSTG - 1 < NC) load_stage(sl, (c + NSTG - 1) * 32);

        const __half* sA = smh + s * STG;
        const __half* sB = sA + ASTG;
        #pragma unroll
        for (int kk = 0; kk < 32; kk += 16) {
            uint32_t af[2][4], bf[4][2];
            #pragma unroll
            for (int mt = 0; mt < 2; mt++) {
                int r = wm * 32 + mt * 16 + l7 + l8 * 8;
                uint32_t addr = smem_u32(&sA[r * RSTR + kk + l16 * 8]);
                ldsm4(af[mt][0], af[mt][1], af[mt][2], af[mt][3], addr);
            }
            #pragma unroll
            for (int p = 0; p < 2; p++) {
                int rn = wn * 32 + p * 16 + l7 + l16 * 8;
                uint32_t addr = smem_u32(&sB[rn * RSTR + kk + l8 * 8]);
                ldsm4(bf[2 * p][0], bf[2 * p][1], bf[2 * p + 1][0], bf[2 * p + 1][1], addr);
            }
            #pragma unroll
            for (int mt = 0; mt < 2; mt++)
                #pragma unroll
                for (int nt = 0; nt < 4; nt++)
                    MMA_F16(acc[mt][nt], af[mt][0], af[mt][1], af[mt][2], af[mt][3],
                            bf[nt][0], bf[nt][1]);
        }
        if (++s == NSTG) s = 0;
        if (++sl == NSTG) sl = 0;
    }

    #pragma unroll
    for (int mt = 0; mt < 2; mt++)
        #pragma unroll
        for (int nt = 0; nt < 4; nt++) {
            int r0 = m0 + wm * 32 + mt * 16 + lq;
            int cc = wn * 32 + nt * 8 + lr * 2;
            #pragma unroll
            for (int half_i = 0; half_i < 2; half_i++) {
                int m = r0 + half_i * 8;
                *reinterpret_cast<float2*>(&C[(size_t)m * 64 + cc]) =
                    make_float2(acc[mt][nt][half_i * 2 + 0], acc[mt][nt][half_i * 2 + 1]);
            }
        }
}

// ---------------- split-K reduce ----------------
__global__ void prred_kernel(const float* __restrict__ prp, float* __restrict__ pr)
{
    int i = blockIdx.x * blockDim.x + threadIdx.x;
    if (i >= ROWS * 64) return;
    float s = 0.f;
    #pragma unroll
    for (int z = 0; z < KSPL; z++) s += prp[(size_t)z * ROWS * 64 + i];
    pr[i] = s;
}

// ---------------- fused double causal dwconv (K=4) + silu, dual output -----------
#define CCHUNK 8
__global__ void conv2_kernel(const float* __restrict__ in,
                             const float* __restrict__ w1, const float* __restrict__ b1,
                             const float* __restrict__ w2, const float* __restrict__ b2,
                             float* __restrict__ out, __half* __restrict__ outh)
{
    int idx = blockIdx.x * blockDim.x + threadIdx.x;
    if (idx >= BATCH * DI * (SEQ / CCHUNK)) return;
    int d  = idx % DI;
    int r  = idx / DI;
    int c0 = r % (SEQ / CCHUNK);
    int b  = r / (SEQ / CCHUNK);
    int t0 = c0 * CCHUNK;

    const float wa0 = w1[d*4+0], wa1 = w1[d*4+1], wa2 = w1[d*4+2], wa3 = w1[d*4+3];
    const float wb0 = w2[d*4+0], wb1 = w2[d*4+1], wb2 = w2[d*4+2], wb3 = w2[d*4+3];
    const float bb1 = b1[d], bb2 = b2[d];
    const float* pin  = in  + (size_t)b * SEQ * DI + d;
    float*       pout = out + (size_t)b * SEQ * DI + d;
    __half*      ph   = outh + (size_t)b * SEQ * DI + d;

    float h[3];
    #pragma unroll
    for (int j = 0; j < 3; j++) {
        int t = t0 - 3 + j;
        if (t >= 0) {
            float a = bb1;
            float wv[4] = {wa0, wa1, wa2, wa3};
            #pragma unroll
            for (int k = 0; k < 4; k++) {
                int tt = t - 3 + k;
                if (tt >= 0) a = fmaf(pin[(size_t)tt * DI], wv[k], a);
            }
            h[j] = siluf(a);
        } else h[j] = 0.f;
    }
    float xm3 = (t0 - 3 >= 0) ? pin[(size_t)(t0 - 3) * DI] : 0.f;
    float xm2 = (t0 - 2 >= 0) ? pin[(size_t)(t0 - 2) * DI] : 0.f;
    float xm1 = (t0 - 1 >= 0) ? pin[(size_t)(t0 - 1) * DI] : 0.f;

    #pragma unroll
    for (int t = t0; t < t0 + CCHUNK; t++) {
        float xt = pin[(size_t)t * DI];
        float v1 = fmaf(wa0, xm3, bb1);
        v1 = fmaf(wa1, xm2, v1);
        v1 = fmaf(wa2, xm1, v1); v1 = fmaf(wa3, xt,  v1);
        float s = siluf(v1);
        float v2 = fmaf(wb0, h[0], bb2);
        v2 = fmaf(wb1, h[1], v2);
        v2 = fmaf(wb2, h[2], v2); v2 = fmaf(wb3, s,    v2);
        float o = siluf(v2);
        pout[(size_t)t * DI] = o;
        ph[(size_t)t * DI] = __float2half_rn(o);
        xm3 = xm2; xm2 = xm1; xm1 = xt;
        h[0] = h[1]; h[1] = h[2]; h[2] = s;
    }
}

// ---------------- x_proj weight zero-pad, PERMUTED, half output -------------------
__global__ void wpad_kernel(const float* __restrict__ W, __half* __restrict__ Wp)
{
    int idx = blockIdx.x * blockDim.x + threadIdx.x;
    if (idx >= NLAYER * 64 * DI) return;
    int k = idx % DI;
    int q = (idx / DI) % 64;
    int l = idx / (DI * 64);
    float v = 0.f;
    if (q == 0) v = W[(size_t)l * 33 * DI + k];
    else if (q >= 2 && q < 34) v = W[((size_t)l * 33 + (q - 1)) * DI + k];
    Wp[idx] = __float2half_rn(v);
}

// ---------------- selective scan: dt precomputed per chunk (off serial path) -------
#define SCH 64
#define NCHK (SEQ / SCH)
#define SCAN_SMEM ((2*SCH*16 + 2*SCH*64 + SCH*16 + SCH*16 + 32) * 4)

__global__ __launch_bounds__(64)
void scan_kernel(const float* __restrict__ x, const float* __restrict__ pr,
                 const float* __restrict__ dtw, const float* __restrict__ dtb,
                 const float* __restrict__ Dv, float* __restrict__ y)
{
    extern __shared__ float sm[];
    float* SX  = sm;                       // [2][SCH][16]
    float* SP  = sm + 2 * SCH * 16;        // [2][SCH][64]
    float* SY  = SP + 2 * SCH * 64;        // [SCH][16]
    float* SDT = SY + SCH * 16;            // [SCH][16] precomputed dt
    float* SW  = SDT + SCH * 16;           // [16] dt weight
    float* SBb = SW + 16;                  // [16] dt bias

    const int tid = threadIdx.x;           // 64
    const int dd  = tid >> 2;              // 0..15
    const int sub = tid & 3;               // 0..3
    const int nblk = DI / 16;
    const int b  = blockIdx.x / nblk;
    const int d0 = (blockIdx.x % nblk) * 16;
    const int d  = d0 + dd;

    const float wdt = dtw[d], bdt = dtb[d], Dd = Dv[d];
    if (sub == 0) { SW[dd] = wdt; SBb[dd] = bdt; }
    const float A0 = -(float)(sub * 4 + 1);
    const float A1 = -(float)(sub * 4 + 2);
    const float A2 = -(float)(sub * 4 + 3);
    const float A3 = -(float)(sub * 4 + 4);
    float h0 = 0.f, h1 = 0.f, h2 = 0.f, h3 = 0.f;

    const float* xg = x + (size_t)b * SEQ * DI + d0;
    const float* pg = pr + (size_t)b * SEQ * 64;
    float*       yg = y + (size_t)b * SEQ * DI + d0;

    auto load_chunk = [&](int buf, int c) {
        int t0 = c * SCH;
        float* dx = SX + buf * SCH * 16;
        float* dp = SP + buf * SCH * 64;
        #pragma unroll
        for (int i = 0; i < 4; i++) {
            int slv = tid + i * 64;
            int t = slv >> 2, ch = slv & 3;
            cp16(smem_u32(dx + t * 16 + ch * 4), xg + (size_t)(t0 + t) * DI + ch * 4);
        }
        #pragma unroll
        for (int i = 0; i < 16; i++) {
            int slv = tid + i * 64;
            int t = slv >> 4, ch = slv & 15;
            cp16(smem_u32(dp + t * 64 + ch * 4), pg + (size_t)(t0 + t) * 64 + ch * 4);
        }
        asm volatile("cp.async.commit_group;" ::: "memory");
    };

    load_chunk(0, 0);
    load_chunk(1, 1);

    for (int c = 0; c < NCHK; c++) {
        const int buf = c & 1;
        if (c + 1 < NCHK) asm volatile("cp.async.wait_group 1;" ::: "memory");
        else              asm volatile("cp.async.wait_group 0;" ::: "memory");
        __syncthreads();

        const float* cx = SX + buf * SCH * 16;
        const float* cp = SP + buf * SCH * 64;

        // parallel dt precompute: one softplus per (s, ch)
        #pragma unroll
        for (int i = 0; i < SCH * 16 / 64; i++) {
            int j = tid + i * 64;
            int s = j >> 4, ch = j & 15;
            float z = fmaf(cp[s * 64], SW[ch], SBb[ch]);
            SDT[j] = (z > 20.f) ? z : log1pf(expf(z));
        }
        __syncthreads();

        #pragma unroll 4
        for (int s = 0; s < SCH; s++) {
            float dt = SDT[s * 16 + dd];
            float xv = cx[s * 16 + dd];
            float2 b01 = *reinterpret_cast<const float2*>(&cp[s * 64 + 2  + 4 * sub]);
            float2 b23 = *reinterpret_cast<const float2*>(&cp[s * 64 + 4  + 4 * sub]);
            float2 c01 = *reinterpret_cast<const float2*>(&cp[s * 64 + 18 + 4 * sub]);
            float2 c23 = *reinterpret_cast<const float2*>(&cp[s * 64 + 20 + 4 * sub]);
            float dtx = dt * xv;
            float t0v = fmaf(h0, A0, dtx * b01.x); h0 = fmaf(dt, t0v, h0);
            float t1v = fmaf(h1, A1, dtx * b01.y); h1 = fmaf(dt, t1v, h1);
            float t2v = fmaf(h2, A2, dtx * b23.x); h2 = fmaf(dt, t2v, h2);
            float t3v = fmaf(h3, A3, dtx * b23.y); h3 = fmaf(dt, t3v, h3);
            float yp = h0 * c01.x;
            yp = fmaf(h1, c01.y, yp);
            yp = fmaf(h2, c23.x, yp);
            yp = fmaf(h3, c23.y, yp);
            yp += __shfl_xor_sync(0xffffffffu, yp, 1);
            yp += __shfl_xor_sync(0xffffffffu, yp, 2);
            if (sub == 0) SY[s * 16 + dd] = fmaf(xv, Dd, yp);
        }
        __syncthreads();

        const int t0 = c * SCH;
        #pragma unroll
        for (int i = 0; i < 16; i++) {
            int slv = tid + i * 64;
            int s = slv >> 4, dd2 = slv & 15;
            yg[(size_t)(t0 + s) * DI + dd2] = SY[s * 16 + dd2];
        }
        if (c + 2 < NCHK) load_chunk(buf, c + 2);
    }
}

// ---------------- host orchestration ----------------
#define SMEM_H128 (4 * (128 + 128) * RSTR * 2)
#define SMEM_H64  (4 * (128 +  64) * RSTR * 2)

extern "C" void kernel_launch(void* const* d_in, const int* in_sizes, int n_in,
                              void* d_out, int out_size)
{
    const float* hidden      = (const float*)d_in[0];
    const float* in_norm_g   = (const float*)d_in[1];
    const float* in_norm_b   = (const float*)d_in[2];
    const float* ln_g        = (const float*)d_in[3];
    const float* ln_b        = (const float*)d_in[4];
    const float* in_proj_w   = (const float*)d_in[5];
    const float* conv_w      = (const float*)d_in[6];
    const float* conv_b      = (const float*)d_in[7];
    const float* x_proj_w    = (const float*)d_in[8];
    const float* dt_proj_w   = (const float*)d_in[9];
    const float* dt_proj_b   = (const float*)d_in[10];
    const float* Dv          = (const float*)d_in[11];
    const float* mamba_ln_g  = (const float*)d_in[12];
    const float* mamba_ln_b  = (const float*)d_in[13];
    const float* out_proj_w  = (const float*)d_in[14];
    const float* op1_w       = (const float*)d_in[15];
    const float* op1_b       = (const float*)d_in[16];
    const float* op2_w       = (const float*)d_in[17];
    const float* op2_b       = (const float*)d_in[18];

    float *x, *res, *xi, *xi2, *pr, *prp, *y;
    __half *xi2h, *wph, *xnh, *yh, *xh, *t1h, *wih, *woh, *op1h, *op2h;
    cudaGetSymbolAddress((void**)&x,    g_x);
    cudaGetSymbolAddress((void**)&res,  g_res);
    cudaGetSymbolAddress((void**)&xi,   g_xi);
    cudaGetSymbolAddress((void**)&xi2,  g_xi2);
    cudaGetSymbolAddress((void**)&pr,   g_pr);
    cudaGetSymbolAddress((void**)&prp,  g_prp);
    cudaGetSymbolAddress((void**)&y,    g_y);
    cudaGetSymbolAddress((void**)&xi2h, g_xi2h);
    cudaGetSymbolAddress((void**)&wph,  g_wph);
    cudaGetSymbolAddress((void**)&xnh,  g_xnh);
    cudaGetSymbolAddress((void**)&yh,   g_yh);
    cudaGetSymbolAddress((void**)&xh,   g_xh);
    cudaGetSymbolAddress((void**)&t1h,  g_t1h);
    cudaGetSymbolAddress((void**)&wih,  g_wih);
    cudaGetSymbolAddress((void**)&woh,  g_woh);
    cudaGetSymbolAddress((void**)&op1h, g_op1h);
    cudaGetSymbolAddress((void**)&op2h, g_op2h);

    cudaFuncSetAttribute(gemm_h<4,128,4>, cudaFuncAttributeMaxDynamicSharedMemorySize, SMEM_H128);
    cudaFuncSetAttribute(gemm_h<1,64,4>,  cudaFuncAttributeMaxDynamicSharedMemorySize, SMEM_H64);
    cudaFuncSetAttribute(gemm_h<2,64,4>,  cudaFuncAttributeMaxDynamicSharedMemorySize, SMEM_H64);
    cudaFuncSetAttribute(gemm_h<3,64,4>,  cudaFuncAttributeMaxDynamicSharedMemorySize, SMEM_H64);
    cudaFuncSetAttribute(xproj_splitk_h,  cudaFuncAttributeMaxDynamicSharedMemorySize, SMEM_H64);
    cudaFuncSetAttribute(scan_kernel, cudaFuncAttributeMaxDynamicSharedMemorySize, SCAN_SMEM);

    // fused weight conversion (one launch)
    {
        int n0 = NLAYER * 2 * DI * HID;
        int n1 = NLAYER * HID * DI;
        int n2 = HID * HID;
        int n3 = HID * HID;
        int tot = n0 + n1 + n2 + n3;
        f2h_all<<<(tot + 255) / 256, 256>>>(in_proj_w, wih, n0, out_proj_w, woh, n1,
                                            op1_w, op1h, n2, op2_w, op2h, n3);
    }
    wpad_kernel<<<(NLAYER * 64 * DI + 255) / 256, 256>>>(x_proj_w, wph);

    // x = LN(hidden)  (fp32 residual)
    ln_kernel<false,false><<<ROWS, 256>>>(hidden, in_norm_g, in_norm_b, nullptr, x, HID);

    for (int l = 0; l < NLAYER; l++) {
        // xnh = half(LN(x))
        ln_kernel<false,true><<<ROWS, 256>>>(x, ln_g + (size_t)l * HID, ln_b + (size_t)l * HID,
                                             nullptr, xnh, HID);
        // in_proj: xi = silu(first half), res = second half
        gemm_h<4,128,4><<<dim3(2 * DI / 128, ROWS / 128), 256, SMEM_H128>>>(
            xnh, wih + (size_t)l * 2 * DI * HID, nullptr, res, xi, nullptr, ROWS, 2 * DI, HID);
        // fused conv1+silu+conv2+silu : xi -> xi2 (fp32) + xi2h (fp16)
        conv2_kernel<<<(BATCH * DI * (SEQ / CCHUNK)) / 256, 256>>>(
            xi,
            conv_w + (size_t)(l * 2 + 0) * DI * KCONV, conv_b + (size_t)(l * 2 + 0) * DI,
            conv_w + (size_t)(l * 2 + 1) * DI * KCONV, conv_b + (size_t)(l * 2 + 1) * DI,
            xi2, xi2h);
        // proj partials (fp16 split-K), then reduce
        xproj_splitk_h<<<dim3(KSPL, ROWS / 128), 256, SMEM_H64>>>(
            xi2h, wph + (size_t)l * 64 * DI, prp, DI);
        prred_kernel<<<(ROWS * 64 + 255) / 256, 256>>>(prp, pr);
        // selective scan -> y
        scan_kernel<<<BATCH * (DI / 16), 64, SCAN_SMEM>>>(
            xi2, pr, dt_proj_w + (size_t)l * DI, dt_proj_b + (size_t)l * DI,
            Dv + (size_t)l * DI, y);
        // yh = half(LN(y) * sigmoid(res))
        ln_kernel<true,true><<<ROWS, 256>>>(y, mamba_ln_g + (size_t)l * DI,
                                            mamba_ln_b + (size_t)l * DI, res, yh, DI);
        // x = x + yh @ woh^T  (fp32 out + half copy xh)
        gemm_h<1,64,4><<<dim3(HID / 64, ROWS / 128), 256, SMEM_H64>>>(
            yh, woh + (size_t)l * HID * DI, nullptr, x, x, xh, ROWS, HID, DI);
    }

    // t1h = half(gelu(xh @ op1h^T + op1_b))
    gemm_h<2,64,4><<<dim3(HID / 64, ROWS / 128), 256, SMEM_H64>>>(
        xh, op1h, op1_b, nullptr, nullptr, t1h, ROWS, HID, HID);
    // out = t1h @ op2h^T + op2_b + hidden  (fp32)
    gemm_h<3,64,4><<<dim3(HID / 64, ROWS / 128), 256, SMEM_H64>>>(
        t1h, op2h, op2_b, (float*)hidden, (float*)d_out, nullptr, ROWS, HID, HID);
}